// round 2
// baseline (speedup 1.0000x reference)
#include <cuda_runtime.h>
#include <math.h>

// ---------------- problem constants ----------------
#define B_   16
#define L_   1024
#define DM   512      // d_model
#define ED   1024     // d_inner
#define NST  16       // d_state
#define NL   4
#define DR   32       // dt_rank
#define CH   8        // scan chunks
#define LC   128      // chunk length  (CH*LC == L_)
#define MROWS (B_*L_) // 16384

// ---------------- scratch (device globals; no allocation allowed) ----------------
__device__ float g_h    [(size_t)MROWS*DM];
__device__ float g_nrm  [(size_t)MROWS*DM];
__device__ float g_xz   [(size_t)MROWS*2*ED];
__device__ float g_xc   [(size_t)MROWS*ED];
__device__ float g_dbc  [(size_t)MROWS*64];
__device__ float g_delta[(size_t)MROWS*ED];
__device__ float g_y    [(size_t)MROWS*ED];
__device__ float g_hloc [(size_t)B_*CH*ED*NST];
__device__ float g_P    [(size_t)B_*CH*ED*NST];
__device__ float g_Hin  [(size_t)B_*CH*ED*NST];
__device__ float g_xT   [(size_t)MROWS*32];

__device__ __forceinline__ float sigmoidf_(float x) { return 1.f / (1.f + __expf(-x)); }

// ---------------- transpose x: (B,32,L) -> (B*L, 32) ----------------
__global__ void transpose_x_kernel(const float* __restrict__ x, float* __restrict__ xT) {
    __shared__ float t[32][33];
    int b  = blockIdx.y;
    int l0 = blockIdx.x * 32;
    int tx = threadIdx.x, ty = threadIdx.y;
    t[ty][tx] = x[((size_t)b*32 + ty)*L_ + l0 + tx];
    __syncthreads();
    xT[((size_t)b*L_ + l0 + ty)*32 + tx] = t[tx][ty];
}

// ---------------- generic SGEMM: C(MxN) = A(MxK) * B(NxK)^T  (+epilogue) ----------------
// MODE: 0=store, 1=+bias, 2=softplus(+bias), 3=residual add into C
template<int BM, int BN, int BK, int TM, int TN, int MODE>
__global__ __launch_bounds__((BM/TM)*(BN/TN))
void sgemm_kernel(const float* __restrict__ A, const float* __restrict__ Bw,
                  float* __restrict__ C, const float* __restrict__ bias,
                  int M, int N, int K, int lda, int ldb, int ldc) {
    constexpr int THREADS = (BM/TM)*(BN/TN);
    __shared__ float As[BK][BM];
    __shared__ float Bs[BK][BN];
    const int tid = threadIdx.x;
    const int bm  = blockIdx.y * BM;
    const int bn  = blockIdx.x * BN;
    const int tx  = tid % (BN/TN);
    const int ty  = tid / (BN/TN);

    float acc[TM][TN];
#pragma unroll
    for (int i = 0; i < TM; i++)
#pragma unroll
        for (int j = 0; j < TN; j++) acc[i][j] = 0.f;

    constexpr int AVEC = BM*BK/4/THREADS;
    constexpr int BVEC = BN*BK/4/THREADS;

    for (int k0 = 0; k0 < K; k0 += BK) {
#pragma unroll
        for (int i = 0; i < AVEC; i++) {
            int idx = tid + i*THREADS;
            int row = idx / (BK/4);
            int kc  = (idx % (BK/4)) * 4;
            float4 v = *reinterpret_cast<const float4*>(&A[(size_t)(bm+row)*lda + k0 + kc]);
            As[kc+0][row] = v.x; As[kc+1][row] = v.y; As[kc+2][row] = v.z; As[kc+3][row] = v.w;
        }
#pragma unroll
        for (int i = 0; i < BVEC; i++) {
            int idx = tid + i*THREADS;
            int row = idx / (BK/4);
            int kc  = (idx % (BK/4)) * 4;
            float4 v = *reinterpret_cast<const float4*>(&Bw[(size_t)(bn+row)*ldb + k0 + kc]);
            Bs[kc+0][row] = v.x; Bs[kc+1][row] = v.y; Bs[kc+2][row] = v.z; Bs[kc+3][row] = v.w;
        }
        __syncthreads();
#pragma unroll
        for (int kk = 0; kk < BK; kk++) {
            float a[TM], b[TN];
#pragma unroll
            for (int i = 0; i < TM; i++) a[i] = As[kk][ty*TM + i];
#pragma unroll
            for (int j = 0; j < TN; j++) b[j] = Bs[kk][tx*TN + j];
#pragma unroll
            for (int i = 0; i < TM; i++)
#pragma unroll
                for (int j = 0; j < TN; j++)
                    acc[i][j] = fmaf(a[i], b[j], acc[i][j]);
        }
        __syncthreads();
    }

#pragma unroll
    for (int i = 0; i < TM; i++) {
        int row = bm + ty*TM + i;
#pragma unroll
        for (int j = 0; j < TN; j++) {
            int col = bn + tx*TN + j;
            float v = acc[i][j];
            if (MODE == 1) v += bias[col];
            if (MODE == 2) {
                v += bias[col];
                v = (v > 20.f) ? v : log1pf(__expf(v));
            }
            if (MODE == 3) v += C[(size_t)row*ldc + col];
            C[(size_t)row*ldc + col] = v;
        }
    }
}

// ---------------- RMSNorm over d_model=512 ----------------
__global__ void rmsnorm_kernel(const float* __restrict__ x, const float* __restrict__ w,
                               float* __restrict__ out) {
    int row = blockIdx.x;
    int tid = threadIdx.x;                       // 128 threads, 4 elems each
    const float4* xr = reinterpret_cast<const float4*>(x + (size_t)row*DM);
    float4 v = xr[tid];
    float ss = v.x*v.x + v.y*v.y + v.z*v.z + v.w*v.w;
#pragma unroll
    for (int o = 16; o; o >>= 1) ss += __shfl_xor_sync(0xffffffffu, ss, o);
    __shared__ float sred[4];
    if ((tid & 31) == 0) sred[tid >> 5] = ss;
    __syncthreads();
    float tot = sred[0] + sred[1] + sred[2] + sred[3];
    float scale = rsqrtf(tot * (1.f/(float)DM) + 1e-5f);
    float4 wv = reinterpret_cast<const float4*>(w)[tid];
    float4 o4;
    o4.x = v.x*scale*wv.x; o4.y = v.y*scale*wv.y;
    o4.z = v.z*scale*wv.z; o4.w = v.w*scale*wv.w;
    reinterpret_cast<float4*>(out + (size_t)row*DM)[tid] = o4;
}

// ---------------- depthwise causal conv(4) + bias + silu ----------------
__global__ void conv_silu_kernel(const float* __restrict__ xz, const float* __restrict__ cw,
                                 const float* __restrict__ cb, float* __restrict__ out) {
    size_t idx = (size_t)blockIdx.x * 256 + threadIdx.x;   // over B*L*ED
    int e = idx & (ED-1);
    int l = (idx >> 10) & (L_-1);
    float4 w4 = *reinterpret_cast<const float4*>(&cw[(size_t)e*4]);
    size_t base = (idx >> 10) * (size_t)(2*ED) + e;        // row (b*L+l) in xz, col e
    float acc = cb[e];
    acc = fmaf(w4.w, xz[base], acc);
    if (l >= 1) acc = fmaf(w4.z, xz[base - 2*ED], acc);
    if (l >= 2) acc = fmaf(w4.y, xz[base - 4*ED], acc);
    if (l >= 3) acc = fmaf(w4.x, xz[base - 6*ED], acc);
    out[idx] = acc * sigmoidf_(acc);
}

// ---------------- scan pass A: per-chunk local scan (h0=0) + decay product ----------------
__global__ void scan_passA(const float* __restrict__ delta, const float* __restrict__ u,
                           const float* __restrict__ dbc, const float* __restrict__ A_log,
                           float* __restrict__ hloc, float* __restrict__ Pout) {
    __shared__ float sB[LC][NST];
    int e = blockIdx.x * 128 + threadIdx.x;
    int c = blockIdx.y, b = blockIdx.z;
    for (int i = threadIdx.x; i < LC*NST; i += 128) {
        int row = i >> 4, col = i & 15;
        sB[row][col] = dbc[(size_t)(b*L_ + c*LC + row)*64 + 32 + col];
    }
    __syncthreads();

    float A[NST];
    bool fast = true;
#pragma unroll
    for (int n = 0; n < NST; n++) {
        float a = -__expf(A_log[(size_t)e*NST + n]);
        A[n] = a;
        fast = fast && (fabsf(a + (float)(n+1)) < 1e-4f * (float)(n+1));
    }

    float h[NST];
#pragma unroll
    for (int n = 0; n < NST; n++) h[n] = 0.f;
    float sd = 0.f;
    const float* dp = delta + (size_t)(b*L_ + c*LC)*ED + e;
    const float* up = u     + (size_t)(b*L_ + c*LC)*ED + e;

    if (fast) {
        for (int l = 0; l < LC; l++) {
            float dl = dp[(size_t)l*ED];
            float ul = up[(size_t)l*ED];
            float r  = __expf(-dl);
            float du = dl * ul;
            float p  = r;
            sd += dl;
#pragma unroll
            for (int n = 0; n < NST; n++) {
                h[n] = fmaf(p, h[n], du * sB[l][n]);
                p *= r;
            }
        }
    } else {
        for (int l = 0; l < LC; l++) {
            float dl = dp[(size_t)l*ED];
            float ul = up[(size_t)l*ED];
            float du = dl * ul;
            sd += dl;
#pragma unroll
            for (int n = 0; n < NST; n++) {
                float dA = __expf(dl * A[n]);
                h[n] = fmaf(dA, h[n], du * sB[l][n]);
            }
        }
    }
    size_t o = ((size_t)(b*CH + c)*ED + e)*NST;
#pragma unroll
    for (int n = 0; n < NST; n++) {
        hloc[o+n] = h[n];
        Pout[o+n] = __expf(A[n] * sd);   // exact: prod_l exp(dl*A) = exp(A*sum dl)
    }
}

// ---------------- scan combine: sequential over CH chunks (cheap) ----------------
__global__ void scan_combine(const float* __restrict__ hloc, const float* __restrict__ P,
                             float* __restrict__ Hin) {
    int idx = blockIdx.x * 256 + threadIdx.x;   // over B*ED*NST = 262144
    int n = idx & 15;
    int e = (idx >> 4) & (ED-1);
    int b = idx >> 14;
    float H = 0.f;
#pragma unroll
    for (int c = 0; c < CH; c++) {
        size_t o = ((size_t)(b*CH + c)*ED + e)*NST + n;
        Hin[o] = H;
        H = fmaf(P[o], H, hloc[o]);
    }
}

// ---------------- scan pass B: re-scan with true init; fused y, D-skip, silu(z) gate ----------------
__global__ void scan_passB(const float* __restrict__ delta, const float* __restrict__ u,
                           const float* __restrict__ dbc, const float* __restrict__ xz,
                           const float* __restrict__ A_log, const float* __restrict__ Dv,
                           const float* __restrict__ Hin, float* __restrict__ yout) {
    __shared__ float sB[LC][NST];
    __shared__ float sC[LC][NST];
    int e = blockIdx.x * 128 + threadIdx.x;
    int c = blockIdx.y, b = blockIdx.z;
    for (int i = threadIdx.x; i < LC*32; i += 128) {
        int row = i >> 5, col = i & 31;
        float v = dbc[(size_t)(b*L_ + c*LC + row)*64 + 32 + col];
        if (col < 16) sB[row][col] = v; else sC[row][col-16] = v;
    }
    __syncthreads();

    float A[NST];
    bool fast = true;
#pragma unroll
    for (int n = 0; n < NST; n++) {
        float a = -__expf(A_log[(size_t)e*NST + n]);
        A[n] = a;
        fast = fast && (fabsf(a + (float)(n+1)) < 1e-4f * (float)(n+1));
    }

    float h[NST];
    size_t oH = ((size_t)(b*CH + c)*ED + e)*NST;
#pragma unroll
    for (int n4 = 0; n4 < NST; n4 += 4) {
        float4 v = *reinterpret_cast<const float4*>(&Hin[oH + n4]);
        h[n4+0] = v.x; h[n4+1] = v.y; h[n4+2] = v.z; h[n4+3] = v.w;
    }
    float Dp = Dv[e];

    const float* dp = delta + (size_t)(b*L_ + c*LC)*ED + e;
    const float* up = u     + (size_t)(b*L_ + c*LC)*ED + e;
    const float* zp = xz    + (size_t)(b*L_ + c*LC)*(2*ED) + ED + e;
    float*       yp = yout  + (size_t)(b*L_ + c*LC)*ED + e;

    if (fast) {
        for (int l = 0; l < LC; l++) {
            float dl = dp[(size_t)l*ED];
            float ul = up[(size_t)l*ED];
            float r  = __expf(-dl);
            float du = dl * ul;
            float p  = r;
            float y  = 0.f;
#pragma unroll
            for (int n = 0; n < NST; n++) {
                h[n] = fmaf(p, h[n], du * sB[l][n]);
                y = fmaf(h[n], sC[l][n], y);
                p *= r;
            }
            float zl = zp[(size_t)l*(2*ED)];
            float yt = fmaf(Dp, ul, y);
            yp[(size_t)l*ED] = yt * zl * sigmoidf_(zl);
        }
    } else {
        for (int l = 0; l < LC; l++) {
            float dl = dp[(size_t)l*ED];
            float ul = up[(size_t)l*ED];
            float du = dl * ul;
            float y  = 0.f;
#pragma unroll
            for (int n = 0; n < NST; n++) {
                float dA = __expf(dl * A[n]);
                h[n] = fmaf(dA, h[n], du * sB[l][n]);
                y = fmaf(h[n], sC[l][n], y);
            }
            float zl = zp[(size_t)l*(2*ED)];
            float yt = fmaf(Dp, ul, y);
            yp[(size_t)l*ED] = yt * zl * sigmoidf_(zl);
        }
    }
}

// ---------------- head: y = h[:, -1, :] @ head_w^T + head_b, transposed write ----------------
__global__ void head_kernel(const float* __restrict__ h, const float* __restrict__ hw,
                            const float* __restrict__ hb, float* __restrict__ out) {
    int w    = blockIdx.x * 8 + (threadIdx.x >> 5);   // 49152 warps
    int lane = threadIdx.x & 31;
    int n = w % 3072;
    int b = w / 3072;
    const float4* hr4 = reinterpret_cast<const float4*>(h + ((size_t)b*L_ + (L_-1))*DM);
    const float4* wr4 = reinterpret_cast<const float4*>(hw + (size_t)n*DM);
    float s = 0.f;
#pragma unroll
    for (int i = 0; i < 4; i++) {
        int k4 = lane + i*32;
        float4 a = hr4[k4];
        float4 ww = wr4[k4];
        s += a.x*ww.x + a.y*ww.y + a.z*ww.z + a.w*ww.w;
    }
#pragma unroll
    for (int o = 16; o; o >>= 1) s += __shfl_xor_sync(0xffffffffu, s, o);
    if (lane == 0) {
        int c = n & 31, t = n >> 5;   // n = t*32 + c ; out[b, c, t]
        out[(size_t)b*3072 + (size_t)c*96 + t] = s + hb[n];
    }
}

// ---------------- launch ----------------
extern "C" void kernel_launch(void* const* d_in, const int* in_sizes, int n_in,
                              void* d_out, int out_size) {
    const float* x        = (const float*)d_in[0];
    const float* embed_w  = (const float*)d_in[1];
    const float* embed_b  = (const float*)d_in[2];
    const float* norm_w   = (const float*)d_in[3];
    const float* in_w     = (const float*)d_in[4];
    const float* conv_w   = (const float*)d_in[5];
    const float* conv_b   = (const float*)d_in[6];
    const float* xp_w     = (const float*)d_in[7];
    const float* dt_w     = (const float*)d_in[8];
    const float* dt_b     = (const float*)d_in[9];
    const float* A_log    = (const float*)d_in[10];
    const float* Dv       = (const float*)d_in[11];
    const float* out_w    = (const float*)d_in[12];
    const float* head_w   = (const float*)d_in[13];
    const float* head_b   = (const float*)d_in[14];
    float* out = (float*)d_out;

    float *h, *nrm, *xz, *xc, *dbc, *delta, *y, *hloc, *P, *Hin, *xT;
    cudaGetSymbolAddress((void**)&h,     g_h);
    cudaGetSymbolAddress((void**)&nrm,   g_nrm);
    cudaGetSymbolAddress((void**)&xz,    g_xz);
    cudaGetSymbolAddress((void**)&xc,    g_xc);
    cudaGetSymbolAddress((void**)&dbc,   g_dbc);
    cudaGetSymbolAddress((void**)&delta, g_delta);
    cudaGetSymbolAddress((void**)&y,     g_y);
    cudaGetSymbolAddress((void**)&hloc,  g_hloc);
    cudaGetSymbolAddress((void**)&P,     g_P);
    cudaGetSymbolAddress((void**)&Hin,   g_Hin);
    cudaGetSymbolAddress((void**)&xT,    g_xT);

    // embed: h = x^T @ embed_w^T + embed_b
    transpose_x_kernel<<<dim3(L_/32, B_), dim3(32, 32)>>>(x, xT);
    sgemm_kernel<128,128,16,8,8,1><<<dim3(DM/128, MROWS/128), 256>>>(
        xT, embed_w, h, embed_b, MROWS, DM, 32, 32, 32, DM);

    for (int i = 0; i < NL; i++) {
        rmsnorm_kernel<<<MROWS, 128>>>(h, norm_w + (size_t)i*DM, nrm);

        // xz = rms @ in_proj^T   (M=16384, N=2048, K=512)
        sgemm_kernel<128,128,16,8,8,0><<<dim3(2*ED/128, MROWS/128), 256>>>(
            nrm, in_w + (size_t)i*2*ED*DM, xz, nullptr, MROWS, 2*ED, DM, DM, DM, 2*ED);

        // depthwise causal conv + silu
        conv_silu_kernel<<<(MROWS*ED)/256, 256>>>(
            xz, conv_w + (size_t)i*ED*4, conv_b + (size_t)i*ED, xc);

        // dbc = xc @ x_proj^T   (N=64, K=1024)
        sgemm_kernel<128,64,16,8,4,0><<<dim3(1, MROWS/128), 256>>>(
            xc, xp_w + (size_t)i*64*ED, dbc, nullptr, MROWS, 64, ED, ED, ED, 64);

        // delta = softplus(dbc[:, :32] @ dt_w^T + dt_b)   (N=1024, K=32, lda=64)
        sgemm_kernel<128,128,16,8,8,2><<<dim3(ED/128, MROWS/128), 256>>>(
            dbc, dt_w + (size_t)i*ED*DR, delta, dt_b + (size_t)i*ED,
            MROWS, ED, DR, 64, DR, ED);

        // chunked selective scan
        scan_passA<<<dim3(ED/128, CH, B_), 128>>>(
            delta, xc, dbc, A_log + (size_t)i*ED*NST, hloc, P);
        scan_combine<<<(B_*ED*NST)/256, 256>>>(hloc, P, Hin);
        scan_passB<<<dim3(ED/128, CH, B_), 128>>>(
            delta, xc, dbc, xz, A_log + (size_t)i*ED*NST, Dv + (size_t)i*ED, Hin, y);

        // h += y @ out_proj^T   (N=512, K=1024)
        sgemm_kernel<128,128,16,8,8,3><<<dim3(DM/128, MROWS/128), 256>>>(
            y, out_w + (size_t)i*DM*ED, h, nullptr, MROWS, DM, ED, ED, ED, DM);
    }

    head_kernel<<<(B_*3072)/8, 256>>>(h, head_w, head_b, out);
}

// round 4
// speedup vs baseline: 1.7550x; 1.7550x over previous
#include <cuda_runtime.h>
#include <cuda_bf16.h>
#include <math.h>
#include <stdint.h>

// ---------------- problem constants ----------------
#define B_   16
#define L_   1024
#define DM   512      // d_model
#define ED   1024     // d_inner
#define NST  16       // d_state
#define NL   4
#define DR   32       // dt_rank
#define CH   8        // scan chunks
#define LC   128      // chunk length  (CH*LC == L_)
#define MROWS (B_*L_) // 16384

// ---------------- scratch (device globals; no allocation allowed) ----------------
__device__ __align__(16) float g_h    [(size_t)MROWS*DM];
__device__ __align__(16) float g_xz   [(size_t)MROWS*2*ED];
__device__ __align__(16) float g_xc   [(size_t)MROWS*ED];
__device__ __align__(16) float g_dbc  [(size_t)MROWS*64];
__device__ __align__(16) float g_delta[(size_t)MROWS*ED];
__device__ __align__(16) float g_hloc [(size_t)B_*CH*ED*NST];
__device__ __align__(16) float g_P    [(size_t)B_*CH*ED*NST];
__device__ __align__(16) float g_Hin  [(size_t)B_*CH*ED*NST];
__device__ __align__(16) float g_xT   [(size_t)MROWS*32];
// bf16 split activations (A operand). lda=512 (rmsnorm out) then lda=1024 (y).
__device__ __align__(16) __nv_bfloat16 g_ah[(size_t)MROWS*ED];
__device__ __align__(16) __nv_bfloat16 g_al[(size_t)MROWS*ED];
// bf16 split weights
__device__ __align__(16) __nv_bfloat16 g_wih[(size_t)NL*2*ED*DM];
__device__ __align__(16) __nv_bfloat16 g_wil[(size_t)NL*2*ED*DM];
__device__ __align__(16) __nv_bfloat16 g_woh[(size_t)NL*DM*ED];
__device__ __align__(16) __nv_bfloat16 g_wol[(size_t)NL*DM*ED];

__device__ __forceinline__ float sigmoidf_(float x) { return 1.f / (1.f + __expf(-x)); }

// ================= mma.sync bf16 helpers (non-arch-gated PTX) =================
__device__ __forceinline__ void ldm_x4(uint32_t (&r)[4], uint32_t a) {
    asm volatile("ldmatrix.sync.aligned.m8n8.x4.shared.b16 {%0,%1,%2,%3}, [%4];"
                 : "=r"(r[0]), "=r"(r[1]), "=r"(r[2]), "=r"(r[3]) : "r"(a));
}
__device__ __forceinline__ void mma_bf16(float (&d)[4], const uint32_t (&a)[4],
                                         uint32_t b0, uint32_t b1) {
    asm volatile(
        "mma.sync.aligned.m16n8k16.row.col.f32.bf16.bf16.f32 "
        "{%0,%1,%2,%3}, {%4,%5,%6,%7}, {%8,%9}, {%0,%1,%2,%3};"
        : "+f"(d[0]), "+f"(d[1]), "+f"(d[2]), "+f"(d[3])
        : "r"(a[0]), "r"(a[1]), "r"(a[2]), "r"(a[3]), "r"(b0), "r"(b1));
}
__device__ __forceinline__ void cp_async16(uint32_t sdst, const void* gsrc) {
    asm volatile("cp.async.cg.shared.global [%0], [%1], 16;" :: "r"(sdst), "l"(gsrc));
}
__device__ __forceinline__ void cp_commit() { asm volatile("cp.async.commit_group;"); }
__device__ __forceinline__ void cp_wait1()  { asm volatile("cp.async.wait_group 1;"); }
__device__ __forceinline__ void cp_wait0()  { asm volatile("cp.async.wait_group 0;"); }

// ================= split-bf16 tensor-core GEMM =================
// C(MxN) = A(MxK)*B(NxK)^T  via  Ah*Bh + Ah*Bl + Al*Bh  (bf16 mma, fp32 accum)
// CTA tile 128x128, 8 warps (2x4), warp tile 64x32, BK=32, 2-stage cp.async pipe.
// SMEM row pitch: 80 bytes (32 bf16 + 8 pad) -> conflict-free ldmatrix.
#define ROWB   80
#define TEN_SZ (128*ROWB)          // 10240 B per tensor tile
#define STG_SZ (4*TEN_SZ)          // 40960 B per stage
#define MMA_SMEM (2*STG_SZ)        // 81920 B

template<int MODE>  // 0: store, 1: C += result
__global__ __launch_bounds__(256)
void mma_gemm(const __nv_bfloat16* __restrict__ Ah, const __nv_bfloat16* __restrict__ Al,
              const __nv_bfloat16* __restrict__ Bh, const __nv_bfloat16* __restrict__ Bl,
              float* __restrict__ C, int K, int lda, int ldb, int ldc) {
    extern __shared__ char smem[];
    const uint32_t sbase = (uint32_t)__cvta_generic_to_shared(smem);
    const int tid  = threadIdx.x;
    const int wid  = tid >> 5, lane = tid & 31;
    const int wm   = wid >> 2;          // 0..1  (64 rows each)
    const int wn   = wid & 3;           // 0..3  (32 cols each)
    const int bm   = blockIdx.y * 128;
    const int bn   = blockIdx.x * 128;
    const int NC   = K >> 5;

    float acc[4][4][4];
#pragma unroll
    for (int i = 0; i < 4; i++)
#pragma unroll
        for (int j = 0; j < 4; j++)
#pragma unroll
            for (int q = 0; q < 4; q++) acc[i][j][q] = 0.f;

    // per-thread load coords: 512 16B-chunks per tensor, 2 per thread
    const int lrow0 = tid >> 2,           lkc0 = (tid & 3);
    const int lrow1 = (tid + 256) >> 2,   lkc1 = (tid & 3);

    const __nv_bfloat16* gA0h = Ah + (size_t)(bm + lrow0) * lda + lkc0 * 8;
    const __nv_bfloat16* gA1h = Ah + (size_t)(bm + lrow1) * lda + lkc1 * 8;
    const __nv_bfloat16* gA0l = Al + (size_t)(bm + lrow0) * lda + lkc0 * 8;
    const __nv_bfloat16* gA1l = Al + (size_t)(bm + lrow1) * lda + lkc1 * 8;
    const __nv_bfloat16* gB0h = Bh + (size_t)(bn + lrow0) * ldb + lkc0 * 8;
    const __nv_bfloat16* gB1h = Bh + (size_t)(bn + lrow1) * ldb + lkc1 * 8;
    const __nv_bfloat16* gB0l = Bl + (size_t)(bn + lrow0) * ldb + lkc0 * 8;
    const __nv_bfloat16* gB1l = Bl + (size_t)(bn + lrow1) * ldb + lkc1 * 8;
    const uint32_t s0 = sbase + lrow0 * ROWB + lkc0 * 16;
    const uint32_t s1 = sbase + lrow1 * ROWB + lkc1 * 16;

#define LOAD_STAGE(c, s) do {                                            \
        int koff = (c) << 5;                                             \
        uint32_t st = (uint32_t)(s) * STG_SZ;                            \
        cp_async16(s0 + st,            gA0h + koff);                     \
        cp_async16(s1 + st,            gA1h + koff);                     \
        cp_async16(s0 + st + TEN_SZ,   gA0l + koff);                     \
        cp_async16(s1 + st + TEN_SZ,   gA1l + koff);                     \
        cp_async16(s0 + st + 2*TEN_SZ, gB0h + koff);                     \
        cp_async16(s1 + st + 2*TEN_SZ, gB1h + koff);                     \
        cp_async16(s0 + st + 3*TEN_SZ, gB0l + koff);                     \
        cp_async16(s1 + st + 3*TEN_SZ, gB1l + koff);                     \
        cp_commit();                                                     \
    } while (0)

    LOAD_STAGE(0, 0);
    if (NC > 1) LOAD_STAGE(1, 1);

    // ldmatrix lane addressing
    const int aRow = (lane & 15);                         // within 16-row frag
    const int aKby = ((lane >> 4) << 4);                  // 0 or 16 bytes (k 0/8)
    const int bRow = (lane & 7) | ((lane >> 4) << 3);     // within 16-n pair
    const int bKby = (((lane >> 3) & 1) << 4);

    for (int c = 0; c < NC; c++) {
        if (c + 1 < NC) cp_wait1(); else cp_wait0();
        __syncthreads();
        const uint32_t st = sbase + (uint32_t)(c & 1) * STG_SZ;
        const uint32_t sAh = st, sAl = st + TEN_SZ, sBh = st + 2*TEN_SZ, sBl = st + 3*TEN_SZ;

#pragma unroll
        for (int k16 = 0; k16 < 2; k16++) {
            const int kb = k16 * 32;   // bytes into row (16 bf16)
            uint32_t ah[4][4], al[4][4], bh[2][4], bl[2][4];
#pragma unroll
            for (int mf = 0; mf < 4; mf++) {
                uint32_t off = (uint32_t)(wm*64 + mf*16 + aRow) * ROWB + kb + aKby;
                ldm_x4(ah[mf], sAh + off);
                ldm_x4(al[mf], sAl + off);
            }
#pragma unroll
            for (int nf2 = 0; nf2 < 2; nf2++) {
                uint32_t off = (uint32_t)(wn*32 + nf2*16 + bRow) * ROWB + kb + bKby;
                ldm_x4(bh[nf2], sBh + off);
                ldm_x4(bl[nf2], sBl + off);
            }
#pragma unroll
            for (int mf = 0; mf < 4; mf++)
#pragma unroll
                for (int nf = 0; nf < 4; nf++) {
                    uint32_t b0h = bh[nf>>1][(nf&1)*2], b1h = bh[nf>>1][(nf&1)*2+1];
                    uint32_t b0l = bl[nf>>1][(nf&1)*2], b1l = bl[nf>>1][(nf&1)*2+1];
                    mma_bf16(acc[mf][nf], ah[mf], b0h, b1h);
                    mma_bf16(acc[mf][nf], ah[mf], b0l, b1l);
                    mma_bf16(acc[mf][nf], al[mf], b0h, b1h);
                }
        }
        __syncthreads();
        if (c + 2 < NC) LOAD_STAGE(c + 2, c & 1);
    }

    // epilogue: direct register -> gmem (float2 stores)
    const int erow = lane >> 2;
    const int ecol = (lane & 3) * 2;
#pragma unroll
    for (int mf = 0; mf < 4; mf++) {
#pragma unroll
        for (int nf = 0; nf < 4; nf++) {
            int row0 = bm + wm*64 + mf*16 + erow;
            int col  = bn + wn*32 + nf*8 + ecol;
            float* p0 = C + (size_t)row0 * ldc + col;
            float* p1 = C + (size_t)(row0 + 8) * ldc + col;
            float2 v0 = make_float2(acc[mf][nf][0], acc[mf][nf][1]);
            float2 v1 = make_float2(acc[mf][nf][2], acc[mf][nf][3]);
            if (MODE == 1) {
                float2 o0 = *reinterpret_cast<float2*>(p0);
                float2 o1 = *reinterpret_cast<float2*>(p1);
                v0.x += o0.x; v0.y += o0.y; v1.x += o1.x; v1.y += o1.y;
            }
            *reinterpret_cast<float2*>(p0) = v0;
            *reinterpret_cast<float2*>(p1) = v1;
        }
    }
#undef LOAD_STAGE
}

// ---------------- fp32 -> bf16 hi/lo split ----------------
__global__ void cvt_split_kernel(const float* __restrict__ x, __nv_bfloat16* __restrict__ h,
                                 __nv_bfloat16* __restrict__ l, int n) {
    int i = blockIdx.x * 256 + threadIdx.x;
    if (i < n) {
        float v = x[i];
        __nv_bfloat16 hb = __float2bfloat16(v);
        h[i] = hb;
        l[i] = __float2bfloat16(v - __bfloat162float(hb));
    }
}

// ---------------- transpose x: (B,32,L) -> (B*L, 32) ----------------
__global__ void transpose_x_kernel(const float* __restrict__ x, float* __restrict__ xT) {
    __shared__ float t[32][33];
    int b  = blockIdx.y;
    int l0 = blockIdx.x * 32;
    int tx = threadIdx.x, ty = threadIdx.y;
    t[ty][tx] = x[((size_t)b*32 + ty)*L_ + l0 + tx];
    __syncthreads();
    xT[((size_t)b*L_ + l0 + ty)*32 + tx] = t[tx][ty];
}

// ---------------- generic SGEMM (small GEMMs): C = A * B^T (+epilogue) ----------------
// MODE: 0=store, 1=+bias, 2=softplus(+bias)
template<int BM, int BN, int BK, int TM, int TN, int MODE>
__global__ __launch_bounds__((BM/TM)*(BN/TN))
void sgemm_kernel(const float* __restrict__ A, const float* __restrict__ Bw,
                  float* __restrict__ C, const float* __restrict__ bias,
                  int M, int N, int K, int lda, int ldb, int ldc) {
    constexpr int THREADS = (BM/TM)*(BN/TN);
    __shared__ float As[BK][BM];
    __shared__ float Bs[BK][BN];
    const int tid = threadIdx.x;
    const int bm  = blockIdx.y * BM;
    const int bn  = blockIdx.x * BN;
    const int tx  = tid % (BN/TN);
    const int ty  = tid / (BN/TN);

    float acc[TM][TN];
#pragma unroll
    for (int i = 0; i < TM; i++)
#pragma unroll
        for (int j = 0; j < TN; j++) acc[i][j] = 0.f;

    constexpr int AVEC = BM*BK/4/THREADS;
    constexpr int BVEC = BN*BK/4/THREADS;

    for (int k0 = 0; k0 < K; k0 += BK) {
#pragma unroll
        for (int i = 0; i < AVEC; i++) {
            int idx = tid + i*THREADS;
            int row = idx / (BK/4);
            int kc  = (idx % (BK/4)) * 4;
            float4 v = *reinterpret_cast<const float4*>(&A[(size_t)(bm+row)*lda + k0 + kc]);
            As[kc+0][row] = v.x; As[kc+1][row] = v.y; As[kc+2][row] = v.z; As[kc+3][row] = v.w;
        }
#pragma unroll
        for (int i = 0; i < BVEC; i++) {
            int idx = tid + i*THREADS;
            int row = idx / (BK/4);
            int kc  = (idx % (BK/4)) * 4;
            float4 v = *reinterpret_cast<const float4*>(&Bw[(size_t)(bn+row)*ldb + k0 + kc]);
            Bs[kc+0][row] = v.x; Bs[kc+1][row] = v.y; Bs[kc+2][row] = v.z; Bs[kc+3][row] = v.w;
        }
        __syncthreads();
#pragma unroll
        for (int kk = 0; kk < BK; kk++) {
            float a[TM], b[TN];
#pragma unroll
            for (int i = 0; i < TM; i++) a[i] = As[kk][ty*TM + i];
#pragma unroll
            for (int j = 0; j < TN; j++) b[j] = Bs[kk][tx*TN + j];
#pragma unroll
            for (int i = 0; i < TM; i++)
#pragma unroll
                for (int j = 0; j < TN; j++)
                    acc[i][j] = fmaf(a[i], b[j], acc[i][j]);
        }
        __syncthreads();
    }

#pragma unroll
    for (int i = 0; i < TM; i++) {
        int row = bm + ty*TM + i;
#pragma unroll
        for (int j = 0; j < TN; j++) {
            int col = bn + tx*TN + j;
            float v = acc[i][j];
            if (MODE == 1) v += bias[col];
            if (MODE == 2) {
                v += bias[col];
                v = (v > 20.f) ? v : log1pf(__expf(v));
            }
            C[(size_t)row*ldc + col] = v;
        }
    }
}

// ---------------- RMSNorm over d_model=512, fused bf16 hi/lo output ----------------
__global__ void rmsnorm_kernel(const float* __restrict__ x, const float* __restrict__ w,
                               __nv_bfloat16* __restrict__ oh, __nv_bfloat16* __restrict__ ol) {
    int row = blockIdx.x;
    int tid = threadIdx.x;                       // 128 threads, 4 elems each
    const float4* xr = reinterpret_cast<const float4*>(x + (size_t)row*DM);
    float4 v = xr[tid];
    float ss = v.x*v.x + v.y*v.y + v.z*v.z + v.w*v.w;
#pragma unroll
    for (int o = 16; o; o >>= 1) ss += __shfl_xor_sync(0xffffffffu, ss, o);
    __shared__ float sred[4];
    if ((tid & 31) == 0) sred[tid >> 5] = ss;
    __syncthreads();
    float tot = sred[0] + sred[1] + sred[2] + sred[3];
    float scale = rsqrtf(tot * (1.f/(float)DM) + 1e-5f);
    float4 wv = reinterpret_cast<const float4*>(w)[tid];
    float o0 = v.x*scale*wv.x, o1 = v.y*scale*wv.y, o2 = v.z*scale*wv.z, o3 = v.w*scale*wv.w;
    __nv_bfloat16 h0 = __float2bfloat16(o0), h1 = __float2bfloat16(o1);
    __nv_bfloat16 h2 = __float2bfloat16(o2), h3 = __float2bfloat16(o3);
    size_t off = (size_t)row*DM + tid*4;
    __nv_bfloat162* oh2 = reinterpret_cast<__nv_bfloat162*>(oh + off);
    __nv_bfloat162* ol2 = reinterpret_cast<__nv_bfloat162*>(ol + off);
    oh2[0] = __nv_bfloat162(h0, h1);
    oh2[1] = __nv_bfloat162(h2, h3);
    ol2[0] = __nv_bfloat162(__float2bfloat16(o0 - __bfloat162float(h0)),
                            __float2bfloat16(o1 - __bfloat162float(h1)));
    ol2[1] = __nv_bfloat162(__float2bfloat16(o2 - __bfloat162float(h2)),
                            __float2bfloat16(o3 - __bfloat162float(h3)));
}

// ---------------- depthwise causal conv(4) + bias + silu ----------------
__global__ void conv_silu_kernel(const float* __restrict__ xz, const float* __restrict__ cw,
                                 const float* __restrict__ cb, float* __restrict__ out) {
    size_t idx = (size_t)blockIdx.x * 256 + threadIdx.x;   // over B*L*ED
    int e = idx & (ED-1);
    int l = (idx >> 10) & (L_-1);
    float4 w4 = *reinterpret_cast<const float4*>(&cw[(size_t)e*4]);
    size_t base = (idx >> 10) * (size_t)(2*ED) + e;        // row (b*L+l) in xz, col e
    float acc = cb[e];
    acc = fmaf(w4.w, xz[base], acc);
    if (l >= 1) acc = fmaf(w4.z, xz[base - 2*ED], acc);
    if (l >= 2) acc = fmaf(w4.y, xz[base - 4*ED], acc);
    if (l >= 3) acc = fmaf(w4.x, xz[base - 6*ED], acc);
    out[idx] = acc * sigmoidf_(acc);
}

// ---------------- scan pass A: per-chunk local scan (h0=0) + decay product ----------------
__global__ void scan_passA(const float* __restrict__ delta, const float* __restrict__ u,
                           const float* __restrict__ dbc, const float* __restrict__ A_log,
                           float* __restrict__ hloc, float* __restrict__ Pout) {
    __shared__ float sB[LC][NST];
    int e = blockIdx.x * 128 + threadIdx.x;
    int c = blockIdx.y, b = blockIdx.z;
    for (int i = threadIdx.x; i < LC*NST; i += 128) {
        int row = i >> 4, col = i & 15;
        sB[row][col] = dbc[(size_t)(b*L_ + c*LC + row)*64 + 32 + col];
    }
    __syncthreads();

    float A[NST];
    bool fast = true;
#pragma unroll
    for (int n = 0; n < NST; n++) {
        float a = -__expf(A_log[(size_t)e*NST + n]);
        A[n] = a;
        fast = fast && (fabsf(a + (float)(n+1)) < 1e-4f * (float)(n+1));
    }

    float h[NST];
#pragma unroll
    for (int n = 0; n < NST; n++) h[n] = 0.f;
    float sd = 0.f;
    const float* dp = delta + (size_t)(b*L_ + c*LC)*ED + e;
    const float* up = u     + (size_t)(b*L_ + c*LC)*ED + e;

    if (fast) {
        for (int l = 0; l < LC; l++) {
            float dl = dp[(size_t)l*ED];
            float ul = up[(size_t)l*ED];
            float r  = __expf(-dl);
            float du = dl * ul;
            float p  = r;
            sd += dl;
#pragma unroll
            for (int n = 0; n < NST; n++) {
                h[n] = fmaf(p, h[n], du * sB[l][n]);
                p *= r;
            }
        }
    } else {
        for (int l = 0; l < LC; l++) {
            float dl = dp[(size_t)l*ED];
            float ul = up[(size_t)l*ED];
            float du = dl * ul;
            sd += dl;
#pragma unroll
            for (int n = 0; n < NST; n++) {
                float dA = __expf(dl * A[n]);
                h[n] = fmaf(dA, h[n], du * sB[l][n]);
            }
        }
    }
    size_t o = ((size_t)(b*CH + c)*ED + e)*NST;
#pragma unroll
    for (int n = 0; n < NST; n++) {
        hloc[o+n] = h[n];
        Pout[o+n] = __expf(A[n] * sd);
    }
}

// ---------------- scan combine: sequential over CH chunks ----------------
__global__ void scan_combine(const float* __restrict__ hloc, const float* __restrict__ P,
                             float* __restrict__ Hin) {
    int idx = blockIdx.x * 256 + threadIdx.x;   // over B*ED*NST = 262144
    int n = idx & 15;
    int e = (idx >> 4) & (ED-1);
    int b = idx >> 14;
    float H = 0.f;
#pragma unroll
    for (int c = 0; c < CH; c++) {
        size_t o = ((size_t)(b*CH + c)*ED + e)*NST + n;
        Hin[o] = H;
        H = fmaf(P[o], H, hloc[o]);
    }
}

// ---------------- scan pass B: re-scan with true init; fused y, D-skip, silu(z) gate, bf16 split out ----------------
__global__ void scan_passB(const float* __restrict__ delta, const float* __restrict__ u,
                           const float* __restrict__ dbc, const float* __restrict__ xz,
                           const float* __restrict__ A_log, const float* __restrict__ Dv,
                           const float* __restrict__ Hin,
                           __nv_bfloat16* __restrict__ yh, __nv_bfloat16* __restrict__ yl) {
    __shared__ float sB[LC][NST];
    __shared__ float sC[LC][NST];
    int e = blockIdx.x * 128 + threadIdx.x;
    int c = blockIdx.y, b = blockIdx.z;
    for (int i = threadIdx.x; i < LC*32; i += 128) {
        int row = i >> 5, col = i & 31;
        float v = dbc[(size_t)(b*L_ + c*LC + row)*64 + 32 + col];
        if (col < 16) sB[row][col] = v; else sC[row][col-16] = v;
    }
    __syncthreads();

    float A[NST];
    bool fast = true;
#pragma unroll
    for (int n = 0; n < NST; n++) {
        float a = -__expf(A_log[(size_t)e*NST + n]);
        A[n] = a;
        fast = fast && (fabsf(a + (float)(n+1)) < 1e-4f * (float)(n+1));
    }

    float h[NST];
    size_t oH = ((size_t)(b*CH + c)*ED + e)*NST;
#pragma unroll
    for (int n4 = 0; n4 < NST; n4 += 4) {
        float4 v = *reinterpret_cast<const float4*>(&Hin[oH + n4]);
        h[n4+0] = v.x; h[n4+1] = v.y; h[n4+2] = v.z; h[n4+3] = v.w;
    }
    float Dp = Dv[e];

    const float* dp = delta + (size_t)(b*L_ + c*LC)*ED + e;
    const float* up = u     + (size_t)(b*L_ + c*LC)*ED + e;
    const float* zp = xz    + (size_t)(b*L_ + c*LC)*(2*ED) + ED + e;
    size_t yo = (size_t)(b*L_ + c*LC)*ED + e;

    if (fast) {
        for (int l = 0; l < LC; l++) {
            float dl = dp[(size_t)l*ED];
            float ul = up[(size_t)l*ED];
            float r  = __expf(-dl);
            float du = dl * ul;
            float p  = r;
            float y  = 0.f;
#pragma unroll
            for (int n = 0; n < NST; n++) {
                h[n] = fmaf(p, h[n], du * sB[l][n]);
                y = fmaf(h[n], sC[l][n], y);
                p *= r;
            }
            float zl = zp[(size_t)l*(2*ED)];
            float yt = fmaf(Dp, ul, y) * zl * sigmoidf_(zl);
            __nv_bfloat16 hb = __float2bfloat16(yt);
            yh[yo + (size_t)l*ED] = hb;
            yl[yo + (size_t)l*ED] = __float2bfloat16(yt - __bfloat162float(hb));
        }
    } else {
        for (int l = 0; l < LC; l++) {
            float dl = dp[(size_t)l*ED];
            float ul = up[(size_t)l*ED];
            float du = dl * ul;
            float y  = 0.f;
#pragma unroll
            for (int n = 0; n < NST; n++) {
                float dA = __expf(dl * A[n]);
                h[n] = fmaf(dA, h[n], du * sB[l][n]);
                y = fmaf(h[n], sC[l][n], y);
            }
            float zl = zp[(size_t)l*(2*ED)];
            float yt = fmaf(Dp, ul, y) * zl * sigmoidf_(zl);
            __nv_bfloat16 hb = __float2bfloat16(yt);
            yh[yo + (size_t)l*ED] = hb;
            yl[yo + (size_t)l*ED] = __float2bfloat16(yt - __bfloat162float(hb));
        }
    }
}

// ---------------- head: y = h[:, -1, :] @ head_w^T + head_b, transposed write ----------------
__global__ void head_kernel(const float* __restrict__ h, const float* __restrict__ hw,
                            const float* __restrict__ hb, float* __restrict__ out) {
    int w    = blockIdx.x * 8 + (threadIdx.x >> 5);
    int lane = threadIdx.x & 31;
    int n = w % 3072;
    int b = w / 3072;
    const float4* hr4 = reinterpret_cast<const float4*>(h + ((size_t)b*L_ + (L_-1))*DM);
    const float4* wr4 = reinterpret_cast<const float4*>(hw + (size_t)n*DM);
    float s = 0.f;
#pragma unroll
    for (int i = 0; i < 4; i++) {
        int k4 = lane + i*32;
        float4 a = hr4[k4];
        float4 ww = wr4[k4];
        s += a.x*ww.x + a.y*ww.y + a.z*ww.z + a.w*ww.w;
    }
#pragma unroll
    for (int o = 16; o; o >>= 1) s += __shfl_xor_sync(0xffffffffu, s, o);
    if (lane == 0) {
        int c = n & 31, t = n >> 5;
        out[(size_t)b*3072 + (size_t)c*96 + t] = s + hb[n];
    }
}

// ---------------- launch ----------------
extern "C" void kernel_launch(void* const* d_in, const int* in_sizes, int n_in,
                              void* d_out, int out_size) {
    const float* x        = (const float*)d_in[0];
    const float* embed_w  = (const float*)d_in[1];
    const float* embed_b  = (const float*)d_in[2];
    const float* norm_w   = (const float*)d_in[3];
    const float* in_w     = (const float*)d_in[4];
    const float* conv_w   = (const float*)d_in[5];
    const float* conv_b   = (const float*)d_in[6];
    const float* xp_w     = (const float*)d_in[7];
    const float* dt_w     = (const float*)d_in[8];
    const float* dt_b     = (const float*)d_in[9];
    const float* A_log    = (const float*)d_in[10];
    const float* Dv       = (const float*)d_in[11];
    const float* out_w    = (const float*)d_in[12];
    const float* head_w   = (const float*)d_in[13];
    const float* head_b   = (const float*)d_in[14];
    float* out = (float*)d_out;

    float *h, *xz, *xc, *dbc, *delta, *hloc, *P, *Hin, *xT;
    __nv_bfloat16 *ah, *al, *wih, *wil, *woh, *wol;
    cudaGetSymbolAddress((void**)&h,     g_h);
    cudaGetSymbolAddress((void**)&xz,    g_xz);
    cudaGetSymbolAddress((void**)&xc,    g_xc);
    cudaGetSymbolAddress((void**)&dbc,   g_dbc);
    cudaGetSymbolAddress((void**)&delta, g_delta);
    cudaGetSymbolAddress((void**)&hloc,  g_hloc);
    cudaGetSymbolAddress((void**)&P,     g_P);
    cudaGetSymbolAddress((void**)&Hin,   g_Hin);
    cudaGetSymbolAddress((void**)&xT,    g_xT);
    cudaGetSymbolAddress((void**)&ah,    g_ah);
    cudaGetSymbolAddress((void**)&al,    g_al);
    cudaGetSymbolAddress((void**)&wih,   g_wih);
    cudaGetSymbolAddress((void**)&wil,   g_wil);
    cudaGetSymbolAddress((void**)&woh,   g_woh);
    cudaGetSymbolAddress((void**)&wol,   g_wol);

    cudaFuncSetAttribute(mma_gemm<0>, cudaFuncAttributeMaxDynamicSharedMemorySize, MMA_SMEM);
    cudaFuncSetAttribute(mma_gemm<1>, cudaFuncAttributeMaxDynamicSharedMemorySize, MMA_SMEM);

    // weight splits (all layers, once per launch)
    cvt_split_kernel<<<(NL*2*ED*DM + 255)/256, 256>>>(in_w,  wih, wil, NL*2*ED*DM);
    cvt_split_kernel<<<(NL*DM*ED   + 255)/256, 256>>>(out_w, woh, wol, NL*DM*ED);

    // embed: h = x^T @ embed_w^T + embed_b
    transpose_x_kernel<<<dim3(L_/32, B_), dim3(32, 32)>>>(x, xT);
    sgemm_kernel<128,128,16,8,8,1><<<dim3(DM/128, MROWS/128), 256>>>(
        xT, embed_w, h, embed_b, MROWS, DM, 32, 32, 32, DM);

    for (int i = 0; i < NL; i++) {
        // rmsnorm -> bf16 hi/lo (A operand for in_proj, lda=512)
        rmsnorm_kernel<<<MROWS, 128>>>(h, norm_w + (size_t)i*DM, ah, al);

        // xz = rms @ in_proj^T  (tensor-core split-bf16: M=16384, N=2048, K=512)
        mma_gemm<0><<<dim3(2*ED/128, MROWS/128), 256, MMA_SMEM>>>(
            ah, al, wih + (size_t)i*2*ED*DM, wil + (size_t)i*2*ED*DM,
            xz, DM, DM, DM, 2*ED);

        // depthwise causal conv + silu
        conv_silu_kernel<<<(MROWS*ED)/256, 256>>>(
            xz, conv_w + (size_t)i*ED*4, conv_b + (size_t)i*ED, xc);

        // dbc = xc @ x_proj^T   (N=64, K=1024)
        sgemm_kernel<128,64,16,8,4,0><<<dim3(1, MROWS/128), 256>>>(
            xc, xp_w + (size_t)i*64*ED, dbc, nullptr, MROWS, 64, ED, ED, ED, 64);

        // delta = softplus(dbc[:, :32] @ dt_w^T + dt_b)
        sgemm_kernel<128,128,16,8,8,2><<<dim3(ED/128, MROWS/128), 256>>>(
            dbc, dt_w + (size_t)i*ED*DR, delta, dt_b + (size_t)i*ED,
            MROWS, ED, DR, 64, DR, ED);

        // chunked selective scan (pass B emits y as bf16 hi/lo, lda=1024)
        scan_passA<<<dim3(ED/128, CH, B_), 128>>>(
            delta, xc, dbc, A_log + (size_t)i*ED*NST, hloc, P);
        scan_combine<<<(B_*ED*NST)/256, 256>>>(hloc, P, Hin);
        scan_passB<<<dim3(ED/128, CH, B_), 128>>>(
            delta, xc, dbc, xz, A_log + (size_t)i*ED*NST, Dv + (size_t)i*ED, Hin, ah, al);

        // h += y @ out_proj^T  (tensor-core split-bf16: M=16384, N=512, K=1024, residual)
        mma_gemm<1><<<dim3(DM/128, MROWS/128), 256, MMA_SMEM>>>(
            ah, al, woh + (size_t)i*DM*ED, wol + (size_t)i*DM*ED,
            h, ED, ED, ED, DM);
    }

    head_kernel<<<(B_*3072)/8, 256>>>(h, head_w, head_b, out);
}

// round 5
// speedup vs baseline: 1.8944x; 1.0795x over previous
#include <cuda_runtime.h>
#include <cuda_bf16.h>
#include <math.h>
#include <stdint.h>

// ---------------- problem constants ----------------
#define B_   16
#define L_   1024
#define DM   512      // d_model
#define ED   1024     // d_inner
#define NST  16       // d_state
#define NL   4
#define DR   32       // dt_rank
#define CH   8        // scan chunks
#define LC   128      // chunk length  (CH*LC == L_)
#define MROWS (B_*L_) // 16384

// ---------------- scratch (device globals; no allocation allowed) ----------------
__device__ __align__(16) float g_h    [(size_t)MROWS*DM];
__device__ __align__(16) float g_xz   [(size_t)MROWS*2*ED];
__device__ __align__(16) float g_xc   [(size_t)MROWS*ED];
__device__ __align__(16) float g_dbc  [(size_t)MROWS*64];
__device__ __align__(16) float g_delta[(size_t)MROWS*ED];
__device__ __align__(16) float g_hloc [(size_t)B_*CH*ED*NST];
__device__ __align__(16) float g_P    [(size_t)B_*CH*ED*NST];
__device__ __align__(16) float g_Hin  [(size_t)B_*CH*ED*NST];
__device__ __align__(16) float g_xT   [(size_t)MROWS*32];
// bf16 split activations (A operand). lda=512 (rmsnorm out) then lda=1024 (y).
__device__ __align__(16) __nv_bfloat16 g_ah[(size_t)MROWS*ED];
__device__ __align__(16) __nv_bfloat16 g_al[(size_t)MROWS*ED];
// bf16 split weights
__device__ __align__(16) __nv_bfloat16 g_wih[(size_t)NL*2*ED*DM];
__device__ __align__(16) __nv_bfloat16 g_wil[(size_t)NL*2*ED*DM];
__device__ __align__(16) __nv_bfloat16 g_woh[(size_t)NL*DM*ED];
__device__ __align__(16) __nv_bfloat16 g_wol[(size_t)NL*DM*ED];

__device__ __forceinline__ float sigmoidf_(float x) { return 1.f / (1.f + __expf(-x)); }

// ================= mma.sync bf16 helpers (non-arch-gated PTX) =================
__device__ __forceinline__ void ldm_x4(uint32_t (&r)[4], uint32_t a) {
    asm volatile("ldmatrix.sync.aligned.m8n8.x4.shared.b16 {%0,%1,%2,%3}, [%4];"
                 : "=r"(r[0]), "=r"(r[1]), "=r"(r[2]), "=r"(r[3]) : "r"(a));
}
__device__ __forceinline__ void mma_bf16(float (&d)[4], const uint32_t (&a)[4],
                                         uint32_t b0, uint32_t b1) {
    asm volatile(
        "mma.sync.aligned.m16n8k16.row.col.f32.bf16.bf16.f32 "
        "{%0,%1,%2,%3}, {%4,%5,%6,%7}, {%8,%9}, {%0,%1,%2,%3};"
        : "+f"(d[0]), "+f"(d[1]), "+f"(d[2]), "+f"(d[3])
        : "r"(a[0]), "r"(a[1]), "r"(a[2]), "r"(a[3]), "r"(b0), "r"(b1));
}
__device__ __forceinline__ void cp_async16(uint32_t sdst, const void* gsrc) {
    asm volatile("cp.async.cg.shared.global [%0], [%1], 16;" :: "r"(sdst), "l"(gsrc));
}
__device__ __forceinline__ void cp_commit() { asm volatile("cp.async.commit_group;"); }
__device__ __forceinline__ void cp_wait1()  { asm volatile("cp.async.wait_group 1;"); }

// ================= split-bf16 tensor-core GEMM =================
// C(MxN) = A(MxK)*B(NxK)^T via Ah*Bh + Ah*Bl + Al*Bh (bf16 mma, fp32 accum)
// CTA tile 128(M)x256(N), 512 threads = 16 warps (4x4), warp tile 32x64.
// BK=32, 3-stage cp.async pipeline. SMEM row pitch 80B (32 bf16 + 16B pad).
#define ROWB    80
#define A_TEN   (128*ROWB)               // 10240
#define B_TEN   (256*ROWB)               // 20480
#define STG_SZ  (2*A_TEN + 2*B_TEN)      // 61440
#define MMA_SMEM (3*STG_SZ)              // 184320

template<int MODE>  // 0: store, 1: C += result
__global__ __launch_bounds__(512, 1)
void mma_gemm(const __nv_bfloat16* __restrict__ Ah, const __nv_bfloat16* __restrict__ Al,
              const __nv_bfloat16* __restrict__ Bh, const __nv_bfloat16* __restrict__ Bl,
              float* __restrict__ C, int K, int lda, int ldb, int ldc) {
    extern __shared__ char smem[];
    const uint32_t sbase = (uint32_t)__cvta_generic_to_shared(smem);
    const int tid  = threadIdx.x;
    const int wid  = tid >> 5, lane = tid & 31;
    const int wm   = wid & 3;           // 0..3 : 32 rows each
    const int wn   = wid >> 2;          // 0..3 : 64 cols each
    const int bm   = blockIdx.y * 128;
    const int bn   = blockIdx.x * 256;
    const int NC   = K >> 5;

    float acc[2][8][4];
#pragma unroll
    for (int i = 0; i < 2; i++)
#pragma unroll
        for (int j = 0; j < 8; j++)
#pragma unroll
            for (int q = 0; q < 4; q++) acc[i][j][q] = 0.f;

    // load coords: A-chunk i in 0..511 (row=i>>2, kc=i&3), B-chunk i in 0..1023
    const int arow  = tid >> 2,          akc = tid & 3;          // A: 1 chunk per tensor
    const int brow0 = tid >> 2,          bkc0 = tid & 3;         // B: 2 chunks per tensor
    const int brow1 = (tid + 512) >> 2,  bkc1 = tid & 3;

    const __nv_bfloat16* gAh = Ah + (size_t)(bm + arow) * lda + akc * 8;
    const __nv_bfloat16* gAl = Al + (size_t)(bm + arow) * lda + akc * 8;
    const __nv_bfloat16* gB0h = Bh + (size_t)(bn + brow0) * ldb + bkc0 * 8;
    const __nv_bfloat16* gB1h = Bh + (size_t)(bn + brow1) * ldb + bkc1 * 8;
    const __nv_bfloat16* gB0l = Bl + (size_t)(bn + brow0) * ldb + bkc0 * 8;
    const __nv_bfloat16* gB1l = Bl + (size_t)(bn + brow1) * ldb + bkc1 * 8;
    const uint32_t sA  = sbase + arow  * ROWB + akc  * 16;
    const uint32_t sB0 = sbase + brow0 * ROWB + bkc0 * 16;
    const uint32_t sB1 = sbase + brow1 * ROWB + bkc1 * 16;

#define LOAD_STAGE(c, s) do {                                          \
        int koff = (c) << 5;                                           \
        uint32_t st = (uint32_t)(s) * STG_SZ;                          \
        cp_async16(sA  + st,                   gAh  + koff);           \
        cp_async16(sA  + st + A_TEN,           gAl  + koff);           \
        cp_async16(sB0 + st + 2*A_TEN,         gB0h + koff);           \
        cp_async16(sB1 + st + 2*A_TEN,         gB1h + koff);           \
        cp_async16(sB0 + st + 2*A_TEN + B_TEN, gB0l + koff);           \
        cp_async16(sB1 + st + 2*A_TEN + B_TEN, gB1l + koff);           \
        cp_commit();                                                   \
    } while (0)

    LOAD_STAGE(0, 0);
    LOAD_STAGE(1, 1);

    // ldmatrix lane addressing
    const int aRow = (lane & 15);                       // row within 16-row frag
    const int aKby = ((lane >> 4) << 4);                // 0/16 bytes (k 0..7 / 8..15)
    const int bRow = (lane & 7) | ((lane >> 4) << 3);
    const int bKby = (((lane >> 3) & 1) << 4);

    int stg = 0;  // stage index of chunk c (cycles 0,1,2)
    for (int c = 0; c < NC; c++) {
        cp_wait1();
        __syncthreads();
        int nstg = stg + 2; if (nstg >= 3) nstg -= 3;
        if (c + 2 < NC) LOAD_STAGE(c + 2, nstg);

        const uint32_t st  = sbase + (uint32_t)stg * STG_SZ;
        const uint32_t sAh_ = st, sAl_ = st + A_TEN;
        const uint32_t sBh_ = st + 2*A_TEN, sBl_ = st + 2*A_TEN + B_TEN;

#pragma unroll
        for (int k16 = 0; k16 < 2; k16++) {
            const int kb = k16 * 32;
            uint32_t ah[2][4], al[2][4];
#pragma unroll
            for (int mf = 0; mf < 2; mf++) {
                uint32_t off = (uint32_t)(wm*32 + mf*16 + aRow) * ROWB + kb + aKby;
                ldm_x4(ah[mf], sAh_ + off);
                ldm_x4(al[mf], sAl_ + off);
            }
#pragma unroll
            for (int nf2 = 0; nf2 < 4; nf2++) {
                uint32_t bh[4], bl[4];
                uint32_t off = (uint32_t)(wn*64 + nf2*16 + bRow) * ROWB + kb + bKby;
                ldm_x4(bh, sBh_ + off);
                ldm_x4(bl, sBl_ + off);
#pragma unroll
                for (int half = 0; half < 2; half++) {
                    uint32_t b0h = bh[half*2], b1h = bh[half*2+1];
                    uint32_t b0l = bl[half*2], b1l = bl[half*2+1];
#pragma unroll
                    for (int mf = 0; mf < 2; mf++) {
                        int nf = nf2*2 + half;
                        mma_bf16(acc[mf][nf], ah[mf], b0h, b1h);
                        mma_bf16(acc[mf][nf], ah[mf], b0l, b1l);
                        mma_bf16(acc[mf][nf], al[mf], b0h, b1h);
                    }
                }
            }
        }
        stg++; if (stg >= 3) stg = 0;
        __syncthreads();
    }

    // epilogue: direct register -> gmem (float2 stores)
    const int erow = lane >> 2;
    const int ecol = (lane & 3) * 2;
#pragma unroll
    for (int mf = 0; mf < 2; mf++) {
#pragma unroll
        for (int nf = 0; nf < 8; nf++) {
            int row0 = bm + wm*32 + mf*16 + erow;
            int col  = bn + wn*64 + nf*8 + ecol;
            float* p0 = C + (size_t)row0 * ldc + col;
            float* p1 = C + (size_t)(row0 + 8) * ldc + col;
            float2 v0 = make_float2(acc[mf][nf][0], acc[mf][nf][1]);
            float2 v1 = make_float2(acc[mf][nf][2], acc[mf][nf][3]);
            if (MODE == 1) {
                float2 o0 = *reinterpret_cast<float2*>(p0);
                float2 o1 = *reinterpret_cast<float2*>(p1);
                v0.x += o0.x; v0.y += o0.y; v1.x += o1.x; v1.y += o1.y;
            }
            *reinterpret_cast<float2*>(p0) = v0;
            *reinterpret_cast<float2*>(p1) = v1;
        }
    }
#undef LOAD_STAGE
}

// ---------------- fp32 -> bf16 hi/lo split ----------------
__global__ void cvt_split_kernel(const float* __restrict__ x, __nv_bfloat16* __restrict__ h,
                                 __nv_bfloat16* __restrict__ l, int n) {
    int i = blockIdx.x * 256 + threadIdx.x;
    if (i < n) {
        float v = x[i];
        __nv_bfloat16 hb = __float2bfloat16(v);
        h[i] = hb;
        l[i] = __float2bfloat16(v - __bfloat162float(hb));
    }
}

// ---------------- transpose x: (B,32,L) -> (B*L, 32) ----------------
__global__ void transpose_x_kernel(const float* __restrict__ x, float* __restrict__ xT) {
    __shared__ float t[32][33];
    int b  = blockIdx.y;
    int l0 = blockIdx.x * 32;
    int tx = threadIdx.x, ty = threadIdx.y;
    t[ty][tx] = x[((size_t)b*32 + ty)*L_ + l0 + tx];
    __syncthreads();
    xT[((size_t)b*L_ + l0 + ty)*32 + tx] = t[tx][ty];
}

// ---------------- generic SGEMM (small GEMMs): C = A * B^T (+epilogue) ----------------
// MODE: 0=store, 1=+bias, 2=softplus(+bias)
template<int BM, int BN, int BK, int TM, int TN, int MODE>
__global__ __launch_bounds__((BM/TM)*(BN/TN))
void sgemm_kernel(const float* __restrict__ A, const float* __restrict__ Bw,
                  float* __restrict__ C, const float* __restrict__ bias,
                  int M, int N, int K, int lda, int ldb, int ldc) {
    constexpr int THREADS = (BM/TM)*(BN/TN);
    __shared__ float As[BK][BM];
    __shared__ float Bs[BK][BN];
    const int tid = threadIdx.x;
    const int bm  = blockIdx.y * BM;
    const int bn  = blockIdx.x * BN;
    const int tx  = tid % (BN/TN);
    const int ty  = tid / (BN/TN);

    float acc[TM][TN];
#pragma unroll
    for (int i = 0; i < TM; i++)
#pragma unroll
        for (int j = 0; j < TN; j++) acc[i][j] = 0.f;

    constexpr int AVEC = BM*BK/4/THREADS;
    constexpr int BVEC = BN*BK/4/THREADS;

    for (int k0 = 0; k0 < K; k0 += BK) {
#pragma unroll
        for (int i = 0; i < AVEC; i++) {
            int idx = tid + i*THREADS;
            int row = idx / (BK/4);
            int kc  = (idx % (BK/4)) * 4;
            float4 v = *reinterpret_cast<const float4*>(&A[(size_t)(bm+row)*lda + k0 + kc]);
            As[kc+0][row] = v.x; As[kc+1][row] = v.y; As[kc+2][row] = v.z; As[kc+3][row] = v.w;
        }
#pragma unroll
        for (int i = 0; i < BVEC; i++) {
            int idx = tid + i*THREADS;
            int row = idx / (BK/4);
            int kc  = (idx % (BK/4)) * 4;
            float4 v = *reinterpret_cast<const float4*>(&Bw[(size_t)(bn+row)*ldb + k0 + kc]);
            Bs[kc+0][row] = v.x; Bs[kc+1][row] = v.y; Bs[kc+2][row] = v.z; Bs[kc+3][row] = v.w;
        }
        __syncthreads();
#pragma unroll
        for (int kk = 0; kk < BK; kk++) {
            float a[TM], b[TN];
#pragma unroll
            for (int i = 0; i < TM; i++) a[i] = As[kk][ty*TM + i];
#pragma unroll
            for (int j = 0; j < TN; j++) b[j] = Bs[kk][tx*TN + j];
#pragma unroll
            for (int i = 0; i < TM; i++)
#pragma unroll
                for (int j = 0; j < TN; j++)
                    acc[i][j] = fmaf(a[i], b[j], acc[i][j]);
        }
        __syncthreads();
    }

#pragma unroll
    for (int i = 0; i < TM; i++) {
        int row = bm + ty*TM + i;
#pragma unroll
        for (int j = 0; j < TN; j++) {
            int col = bn + tx*TN + j;
            float v = acc[i][j];
            if (MODE == 1) v += bias[col];
            if (MODE == 2) {
                v += bias[col];
                v = (v > 20.f) ? v : log1pf(__expf(v));
            }
            C[(size_t)row*ldc + col] = v;
        }
    }
}

// ---------------- RMSNorm over d_model=512, fused bf16 hi/lo output ----------------
__global__ void rmsnorm_kernel(const float* __restrict__ x, const float* __restrict__ w,
                               __nv_bfloat16* __restrict__ oh, __nv_bfloat16* __restrict__ ol) {
    int row = blockIdx.x;
    int tid = threadIdx.x;                       // 128 threads, 4 elems each
    const float4* xr = reinterpret_cast<const float4*>(x + (size_t)row*DM);
    float4 v = xr[tid];
    float ss = v.x*v.x + v.y*v.y + v.z*v.z + v.w*v.w;
#pragma unroll
    for (int o = 16; o; o >>= 1) ss += __shfl_xor_sync(0xffffffffu, ss, o);
    __shared__ float sred[4];
    if ((tid & 31) == 0) sred[tid >> 5] = ss;
    __syncthreads();
    float tot = sred[0] + sred[1] + sred[2] + sred[3];
    float scale = rsqrtf(tot * (1.f/(float)DM) + 1e-5f);
    float4 wv = reinterpret_cast<const float4*>(w)[tid];
    float o0 = v.x*scale*wv.x, o1 = v.y*scale*wv.y, o2 = v.z*scale*wv.z, o3 = v.w*scale*wv.w;
    __nv_bfloat16 h0 = __float2bfloat16(o0), h1 = __float2bfloat16(o1);
    __nv_bfloat16 h2 = __float2bfloat16(o2), h3 = __float2bfloat16(o3);
    size_t off = (size_t)row*DM + tid*4;
    __nv_bfloat162* oh2 = reinterpret_cast<__nv_bfloat162*>(oh + off);
    __nv_bfloat162* ol2 = reinterpret_cast<__nv_bfloat162*>(ol + off);
    oh2[0] = __nv_bfloat162(h0, h1);
    oh2[1] = __nv_bfloat162(h2, h3);
    ol2[0] = __nv_bfloat162(__float2bfloat16(o0 - __bfloat162float(h0)),
                            __float2bfloat16(o1 - __bfloat162float(h1)));
    ol2[1] = __nv_bfloat162(__float2bfloat16(o2 - __bfloat162float(h2)),
                            __float2bfloat16(o3 - __bfloat162float(h3)));
}

// ---------------- depthwise causal conv(4) + bias + silu ----------------
__global__ void conv_silu_kernel(const float* __restrict__ xz, const float* __restrict__ cw,
                                 const float* __restrict__ cb, float* __restrict__ out) {
    size_t idx = (size_t)blockIdx.x * 256 + threadIdx.x;   // over B*L*ED
    int e = idx & (ED-1);
    int l = (idx >> 10) & (L_-1);
    float4 w4 = *reinterpret_cast<const float4*>(&cw[(size_t)e*4]);
    size_t base = (idx >> 10) * (size_t)(2*ED) + e;        // row (b*L+l) in xz, col e
    float acc = cb[e];
    acc = fmaf(w4.w, xz[base], acc);
    if (l >= 1) acc = fmaf(w4.z, xz[base - 2*ED], acc);
    if (l >= 2) acc = fmaf(w4.y, xz[base - 4*ED], acc);
    if (l >= 3) acc = fmaf(w4.x, xz[base - 6*ED], acc);
    out[idx] = acc * sigmoidf_(acc);
}

// ---------------- scan pass A: per-chunk local scan (h0=0) + decay product ----------------
__global__ void scan_passA(const float* __restrict__ delta, const float* __restrict__ u,
                           const float* __restrict__ dbc, const float* __restrict__ A_log,
                           float* __restrict__ hloc, float* __restrict__ Pout) {
    __shared__ float sB[LC][NST];
    int e = blockIdx.x * 128 + threadIdx.x;
    int c = blockIdx.y, b = blockIdx.z;
    for (int i = threadIdx.x; i < LC*NST; i += 128) {
        int row = i >> 4, col = i & 15;
        sB[row][col] = dbc[(size_t)(b*L_ + c*LC + row)*64 + 32 + col];
    }
    __syncthreads();

    float A[NST];
    bool fast = true;
#pragma unroll
    for (int n = 0; n < NST; n++) {
        float a = -__expf(A_log[(size_t)e*NST + n]);
        A[n] = a;
        fast = fast && (fabsf(a + (float)(n+1)) < 1e-4f * (float)(n+1));
    }

    float h[NST];
#pragma unroll
    for (int n = 0; n < NST; n++) h[n] = 0.f;
    float sd = 0.f;
    const float* dp = delta + (size_t)(b*L_ + c*LC)*ED + e;
    const float* up = u     + (size_t)(b*L_ + c*LC)*ED + e;

    if (fast) {
        for (int l = 0; l < LC; l++) {
            float dl = dp[(size_t)l*ED];
            float ul = up[(size_t)l*ED];
            float r  = __expf(-dl);
            float du = dl * ul;
            float p  = r;
            sd += dl;
#pragma unroll
            for (int n = 0; n < NST; n++) {
                h[n] = fmaf(p, h[n], du * sB[l][n]);
                p *= r;
            }
        }
    } else {
        for (int l = 0; l < LC; l++) {
            float dl = dp[(size_t)l*ED];
            float ul = up[(size_t)l*ED];
            float du = dl * ul;
            sd += dl;
#pragma unroll
            for (int n = 0; n < NST; n++) {
                float dA = __expf(dl * A[n]);
                h[n] = fmaf(dA, h[n], du * sB[l][n]);
            }
        }
    }
    size_t o = ((size_t)(b*CH + c)*ED + e)*NST;
#pragma unroll
    for (int n = 0; n < NST; n++) {
        hloc[o+n] = h[n];
        Pout[o+n] = __expf(A[n] * sd);
    }
}

// ---------------- scan combine: sequential over CH chunks ----------------
__global__ void scan_combine(const float* __restrict__ hloc, const float* __restrict__ P,
                             float* __restrict__ Hin) {
    int idx = blockIdx.x * 256 + threadIdx.x;   // over B*ED*NST = 262144
    int n = idx & 15;
    int e = (idx >> 4) & (ED-1);
    int b = idx >> 14;
    float H = 0.f;
#pragma unroll
    for (int c = 0; c < CH; c++) {
        size_t o = ((size_t)(b*CH + c)*ED + e)*NST + n;
        Hin[o] = H;
        H = fmaf(P[o], H, hloc[o]);
    }
}

// ---------------- scan pass B: re-scan with true init; fused y, D-skip, silu(z) gate, bf16 split out ----------------
__global__ void scan_passB(const float* __restrict__ delta, const float* __restrict__ u,
                           const float* __restrict__ dbc, const float* __restrict__ xz,
                           const float* __restrict__ A_log, const float* __restrict__ Dv,
                           const float* __restrict__ Hin,
                           __nv_bfloat16* __restrict__ yh, __nv_bfloat16* __restrict__ yl) {
    __shared__ float sB[LC][NST];
    __shared__ float sC[LC][NST];
    int e = blockIdx.x * 128 + threadIdx.x;
    int c = blockIdx.y, b = blockIdx.z;
    for (int i = threadIdx.x; i < LC*32; i += 128) {
        int row = i >> 5, col = i & 31;
        float v = dbc[(size_t)(b*L_ + c*LC + row)*64 + 32 + col];
        if (col < 16) sB[row][col] = v; else sC[row][col-16] = v;
    }
    __syncthreads();

    float A[NST];
    bool fast = true;
#pragma unroll
    for (int n = 0; n < NST; n++) {
        float a = -__expf(A_log[(size_t)e*NST + n]);
        A[n] = a;
        fast = fast && (fabsf(a + (float)(n+1)) < 1e-4f * (float)(n+1));
    }

    float h[NST];
    size_t oH = ((size_t)(b*CH + c)*ED + e)*NST;
#pragma unroll
    for (int n4 = 0; n4 < NST; n4 += 4) {
        float4 v = *reinterpret_cast<const float4*>(&Hin[oH + n4]);
        h[n4+0] = v.x; h[n4+1] = v.y; h[n4+2] = v.z; h[n4+3] = v.w;
    }
    float Dp = Dv[e];

    const float* dp = delta + (size_t)(b*L_ + c*LC)*ED + e;
    const float* up = u     + (size_t)(b*L_ + c*LC)*ED + e;
    const float* zp = xz    + (size_t)(b*L_ + c*LC)*(2*ED) + ED + e;
    size_t yo = (size_t)(b*L_ + c*LC)*ED + e;

    if (fast) {
        for (int l = 0; l < LC; l++) {
            float dl = dp[(size_t)l*ED];
            float ul = up[(size_t)l*ED];
            float r  = __expf(-dl);
            float du = dl * ul;
            float p  = r;
            float y  = 0.f;
#pragma unroll
            for (int n = 0; n < NST; n++) {
                h[n] = fmaf(p, h[n], du * sB[l][n]);
                y = fmaf(h[n], sC[l][n], y);
                p *= r;
            }
            float zl = zp[(size_t)l*(2*ED)];
            float yt = fmaf(Dp, ul, y) * zl * sigmoidf_(zl);
            __nv_bfloat16 hb = __float2bfloat16(yt);
            yh[yo + (size_t)l*ED] = hb;
            yl[yo + (size_t)l*ED] = __float2bfloat16(yt - __bfloat162float(hb));
        }
    } else {
        for (int l = 0; l < LC; l++) {
            float dl = dp[(size_t)l*ED];
            float ul = up[(size_t)l*ED];
            float du = dl * ul;
            float y  = 0.f;
#pragma unroll
            for (int n = 0; n < NST; n++) {
                float dA = __expf(dl * A[n]);
                h[n] = fmaf(dA, h[n], du * sB[l][n]);
                y = fmaf(h[n], sC[l][n], y);
            }
            float zl = zp[(size_t)l*(2*ED)];
            float yt = fmaf(Dp, ul, y) * zl * sigmoidf_(zl);
            __nv_bfloat16 hb = __float2bfloat16(yt);
            yh[yo + (size_t)l*ED] = hb;
            yl[yo + (size_t)l*ED] = __float2bfloat16(yt - __bfloat162float(hb));
        }
    }
}

// ---------------- head: y = h[:, -1, :] @ head_w^T + head_b, transposed write ----------------
__global__ void head_kernel(const float* __restrict__ h, const float* __restrict__ hw,
                            const float* __restrict__ hb, float* __restrict__ out) {
    int w    = blockIdx.x * 8 + (threadIdx.x >> 5);
    int lane = threadIdx.x & 31;
    int n = w % 3072;
    int b = w / 3072;
    const float4* hr4 = reinterpret_cast<const float4*>(h + ((size_t)b*L_ + (L_-1))*DM);
    const float4* wr4 = reinterpret_cast<const float4*>(hw + (size_t)n*DM);
    float s = 0.f;
#pragma unroll
    for (int i = 0; i < 4; i++) {
        int k4 = lane + i*32;
        float4 a = hr4[k4];
        float4 ww = wr4[k4];
        s += a.x*ww.x + a.y*ww.y + a.z*ww.z + a.w*ww.w;
    }
#pragma unroll
    for (int o = 16; o; o >>= 1) s += __shfl_xor_sync(0xffffffffu, s, o);
    if (lane == 0) {
        int c = n & 31, t = n >> 5;
        out[(size_t)b*3072 + (size_t)c*96 + t] = s + hb[n];
    }
}

// ---------------- launch ----------------
extern "C" void kernel_launch(void* const* d_in, const int* in_sizes, int n_in,
                              void* d_out, int out_size) {
    const float* x        = (const float*)d_in[0];
    const float* embed_w  = (const float*)d_in[1];
    const float* embed_b  = (const float*)d_in[2];
    const float* norm_w   = (const float*)d_in[3];
    const float* in_w     = (const float*)d_in[4];
    const float* conv_w   = (const float*)d_in[5];
    const float* conv_b   = (const float*)d_in[6];
    const float* xp_w     = (const float*)d_in[7];
    const float* dt_w     = (const float*)d_in[8];
    const float* dt_b     = (const float*)d_in[9];
    const float* A_log    = (const float*)d_in[10];
    const float* Dv       = (const float*)d_in[11];
    const float* out_w    = (const float*)d_in[12];
    const float* head_w   = (const float*)d_in[13];
    const float* head_b   = (const float*)d_in[14];
    float* out = (float*)d_out;

    float *h, *xz, *xc, *dbc, *delta, *hloc, *P, *Hin, *xT;
    __nv_bfloat16 *ah, *al, *wih, *wil, *woh, *wol;
    cudaGetSymbolAddress((void**)&h,     g_h);
    cudaGetSymbolAddress((void**)&xz,    g_xz);
    cudaGetSymbolAddress((void**)&xc,    g_xc);
    cudaGetSymbolAddress((void**)&dbc,   g_dbc);
    cudaGetSymbolAddress((void**)&delta, g_delta);
    cudaGetSymbolAddress((void**)&hloc,  g_hloc);
    cudaGetSymbolAddress((void**)&P,     g_P);
    cudaGetSymbolAddress((void**)&Hin,   g_Hin);
    cudaGetSymbolAddress((void**)&xT,    g_xT);
    cudaGetSymbolAddress((void**)&ah,    g_ah);
    cudaGetSymbolAddress((void**)&al,    g_al);
    cudaGetSymbolAddress((void**)&wih,   g_wih);
    cudaGetSymbolAddress((void**)&wil,   g_wil);
    cudaGetSymbolAddress((void**)&woh,   g_woh);
    cudaGetSymbolAddress((void**)&wol,   g_wol);

    cudaFuncSetAttribute(mma_gemm<0>, cudaFuncAttributeMaxDynamicSharedMemorySize, MMA_SMEM);
    cudaFuncSetAttribute(mma_gemm<1>, cudaFuncAttributeMaxDynamicSharedMemorySize, MMA_SMEM);

    // weight splits (all layers, once per launch)
    cvt_split_kernel<<<(NL*2*ED*DM + 255)/256, 256>>>(in_w,  wih, wil, NL*2*ED*DM);
    cvt_split_kernel<<<(NL*DM*ED   + 255)/256, 256>>>(out_w, woh, wol, NL*DM*ED);

    // embed: h = x^T @ embed_w^T + embed_b
    transpose_x_kernel<<<dim3(L_/32, B_), dim3(32, 32)>>>(x, xT);
    sgemm_kernel<128,128,16,8,8,1><<<dim3(DM/128, MROWS/128), 256>>>(
        xT, embed_w, h, embed_b, MROWS, DM, 32, 32, 32, DM);

    for (int i = 0; i < NL; i++) {
        // rmsnorm -> bf16 hi/lo (A operand for in_proj, lda=512)
        rmsnorm_kernel<<<MROWS, 128>>>(h, norm_w + (size_t)i*DM, ah, al);

        // xz = rms @ in_proj^T  (tensor-core split-bf16: M=16384, N=2048, K=512)
        mma_gemm<0><<<dim3(2*ED/256, MROWS/128), 512, MMA_SMEM>>>(
            ah, al, wih + (size_t)i*2*ED*DM, wil + (size_t)i*2*ED*DM,
            xz, DM, DM, DM, 2*ED);

        // depthwise causal conv + silu
        conv_silu_kernel<<<(MROWS*ED)/256, 256>>>(
            xz, conv_w + (size_t)i*ED*4, conv_b + (size_t)i*ED, xc);

        // dbc = xc @ x_proj^T   (N=64, K=1024)
        sgemm_kernel<128,64,16,8,4,0><<<dim3(1, MROWS/128), 256>>>(
            xc, xp_w + (size_t)i*64*ED, dbc, nullptr, MROWS, 64, ED, ED, ED, 64);

        // delta = softplus(dbc[:, :32] @ dt_w^T + dt_b)
        sgemm_kernel<128,128,16,8,8,2><<<dim3(ED/128, MROWS/128), 256>>>(
            dbc, dt_w + (size_t)i*ED*DR, delta, dt_b + (size_t)i*ED,
            MROWS, ED, DR, 64, DR, ED);

        // chunked selective scan (pass B emits y as bf16 hi/lo, lda=1024)
        scan_passA<<<dim3(ED/128, CH, B_), 128>>>(
            delta, xc, dbc, A_log + (size_t)i*ED*NST, hloc, P);
        scan_combine<<<(B_*ED*NST)/256, 256>>>(hloc, P, Hin);
        scan_passB<<<dim3(ED/128, CH, B_), 128>>>(
            delta, xc, dbc, xz, A_log + (size_t)i*ED*NST, Dv + (size_t)i*ED, Hin, ah, al);

        // h += y @ out_proj^T  (tensor-core split-bf16: M=16384, N=512, K=1024, residual)
        mma_gemm<1><<<dim3(DM/256, MROWS/128), 512, MMA_SMEM>>>(
            ah, al, woh + (size_t)i*DM*ED, wol + (size_t)i*DM*ED,
            h, ED, ED, ED, DM);
    }

    head_kernel<<<(B_*3072)/8, 256>>>(h, head_w, head_b, out);
}

// round 6
// speedup vs baseline: 1.9484x; 1.0285x over previous
#include <cuda_runtime.h>
#include <cuda_bf16.h>
#include <math.h>
#include <stdint.h>

// ---------------- problem constants ----------------
#define B_   16
#define L_   1024
#define DM   512      // d_model
#define ED   1024     // d_inner
#define NST  16       // d_state
#define NL   4
#define DR   32       // dt_rank
#define CH   8        // scan chunks
#define LC   128      // chunk length  (CH*LC == L_)
#define MROWS (B_*L_) // 16384

// ---------------- scratch (device globals; no allocation allowed) ----------------
__device__ __align__(16) float g_h    [(size_t)MROWS*DM];
__device__ __align__(16) float g_xz   [(size_t)MROWS*2*ED];
__device__ __align__(16) float g_xc   [(size_t)MROWS*ED];
__device__ __align__(16) float g_dbc  [(size_t)MROWS*64];
__device__ __align__(16) float g_delta[(size_t)MROWS*ED];
__device__ __align__(16) float g_hloc [(size_t)B_*CH*ED*NST];
__device__ __align__(16) float g_P    [(size_t)B_*CH*ED*NST];
__device__ __align__(16) float g_Hin  [(size_t)B_*CH*ED*NST];
__device__ __align__(16) float g_xT   [(size_t)MROWS*32];
// bf16 split activations (A operand). lda=512 (rmsnorm out) then lda=1024 (y).
__device__ __align__(16) __nv_bfloat16 g_ah[(size_t)MROWS*ED];
__device__ __align__(16) __nv_bfloat16 g_al[(size_t)MROWS*ED];
// bf16 split weights
__device__ __align__(16) __nv_bfloat16 g_wih[(size_t)NL*2*ED*DM];
__device__ __align__(16) __nv_bfloat16 g_wil[(size_t)NL*2*ED*DM];
__device__ __align__(16) __nv_bfloat16 g_woh[(size_t)NL*DM*ED];
__device__ __align__(16) __nv_bfloat16 g_wol[(size_t)NL*DM*ED];

__device__ __forceinline__ float sigmoidf_(float x) { return 1.f / (1.f + __expf(-x)); }

// ================= mma.sync bf16 helpers (non-arch-gated PTX) =================
__device__ __forceinline__ void ldm_x4(uint32_t (&r)[4], uint32_t a) {
    asm volatile("ldmatrix.sync.aligned.m8n8.x4.shared.b16 {%0,%1,%2,%3}, [%4];"
                 : "=r"(r[0]), "=r"(r[1]), "=r"(r[2]), "=r"(r[3]) : "r"(a));
}
__device__ __forceinline__ void mma_bf16(float (&d)[4], const uint32_t (&a)[4],
                                         uint32_t b0, uint32_t b1) {
    asm volatile(
        "mma.sync.aligned.m16n8k16.row.col.f32.bf16.bf16.f32 "
        "{%0,%1,%2,%3}, {%4,%5,%6,%7}, {%8,%9}, {%0,%1,%2,%3};"
        : "+f"(d[0]), "+f"(d[1]), "+f"(d[2]), "+f"(d[3])
        : "r"(a[0]), "r"(a[1]), "r"(a[2]), "r"(a[3]), "r"(b0), "r"(b1));
}
__device__ __forceinline__ void cp_async16(uint32_t sdst, const void* gsrc) {
    asm volatile("cp.async.cg.shared.global [%0], [%1], 16;" :: "r"(sdst), "l"(gsrc));
}
__device__ __forceinline__ void cp_commit() { asm volatile("cp.async.commit_group;"); }
__device__ __forceinline__ void cp_wait1()  { asm volatile("cp.async.wait_group 1;"); }
__device__ __forceinline__ void cp_wait0()  { asm volatile("cp.async.wait_group 0;"); }

// ================= split-bf16 tensor-core GEMM =================
// C(MxN) = A(MxK)*B(NxK)^T via Ah*Bh + Ah*Bl + Al*Bh (bf16 mma, fp32 accum)
// CTA tile 128(M)x256(N), 512 threads = 16 warps (4x4), warp tile 32x64.
// BK=32, 3-stage cp.async pipeline, ONE __syncthreads per chunk.
// SMEM row pitch 80B (32 bf16 + 16B pad).
#define ROWB    80
#define A_TEN   (128*ROWB)               // 10240
#define B_TEN   (256*ROWB)               // 20480
#define STG_SZ  (2*A_TEN + 2*B_TEN)      // 61440
#define MMA_SMEM (3*STG_SZ)              // 184320

template<int MODE>  // 0: store, 1: C += result
__global__ __launch_bounds__(512, 1)
void mma_gemm(const __nv_bfloat16* __restrict__ Ah, const __nv_bfloat16* __restrict__ Al,
              const __nv_bfloat16* __restrict__ Bh, const __nv_bfloat16* __restrict__ Bl,
              float* __restrict__ C, int K, int lda, int ldb, int ldc) {
    extern __shared__ char smem[];
    const uint32_t sbase = (uint32_t)__cvta_generic_to_shared(smem);
    const int tid  = threadIdx.x;
    const int wid  = tid >> 5, lane = tid & 31;
    const int wm   = wid & 3;           // 0..3 : 32 rows each
    const int wn   = wid >> 2;          // 0..3 : 64 cols each
    const int bm   = blockIdx.y * 128;
    const int bn   = blockIdx.x * 256;
    const int NC   = K >> 5;

    float acc[2][8][4];
#pragma unroll
    for (int i = 0; i < 2; i++)
#pragma unroll
        for (int j = 0; j < 8; j++)
#pragma unroll
            for (int q = 0; q < 4; q++) acc[i][j][q] = 0.f;

    const int arow  = tid >> 2,          akc = tid & 3;
    const int brow0 = tid >> 2,          bkc0 = tid & 3;
    const int brow1 = (tid + 512) >> 2,  bkc1 = tid & 3;

    const __nv_bfloat16* gAh = Ah + (size_t)(bm + arow) * lda + akc * 8;
    const __nv_bfloat16* gAl = Al + (size_t)(bm + arow) * lda + akc * 8;
    const __nv_bfloat16* gB0h = Bh + (size_t)(bn + brow0) * ldb + bkc0 * 8;
    const __nv_bfloat16* gB1h = Bh + (size_t)(bn + brow1) * ldb + bkc1 * 8;
    const __nv_bfloat16* gB0l = Bl + (size_t)(bn + brow0) * ldb + bkc0 * 8;
    const __nv_bfloat16* gB1l = Bl + (size_t)(bn + brow1) * ldb + bkc1 * 8;
    const uint32_t sA  = sbase + arow  * ROWB + akc  * 16;
    const uint32_t sB0 = sbase + brow0 * ROWB + bkc0 * 16;
    const uint32_t sB1 = sbase + brow1 * ROWB + bkc1 * 16;

#define LOAD_STAGE(c, s) do {                                          \
        int koff = (c) << 5;                                           \
        uint32_t st = (uint32_t)(s) * STG_SZ;                          \
        cp_async16(sA  + st,                   gAh  + koff);           \
        cp_async16(sA  + st + A_TEN,           gAl  + koff);           \
        cp_async16(sB0 + st + 2*A_TEN,         gB0h + koff);           \
        cp_async16(sB1 + st + 2*A_TEN,         gB1h + koff);           \
        cp_async16(sB0 + st + 2*A_TEN + B_TEN, gB0l + koff);           \
        cp_async16(sB1 + st + 2*A_TEN + B_TEN, gB1l + koff);           \
        cp_commit();                                                   \
    } while (0)

    LOAD_STAGE(0, 0);
    LOAD_STAGE(1, 1);

    const int aRow = (lane & 15);
    const int aKby = ((lane >> 4) << 4);
    const int bRow = (lane & 7) | ((lane >> 4) << 3);
    const int bKby = (((lane >> 3) & 1) << 4);

    int stg = 0;
    for (int c = 0; c < NC; c++) {
        // guarantee chunk c's data: 2 groups pending except on last chunk
        if (c + 1 < NC) cp_wait1(); else cp_wait0();
        __syncthreads();   // also: all warps done reading stage (c-1)%3 == (c+2)%3
        int nstg = stg + 2; if (nstg >= 3) nstg -= 3;
        if (c + 2 < NC) LOAD_STAGE(c + 2, nstg);

        const uint32_t st  = sbase + (uint32_t)stg * STG_SZ;
        const uint32_t sAh_ = st, sAl_ = st + A_TEN;
        const uint32_t sBh_ = st + 2*A_TEN, sBl_ = st + 2*A_TEN + B_TEN;

        // A-fragment double buffer across the two k16 halves
        uint32_t ah[2][2][4], al[2][2][4];
#pragma unroll
        for (int mf = 0; mf < 2; mf++) {
            uint32_t off = (uint32_t)(wm*32 + mf*16 + aRow) * ROWB + aKby;
            ldm_x4(ah[0][mf], sAh_ + off);
            ldm_x4(al[0][mf], sAl_ + off);
        }
#pragma unroll
        for (int k16 = 0; k16 < 2; k16++) {
            const int kb = k16 * 32;
            if (k16 == 0) {   // prefetch k16=1 A frags while mma of k16=0 runs
#pragma unroll
                for (int mf = 0; mf < 2; mf++) {
                    uint32_t off = (uint32_t)(wm*32 + mf*16 + aRow) * ROWB + 32 + aKby;
                    ldm_x4(ah[1][mf], sAh_ + off);
                    ldm_x4(al[1][mf], sAl_ + off);
                }
            }
#pragma unroll
            for (int nf2 = 0; nf2 < 4; nf2++) {
                uint32_t bh[4], bl[4];
                uint32_t off = (uint32_t)(wn*64 + nf2*16 + bRow) * ROWB + kb + bKby;
                ldm_x4(bh, sBh_ + off);
                ldm_x4(bl, sBl_ + off);
#pragma unroll
                for (int half = 0; half < 2; half++) {
                    uint32_t b0h = bh[half*2], b1h = bh[half*2+1];
                    uint32_t b0l = bl[half*2], b1l = bl[half*2+1];
#pragma unroll
                    for (int mf = 0; mf < 2; mf++) {
                        int nf = nf2*2 + half;
                        mma_bf16(acc[mf][nf], ah[k16][mf], b0h, b1h);
                        mma_bf16(acc[mf][nf], ah[k16][mf], b0l, b1l);
                        mma_bf16(acc[mf][nf], al[k16][mf], b0h, b1h);
                    }
                }
            }
        }
        stg++; if (stg >= 3) stg = 0;
    }

    // epilogue: direct register -> gmem (float2 stores)
    const int erow = lane >> 2;
    const int ecol = (lane & 3) * 2;
#pragma unroll
    for (int mf = 0; mf < 2; mf++) {
#pragma unroll
        for (int nf = 0; nf < 8; nf++) {
            int row0 = bm + wm*32 + mf*16 + erow;
            int col  = bn + wn*64 + nf*8 + ecol;
            float* p0 = C + (size_t)row0 * ldc + col;
            float* p1 = C + (size_t)(row0 + 8) * ldc + col;
            float2 v0 = make_float2(acc[mf][nf][0], acc[mf][nf][1]);
            float2 v1 = make_float2(acc[mf][nf][2], acc[mf][nf][3]);
            if (MODE == 1) {
                float2 o0 = *reinterpret_cast<float2*>(p0);
                float2 o1 = *reinterpret_cast<float2*>(p1);
                v0.x += o0.x; v0.y += o0.y; v1.x += o1.x; v1.y += o1.y;
            }
            *reinterpret_cast<float2*>(p0) = v0;
            *reinterpret_cast<float2*>(p1) = v1;
        }
    }
#undef LOAD_STAGE
}

// ---------------- fp32 -> bf16 hi/lo split ----------------
__global__ void cvt_split_kernel(const float* __restrict__ x, __nv_bfloat16* __restrict__ h,
                                 __nv_bfloat16* __restrict__ l, int n) {
    int i = blockIdx.x * 256 + threadIdx.x;
    if (i < n) {
        float v = x[i];
        __nv_bfloat16 hb = __float2bfloat16(v);
        h[i] = hb;
        l[i] = __float2bfloat16(v - __bfloat162float(hb));
    }
}

// ---------------- transpose x: (B,32,L) -> (B*L, 32) ----------------
__global__ void transpose_x_kernel(const float* __restrict__ x, float* __restrict__ xT) {
    __shared__ float t[32][33];
    int b  = blockIdx.y;
    int l0 = blockIdx.x * 32;
    int tx = threadIdx.x, ty = threadIdx.y;
    t[ty][tx] = x[((size_t)b*32 + ty)*L_ + l0 + tx];
    __syncthreads();
    xT[((size_t)b*L_ + l0 + ty)*32 + tx] = t[tx][ty];
}

// ---------------- generic SGEMM (small GEMMs): C = A * B^T (+epilogue) ----------------
// MODE: 0=store, 1=+bias, 2=softplus(+bias)
template<int BM, int BN, int BK, int TM, int TN, int MODE>
__global__ __launch_bounds__((BM/TM)*(BN/TN))
void sgemm_kernel(const float* __restrict__ A, const float* __restrict__ Bw,
                  float* __restrict__ C, const float* __restrict__ bias,
                  int M, int N, int K, int lda, int ldb, int ldc) {
    constexpr int THREADS = (BM/TM)*(BN/TN);
    __shared__ float As[BK][BM];
    __shared__ float Bs[BK][BN];
    const int tid = threadIdx.x;
    const int bm  = blockIdx.y * BM;
    const int bn  = blockIdx.x * BN;
    const int tx  = tid % (BN/TN);
    const int ty  = tid / (BN/TN);

    float acc[TM][TN];
#pragma unroll
    for (int i = 0; i < TM; i++)
#pragma unroll
        for (int j = 0; j < TN; j++) acc[i][j] = 0.f;

    constexpr int AVEC = BM*BK/4/THREADS;
    constexpr int BVEC = BN*BK/4/THREADS;

    for (int k0 = 0; k0 < K; k0 += BK) {
#pragma unroll
        for (int i = 0; i < AVEC; i++) {
            int idx = tid + i*THREADS;
            int row = idx / (BK/4);
            int kc  = (idx % (BK/4)) * 4;
            float4 v = *reinterpret_cast<const float4*>(&A[(size_t)(bm+row)*lda + k0 + kc]);
            As[kc+0][row] = v.x; As[kc+1][row] = v.y; As[kc+2][row] = v.z; As[kc+3][row] = v.w;
        }
#pragma unroll
        for (int i = 0; i < BVEC; i++) {
            int idx = tid + i*THREADS;
            int row = idx / (BK/4);
            int kc  = (idx % (BK/4)) * 4;
            float4 v = *reinterpret_cast<const float4*>(&Bw[(size_t)(bn+row)*ldb + k0 + kc]);
            Bs[kc+0][row] = v.x; Bs[kc+1][row] = v.y; Bs[kc+2][row] = v.z; Bs[kc+3][row] = v.w;
        }
        __syncthreads();
#pragma unroll
        for (int kk = 0; kk < BK; kk++) {
            float a[TM], b[TN];
#pragma unroll
            for (int i = 0; i < TM; i++) a[i] = As[kk][ty*TM + i];
#pragma unroll
            for (int j = 0; j < TN; j++) b[j] = Bs[kk][tx*TN + j];
#pragma unroll
            for (int i = 0; i < TM; i++)
#pragma unroll
                for (int j = 0; j < TN; j++)
                    acc[i][j] = fmaf(a[i], b[j], acc[i][j]);
        }
        __syncthreads();
    }

#pragma unroll
    for (int i = 0; i < TM; i++) {
        int row = bm + ty*TM + i;
#pragma unroll
        for (int j = 0; j < TN; j++) {
            int col = bn + tx*TN + j;
            float v = acc[i][j];
            if (MODE == 1) v += bias[col];
            if (MODE == 2) {
                v += bias[col];
                v = (v > 20.f) ? v : log1pf(__expf(v));
            }
            C[(size_t)row*ldc + col] = v;
        }
    }
}

// ---------------- RMSNorm over d_model=512, fused bf16 hi/lo output ----------------
__global__ void rmsnorm_kernel(const float* __restrict__ x, const float* __restrict__ w,
                               __nv_bfloat16* __restrict__ oh, __nv_bfloat16* __restrict__ ol) {
    int row = blockIdx.x;
    int tid = threadIdx.x;                       // 128 threads, 4 elems each
    const float4* xr = reinterpret_cast<const float4*>(x + (size_t)row*DM);
    float4 v = xr[tid];
    float ss = v.x*v.x + v.y*v.y + v.z*v.z + v.w*v.w;
#pragma unroll
    for (int o = 16; o; o >>= 1) ss += __shfl_xor_sync(0xffffffffu, ss, o);
    __shared__ float sred[4];
    if ((tid & 31) == 0) sred[tid >> 5] = ss;
    __syncthreads();
    float tot = sred[0] + sred[1] + sred[2] + sred[3];
    float scale = rsqrtf(tot * (1.f/(float)DM) + 1e-5f);
    float4 wv = reinterpret_cast<const float4*>(w)[tid];
    float o0 = v.x*scale*wv.x, o1 = v.y*scale*wv.y, o2 = v.z*scale*wv.z, o3 = v.w*scale*wv.w;
    __nv_bfloat16 h0 = __float2bfloat16(o0), h1 = __float2bfloat16(o1);
    __nv_bfloat16 h2 = __float2bfloat16(o2), h3 = __float2bfloat16(o3);
    size_t off = (size_t)row*DM + tid*4;
    __nv_bfloat162* oh2 = reinterpret_cast<__nv_bfloat162*>(oh + off);
    __nv_bfloat162* ol2 = reinterpret_cast<__nv_bfloat162*>(ol + off);
    oh2[0] = __nv_bfloat162(h0, h1);
    oh2[1] = __nv_bfloat162(h2, h3);
    ol2[0] = __nv_bfloat162(__float2bfloat16(o0 - __bfloat162float(h0)),
                            __float2bfloat16(o1 - __bfloat162float(h1)));
    ol2[1] = __nv_bfloat162(__float2bfloat16(o2 - __bfloat162float(h2)),
                            __float2bfloat16(o3 - __bfloat162float(h3)));
}

// ---------------- depthwise causal conv(4) + bias + silu ----------------
__global__ void conv_silu_kernel(const float* __restrict__ xz, const float* __restrict__ cw,
                                 const float* __restrict__ cb, float* __restrict__ out) {
    size_t idx = (size_t)blockIdx.x * 256 + threadIdx.x;   // over B*L*ED
    int e = idx & (ED-1);
    int l = (idx >> 10) & (L_-1);
    float4 w4 = *reinterpret_cast<const float4*>(&cw[(size_t)e*4]);
    size_t base = (idx >> 10) * (size_t)(2*ED) + e;        // row (b*L+l) in xz, col e
    float acc = cb[e];
    acc = fmaf(w4.w, xz[base], acc);
    if (l >= 1) acc = fmaf(w4.z, xz[base - 2*ED], acc);
    if (l >= 2) acc = fmaf(w4.y, xz[base - 4*ED], acc);
    if (l >= 3) acc = fmaf(w4.x, xz[base - 6*ED], acc);
    out[idx] = acc * sigmoidf_(acc);
}

// ---------------- scan pass A: per-chunk local scan (h0=0) + decay product ----------------
__global__ void scan_passA(const float* __restrict__ delta, const float* __restrict__ u,
                           const float* __restrict__ dbc, const float* __restrict__ A_log,
                           float* __restrict__ hloc, float* __restrict__ Pout) {
    __shared__ float sB[LC][NST];
    int e = blockIdx.x * 128 + threadIdx.x;
    int c = blockIdx.y, b = blockIdx.z;
    for (int i = threadIdx.x; i < LC*NST; i += 128) {
        int row = i >> 4, col = i & 15;
        sB[row][col] = dbc[(size_t)(b*L_ + c*LC + row)*64 + 32 + col];
    }
    __syncthreads();

    float A[NST];
    bool fast = true;
#pragma unroll
    for (int n = 0; n < NST; n++) {
        float a = -__expf(A_log[(size_t)e*NST + n]);
        A[n] = a;
        fast = fast && (fabsf(a + (float)(n+1)) < 1e-4f * (float)(n+1));
    }

    float h[NST];
#pragma unroll
    for (int n = 0; n < NST; n++) h[n] = 0.f;
    float sd = 0.f;
    const float* dp = delta + (size_t)(b*L_ + c*LC)*ED + e;
    const float* up = u     + (size_t)(b*L_ + c*LC)*ED + e;

    if (fast) {
        for (int l = 0; l < LC; l++) {
            float dl = dp[(size_t)l*ED];
            float ul = up[(size_t)l*ED];
            float r  = __expf(-dl);
            float du = dl * ul;
            float p  = r;
            sd += dl;
#pragma unroll
            for (int n = 0; n < NST; n++) {
                h[n] = fmaf(p, h[n], du * sB[l][n]);
                p *= r;
            }
        }
    } else {
        for (int l = 0; l < LC; l++) {
            float dl = dp[(size_t)l*ED];
            float ul = up[(size_t)l*ED];
            float du = dl * ul;
            sd += dl;
#pragma unroll
            for (int n = 0; n < NST; n++) {
                float dA = __expf(dl * A[n]);
                h[n] = fmaf(dA, h[n], du * sB[l][n]);
            }
        }
    }
    size_t o = ((size_t)(b*CH + c)*ED + e)*NST;
#pragma unroll
    for (int n = 0; n < NST; n++) {
        hloc[o+n] = h[n];
        Pout[o+n] = __expf(A[n] * sd);
    }
}

// ---------------- scan combine: sequential over CH chunks ----------------
__global__ void scan_combine(const float* __restrict__ hloc, const float* __restrict__ P,
                             float* __restrict__ Hin) {
    int idx = blockIdx.x * 256 + threadIdx.x;   // over B*ED*NST = 262144
    int n = idx & 15;
    int e = (idx >> 4) & (ED-1);
    int b = idx >> 14;
    float H = 0.f;
#pragma unroll
    for (int c = 0; c < CH; c++) {
        size_t o = ((size_t)(b*CH + c)*ED + e)*NST + n;
        Hin[o] = H;
        H = fmaf(P[o], H, hloc[o]);
    }
}

// ---------------- scan pass B: re-scan with true init; fused y, D-skip, silu(z) gate, bf16 split out ----------------
__global__ void scan_passB(const float* __restrict__ delta, const float* __restrict__ u,
                           const float* __restrict__ dbc, const float* __restrict__ xz,
                           const float* __restrict__ A_log, const float* __restrict__ Dv,
                           const float* __restrict__ Hin,
                           __nv_bfloat16* __restrict__ yh, __nv_bfloat16* __restrict__ yl) {
    __shared__ float sB[LC][NST];
    __shared__ float sC[LC][NST];
    int e = blockIdx.x * 128 + threadIdx.x;
    int c = blockIdx.y, b = blockIdx.z;
    for (int i = threadIdx.x; i < LC*32; i += 128) {
        int row = i >> 5, col = i & 31;
        float v = dbc[(size_t)(b*L_ + c*LC + row)*64 + 32 + col];
        if (col < 16) sB[row][col] = v; else sC[row][col-16] = v;
    }
    __syncthreads();

    float A[NST];
    bool fast = true;
#pragma unroll
    for (int n = 0; n < NST; n++) {
        float a = -__expf(A_log[(size_t)e*NST + n]);
        A[n] = a;
        fast = fast && (fabsf(a + (float)(n+1)) < 1e-4f * (float)(n+1));
    }

    float h[NST];
    size_t oH = ((size_t)(b*CH + c)*ED + e)*NST;
#pragma unroll
    for (int n4 = 0; n4 < NST; n4 += 4) {
        float4 v = *reinterpret_cast<const float4*>(&Hin[oH + n4]);
        h[n4+0] = v.x; h[n4+1] = v.y; h[n4+2] = v.z; h[n4+3] = v.w;
    }
    float Dp = Dv[e];

    const float* dp = delta + (size_t)(b*L_ + c*LC)*ED + e;
    const float* up = u     + (size_t)(b*L_ + c*LC)*ED + e;
    const float* zp = xz    + (size_t)(b*L_ + c*LC)*(2*ED) + ED + e;
    size_t yo = (size_t)(b*L_ + c*LC)*ED + e;

    if (fast) {
        for (int l = 0; l < LC; l++) {
            float dl = dp[(size_t)l*ED];
            float ul = up[(size_t)l*ED];
            float r  = __expf(-dl);
            float du = dl * ul;
            float p  = r;
            float y  = 0.f;
#pragma unroll
            for (int n = 0; n < NST; n++) {
                h[n] = fmaf(p, h[n], du * sB[l][n]);
                y = fmaf(h[n], sC[l][n], y);
                p *= r;
            }
            float zl = zp[(size_t)l*(2*ED)];
            float yt = fmaf(Dp, ul, y) * zl * sigmoidf_(zl);
            __nv_bfloat16 hb = __float2bfloat16(yt);
            yh[yo + (size_t)l*ED] = hb;
            yl[yo + (size_t)l*ED] = __float2bfloat16(yt - __bfloat162float(hb));
        }
    } else {
        for (int l = 0; l < LC; l++) {
            float dl = dp[(size_t)l*ED];
            float ul = up[(size_t)l*ED];
            float du = dl * ul;
            float y  = 0.f;
#pragma unroll
            for (int n = 0; n < NST; n++) {
                float dA = __expf(dl * A[n]);
                h[n] = fmaf(dA, h[n], du * sB[l][n]);
                y = fmaf(h[n], sC[l][n], y);
            }
            float zl = zp[(size_t)l*(2*ED)];
            float yt = fmaf(Dp, ul, y) * zl * sigmoidf_(zl);
            __nv_bfloat16 hb = __float2bfloat16(yt);
            yh[yo + (size_t)l*ED] = hb;
            yl[yo + (size_t)l*ED] = __float2bfloat16(yt - __bfloat162float(hb));
        }
    }
}

// ---------------- head: y = h[:, -1, :] @ head_w^T + head_b, transposed write ----------------
__global__ void head_kernel(const float* __restrict__ h, const float* __restrict__ hw,
                            const float* __restrict__ hb, float* __restrict__ out) {
    int w    = blockIdx.x * 8 + (threadIdx.x >> 5);
    int lane = threadIdx.x & 31;
    int n = w % 3072;
    int b = w / 3072;
    const float4* hr4 = reinterpret_cast<const float4*>(h + ((size_t)b*L_ + (L_-1))*DM);
    const float4* wr4 = reinterpret_cast<const float4*>(hw + (size_t)n*DM);
    float s = 0.f;
#pragma unroll
    for (int i = 0; i < 4; i++) {
        int k4 = lane + i*32;
        float4 a = hr4[k4];
        float4 ww = wr4[k4];
        s += a.x*ww.x + a.y*ww.y + a.z*ww.z + a.w*ww.w;
    }
#pragma unroll
    for (int o = 16; o; o >>= 1) s += __shfl_xor_sync(0xffffffffu, s, o);
    if (lane == 0) {
        int c = n & 31, t = n >> 5;
        out[(size_t)b*3072 + (size_t)c*96 + t] = s + hb[n];
    }
}

// ---------------- launch ----------------
extern "C" void kernel_launch(void* const* d_in, const int* in_sizes, int n_in,
                              void* d_out, int out_size) {
    const float* x        = (const float*)d_in[0];
    const float* embed_w  = (const float*)d_in[1];
    const float* embed_b  = (const float*)d_in[2];
    const float* norm_w   = (const float*)d_in[3];
    const float* in_w     = (const float*)d_in[4];
    const float* conv_w   = (const float*)d_in[5];
    const float* conv_b   = (const float*)d_in[6];
    const float* xp_w     = (const float*)d_in[7];
    const float* dt_w     = (const float*)d_in[8];
    const float* dt_b     = (const float*)d_in[9];
    const float* A_log    = (const float*)d_in[10];
    const float* Dv       = (const float*)d_in[11];
    const float* out_w    = (const float*)d_in[12];
    const float* head_w   = (const float*)d_in[13];
    const float* head_b   = (const float*)d_in[14];
    float* out = (float*)d_out;

    float *h, *xz, *xc, *dbc, *delta, *hloc, *P, *Hin, *xT;
    __nv_bfloat16 *ah, *al, *wih, *wil, *woh, *wol;
    cudaGetSymbolAddress((void**)&h,     g_h);
    cudaGetSymbolAddress((void**)&xz,    g_xz);
    cudaGetSymbolAddress((void**)&xc,    g_xc);
    cudaGetSymbolAddress((void**)&dbc,   g_dbc);
    cudaGetSymbolAddress((void**)&delta, g_delta);
    cudaGetSymbolAddress((void**)&hloc,  g_hloc);
    cudaGetSymbolAddress((void**)&P,     g_P);
    cudaGetSymbolAddress((void**)&Hin,   g_Hin);
    cudaGetSymbolAddress((void**)&xT,    g_xT);
    cudaGetSymbolAddress((void**)&ah,    g_ah);
    cudaGetSymbolAddress((void**)&al,    g_al);
    cudaGetSymbolAddress((void**)&wih,   g_wih);
    cudaGetSymbolAddress((void**)&wil,   g_wil);
    cudaGetSymbolAddress((void**)&woh,   g_woh);
    cudaGetSymbolAddress((void**)&wol,   g_wol);

    cudaFuncSetAttribute(mma_gemm<0>, cudaFuncAttributeMaxDynamicSharedMemorySize, MMA_SMEM);
    cudaFuncSetAttribute(mma_gemm<1>, cudaFuncAttributeMaxDynamicSharedMemorySize, MMA_SMEM);

    // weight splits (all layers, once per launch)
    cvt_split_kernel<<<(NL*2*ED*DM + 255)/256, 256>>>(in_w,  wih, wil, NL*2*ED*DM);
    cvt_split_kernel<<<(NL*DM*ED   + 255)/256, 256>>>(out_w, woh, wol, NL*DM*ED);

    // embed: h = x^T @ embed_w^T + embed_b
    transpose_x_kernel<<<dim3(L_/32, B_), dim3(32, 32)>>>(x, xT);
    sgemm_kernel<128,128,16,8,8,1><<<dim3(DM/128, MROWS/128), 256>>>(
        xT, embed_w, h, embed_b, MROWS, DM, 32, 32, 32, DM);

    for (int i = 0; i < NL; i++) {
        // rmsnorm -> bf16 hi/lo (A operand for in_proj, lda=512)
        rmsnorm_kernel<<<MROWS, 128>>>(h, norm_w + (size_t)i*DM, ah, al);

        // xz = rms @ in_proj^T  (tensor-core split-bf16: M=16384, N=2048, K=512)
        mma_gemm<0><<<dim3(2*ED/256, MROWS/128), 512, MMA_SMEM>>>(
            ah, al, wih + (size_t)i*2*ED*DM, wil + (size_t)i*2*ED*DM,
            xz, DM, DM, DM, 2*ED);

        // depthwise causal conv + silu
        conv_silu_kernel<<<(MROWS*ED)/256, 256>>>(
            xz, conv_w + (size_t)i*ED*4, conv_b + (size_t)i*ED, xc);

        // dbc = xc @ x_proj^T   (N=64, K=1024) — 64x64 tiles -> 256 CTAs
        sgemm_kernel<64,64,16,4,4,0><<<dim3(1, MROWS/64), 256>>>(
            xc, xp_w + (size_t)i*64*ED, dbc, nullptr, MROWS, 64, ED, ED, ED, 64);

        // delta = softplus(dbc[:, :32] @ dt_w^T + dt_b)
        sgemm_kernel<128,128,16,8,8,2><<<dim3(ED/128, MROWS/128), 256>>>(
            dbc, dt_w + (size_t)i*ED*DR, delta, dt_b + (size_t)i*ED,
            MROWS, ED, DR, 64, DR, ED);

        // chunked selective scan (pass B emits y as bf16 hi/lo, lda=1024)
        scan_passA<<<dim3(ED/128, CH, B_), 128>>>(
            delta, xc, dbc, A_log + (size_t)i*ED*NST, hloc, P);
        scan_combine<<<(B_*ED*NST)/256, 256>>>(hloc, P, Hin);
        scan_passB<<<dim3(ED/128, CH, B_), 128>>>(
            delta, xc, dbc, xz, A_log + (size_t)i*ED*NST, Dv + (size_t)i*ED, Hin, ah, al);

        // h += y @ out_proj^T  (tensor-core split-bf16: M=16384, N=512, K=1024, residual)
        mma_gemm<1><<<dim3(DM/256, MROWS/128), 512, MMA_SMEM>>>(
            ah, al, woh + (size_t)i*DM*ED, wol + (size_t)i*DM*ED,
            h, ED, ED, ED, DM);
    }

    head_kernel<<<(B_*3072)/8, 256>>>(h, head_w, head_b, out);
}

// round 7
// speedup vs baseline: 2.2342x; 1.1467x over previous
#include <cuda_runtime.h>
#include <cuda_fp16.h>
#include <math.h>
#include <stdint.h>

// ---------------- problem constants ----------------
#define B_   16
#define L_   1024
#define DM   512      // d_model
#define ED   1024     // d_inner
#define NST  16       // d_state
#define NL   4
#define DR   32       // dt_rank
#define CH   8        // scan chunks
#define LC   128      // chunk length  (CH*LC == L_)
#define MROWS (B_*L_) // 16384

// ---------------- scratch (device globals; no allocation allowed) ----------------
__device__ __align__(16) float g_h    [(size_t)MROWS*DM];
__device__ __align__(16) float g_xz   [(size_t)MROWS*2*ED];
__device__ __align__(16) float g_xc   [(size_t)MROWS*ED];
__device__ __align__(16) float g_dbc  [(size_t)MROWS*64];
__device__ __align__(16) float g_delta[(size_t)MROWS*ED];
__device__ __align__(16) float g_hloc [(size_t)B_*CH*ED*NST];
__device__ __align__(16) float g_P    [(size_t)B_*CH*ED*NST];
__device__ __align__(16) float g_Hin  [(size_t)B_*CH*ED*NST];
__device__ __align__(16) float g_xT   [(size_t)MROWS*32];
// fp16 activations (A operand). lda=512 (rmsnorm out) then lda=1024 (y).
__device__ __align__(16) __half g_a  [(size_t)MROWS*ED];
// fp16 split weights (hi + lo)
__device__ __align__(16) __half g_wih[(size_t)NL*2*ED*DM];
__device__ __align__(16) __half g_wil[(size_t)NL*2*ED*DM];
__device__ __align__(16) __half g_woh[(size_t)NL*DM*ED];
__device__ __align__(16) __half g_wol[(size_t)NL*DM*ED];

__device__ __forceinline__ float sigmoidf_(float x) { return 1.f / (1.f + __expf(-x)); }

// ================= mma.sync fp16 helpers (non-arch-gated PTX) =================
__device__ __forceinline__ void ldm_x4(uint32_t (&r)[4], uint32_t a) {
    asm volatile("ldmatrix.sync.aligned.m8n8.x4.shared.b16 {%0,%1,%2,%3}, [%4];"
                 : "=r"(r[0]), "=r"(r[1]), "=r"(r[2]), "=r"(r[3]) : "r"(a));
}
__device__ __forceinline__ void mma_fp16(float (&d)[4], const uint32_t (&a)[4],
                                         uint32_t b0, uint32_t b1) {
    asm volatile(
        "mma.sync.aligned.m16n8k16.row.col.f32.f16.f16.f32 "
        "{%0,%1,%2,%3}, {%4,%5,%6,%7}, {%8,%9}, {%0,%1,%2,%3};"
        : "+f"(d[0]), "+f"(d[1]), "+f"(d[2]), "+f"(d[3])
        : "r"(a[0]), "r"(a[1]), "r"(a[2]), "r"(a[3]), "r"(b0), "r"(b1));
}
__device__ __forceinline__ void cp_async16(uint32_t sdst, const void* gsrc) {
    asm volatile("cp.async.cg.shared.global [%0], [%1], 16;" :: "r"(sdst), "l"(gsrc));
}
__device__ __forceinline__ void cp_commit() { asm volatile("cp.async.commit_group;"); }
__device__ __forceinline__ void cp_wait1()  { asm volatile("cp.async.wait_group 1;"); }
__device__ __forceinline__ void cp_wait0()  { asm volatile("cp.async.wait_group 0;"); }

// ================= split-fp16 tensor-core GEMM =================
// C(MxN) = A(MxK)*B(NxK)^T via A*Bh + A*Bl (fp16 mma, fp32 accum; B=Bh+Bl exact)
// CTA tile 128(M)x256(N), 512 threads = 16 warps (4x4), warp tile 32x64.
// BK=32, 3-stage cp.async pipeline, one __syncthreads per chunk.
// SMEM row pitch 80B (32 fp16 + 16B pad).
#define ROWB    80
#define A_TEN   (128*ROWB)               // 10240
#define B_TEN   (256*ROWB)               // 20480
#define STG_SZ  (A_TEN + 2*B_TEN)        // 51200
#define MMA_SMEM (3*STG_SZ)              // 153600

template<int MODE>  // 0: store, 1: C += result
__global__ __launch_bounds__(512, 1)
void mma_gemm(const __half* __restrict__ A,
              const __half* __restrict__ Bh, const __half* __restrict__ Bl,
              float* __restrict__ C, int K, int lda, int ldb, int ldc) {
    extern __shared__ char smem[];
    const uint32_t sbase = (uint32_t)__cvta_generic_to_shared(smem);
    const int tid  = threadIdx.x;
    const int wid  = tid >> 5, lane = tid & 31;
    const int wm   = wid & 3;           // 0..3 : 32 rows each
    const int wn   = wid >> 2;          // 0..3 : 64 cols each
    const int bm   = blockIdx.y * 128;
    const int bn   = blockIdx.x * 256;
    const int NC   = K >> 5;

    float acc[2][8][4];
#pragma unroll
    for (int i = 0; i < 2; i++)
#pragma unroll
        for (int j = 0; j < 8; j++)
#pragma unroll
            for (int q = 0; q < 4; q++) acc[i][j][q] = 0.f;

    const int arow  = tid >> 2,          akc = tid & 3;
    const int brow0 = tid >> 2,          bkc0 = tid & 3;
    const int brow1 = (tid + 512) >> 2,  bkc1 = tid & 3;

    const __half* gA   = A  + (size_t)(bm + arow)  * lda + akc  * 8;
    const __half* gB0h = Bh + (size_t)(bn + brow0) * ldb + bkc0 * 8;
    const __half* gB1h = Bh + (size_t)(bn + brow1) * ldb + bkc1 * 8;
    const __half* gB0l = Bl + (size_t)(bn + brow0) * ldb + bkc0 * 8;
    const __half* gB1l = Bl + (size_t)(bn + brow1) * ldb + bkc1 * 8;
    const uint32_t sA  = sbase + arow  * ROWB + akc  * 16;
    const uint32_t sB0 = sbase + brow0 * ROWB + bkc0 * 16;
    const uint32_t sB1 = sbase + brow1 * ROWB + bkc1 * 16;

#define LOAD_STAGE(c, s) do {                                          \
        int koff = (c) << 5;                                           \
        uint32_t st = (uint32_t)(s) * STG_SZ;                          \
        cp_async16(sA  + st,                 gA   + koff);             \
        cp_async16(sB0 + st + A_TEN,         gB0h + koff);             \
        cp_async16(sB1 + st + A_TEN,         gB1h + koff);             \
        cp_async16(sB0 + st + A_TEN + B_TEN, gB0l + koff);             \
        cp_async16(sB1 + st + A_TEN + B_TEN, gB1l + koff);             \
        cp_commit();                                                   \
    } while (0)

    LOAD_STAGE(0, 0);
    LOAD_STAGE(1, 1);

    const int aRow = (lane & 15);
    const int aKby = ((lane >> 4) << 4);
    const int bRow = (lane & 7) | ((lane >> 4) << 3);
    const int bKby = (((lane >> 3) & 1) << 4);

    int stg = 0;
    for (int c = 0; c < NC; c++) {
        if (c + 1 < NC) cp_wait1(); else cp_wait0();
        __syncthreads();
        int nstg = stg + 2; if (nstg >= 3) nstg -= 3;
        if (c + 2 < NC) LOAD_STAGE(c + 2, nstg);

        const uint32_t st  = sbase + (uint32_t)stg * STG_SZ;
        const uint32_t sA_ = st;
        const uint32_t sBh_ = st + A_TEN, sBl_ = st + A_TEN + B_TEN;

        // A-fragment double buffer across the two k16 halves
        uint32_t af[2][2][4];
#pragma unroll
        for (int mf = 0; mf < 2; mf++) {
            uint32_t off = (uint32_t)(wm*32 + mf*16 + aRow) * ROWB + aKby;
            ldm_x4(af[0][mf], sA_ + off);
        }
#pragma unroll
        for (int k16 = 0; k16 < 2; k16++) {
            const int kb = k16 * 32;
            if (k16 == 0) {
#pragma unroll
                for (int mf = 0; mf < 2; mf++) {
                    uint32_t off = (uint32_t)(wm*32 + mf*16 + aRow) * ROWB + 32 + aKby;
                    ldm_x4(af[1][mf], sA_ + off);
                }
            }
#pragma unroll
            for (int nf2 = 0; nf2 < 4; nf2++) {
                uint32_t bh[4], bl[4];
                uint32_t off = (uint32_t)(wn*64 + nf2*16 + bRow) * ROWB + kb + bKby;
                ldm_x4(bh, sBh_ + off);
                ldm_x4(bl, sBl_ + off);
#pragma unroll
                for (int half = 0; half < 2; half++) {
                    uint32_t b0h = bh[half*2], b1h = bh[half*2+1];
                    uint32_t b0l = bl[half*2], b1l = bl[half*2+1];
#pragma unroll
                    for (int mf = 0; mf < 2; mf++) {
                        int nf = nf2*2 + half;
                        mma_fp16(acc[mf][nf], af[k16][mf], b0h, b1h);
                        mma_fp16(acc[mf][nf], af[k16][mf], b0l, b1l);
                    }
                }
            }
        }
        stg++; if (stg >= 3) stg = 0;
    }

    // epilogue: direct register -> gmem (float2 stores)
    const int erow = lane >> 2;
    const int ecol = (lane & 3) * 2;
#pragma unroll
    for (int mf = 0; mf < 2; mf++) {
#pragma unroll
        for (int nf = 0; nf < 8; nf++) {
            int row0 = bm + wm*32 + mf*16 + erow;
            int col  = bn + wn*64 + nf*8 + ecol;
            float* p0 = C + (size_t)row0 * ldc + col;
            float* p1 = C + (size_t)(row0 + 8) * ldc + col;
            float2 v0 = make_float2(acc[mf][nf][0], acc[mf][nf][1]);
            float2 v1 = make_float2(acc[mf][nf][2], acc[mf][nf][3]);
            if (MODE == 1) {
                float2 o0 = *reinterpret_cast<float2*>(p0);
                float2 o1 = *reinterpret_cast<float2*>(p1);
                v0.x += o0.x; v0.y += o0.y; v1.x += o1.x; v1.y += o1.y;
            }
            *reinterpret_cast<float2*>(p0) = v0;
            *reinterpret_cast<float2*>(p1) = v1;
        }
    }
#undef LOAD_STAGE
}

// ---------------- fp32 -> fp16 hi/lo split ----------------
__global__ void cvt_split_kernel(const float* __restrict__ x, __half* __restrict__ h,
                                 __half* __restrict__ l, int n) {
    int i = blockIdx.x * 256 + threadIdx.x;
    if (i < n) {
        float v = x[i];
        __half hb = __float2half_rn(v);
        h[i] = hb;
        l[i] = __float2half_rn(v - __half2float(hb));
    }
}

// ---------------- transpose x: (B,32,L) -> (B*L, 32) ----------------
__global__ void transpose_x_kernel(const float* __restrict__ x, float* __restrict__ xT) {
    __shared__ float t[32][33];
    int b  = blockIdx.y;
    int l0 = blockIdx.x * 32;
    int tx = threadIdx.x, ty = threadIdx.y;
    t[ty][tx] = x[((size_t)b*32 + ty)*L_ + l0 + tx];
    __syncthreads();
    xT[((size_t)b*L_ + l0 + ty)*32 + tx] = t[tx][ty];
}

// ---------------- generic SGEMM (small GEMMs): C = A * B^T (+epilogue) ----------------
// MODE: 0=store, 1=+bias, 2=softplus(+bias)
template<int BM, int BN, int BK, int TM, int TN, int MODE>
__global__ __launch_bounds__((BM/TM)*(BN/TN))
void sgemm_kernel(const float* __restrict__ A, const float* __restrict__ Bw,
                  float* __restrict__ C, const float* __restrict__ bias,
                  int M, int N, int K, int lda, int ldb, int ldc) {
    constexpr int THREADS = (BM/TM)*(BN/TN);
    __shared__ float As[BK][BM];
    __shared__ float Bs[BK][BN];
    const int tid = threadIdx.x;
    const int bm  = blockIdx.y * BM;
    const int bn  = blockIdx.x * BN;
    const int tx  = tid % (BN/TN);
    const int ty  = tid / (BN/TN);

    float acc[TM][TN];
#pragma unroll
    for (int i = 0; i < TM; i++)
#pragma unroll
        for (int j = 0; j < TN; j++) acc[i][j] = 0.f;

    constexpr int AVEC = BM*BK/4/THREADS;
    constexpr int BVEC = BN*BK/4/THREADS;

    for (int k0 = 0; k0 < K; k0 += BK) {
#pragma unroll
        for (int i = 0; i < AVEC; i++) {
            int idx = tid + i*THREADS;
            int row = idx / (BK/4);
            int kc  = (idx % (BK/4)) * 4;
            float4 v = *reinterpret_cast<const float4*>(&A[(size_t)(bm+row)*lda + k0 + kc]);
            As[kc+0][row] = v.x; As[kc+1][row] = v.y; As[kc+2][row] = v.z; As[kc+3][row] = v.w;
        }
#pragma unroll
        for (int i = 0; i < BVEC; i++) {
            int idx = tid + i*THREADS;
            int row = idx / (BK/4);
            int kc  = (idx % (BK/4)) * 4;
            float4 v = *reinterpret_cast<const float4*>(&Bw[(size_t)(bn+row)*ldb + k0 + kc]);
            Bs[kc+0][row] = v.x; Bs[kc+1][row] = v.y; Bs[kc+2][row] = v.z; Bs[kc+3][row] = v.w;
        }
        __syncthreads();
#pragma unroll
        for (int kk = 0; kk < BK; kk++) {
            float a[TM], b[TN];
#pragma unroll
            for (int i = 0; i < TM; i++) a[i] = As[kk][ty*TM + i];
#pragma unroll
            for (int j = 0; j < TN; j++) b[j] = Bs[kk][tx*TN + j];
#pragma unroll
            for (int i = 0; i < TM; i++)
#pragma unroll
                for (int j = 0; j < TN; j++)
                    acc[i][j] = fmaf(a[i], b[j], acc[i][j]);
        }
        __syncthreads();
    }

#pragma unroll
    for (int i = 0; i < TM; i++) {
        int row = bm + ty*TM + i;
#pragma unroll
        for (int j = 0; j < TN; j++) {
            int col = bn + tx*TN + j;
            float v = acc[i][j];
            if (MODE == 1) v += bias[col];
            if (MODE == 2) {
                v += bias[col];
                v = (v > 20.f) ? v : log1pf(__expf(v));
            }
            C[(size_t)row*ldc + col] = v;
        }
    }
}

// ---------------- RMSNorm over d_model=512, fp16 output ----------------
__global__ void rmsnorm_kernel(const float* __restrict__ x, const float* __restrict__ w,
                               __half* __restrict__ oa) {
    int row = blockIdx.x;
    int tid = threadIdx.x;                       // 128 threads, 4 elems each
    const float4* xr = reinterpret_cast<const float4*>(x + (size_t)row*DM);
    float4 v = xr[tid];
    float ss = v.x*v.x + v.y*v.y + v.z*v.z + v.w*v.w;
#pragma unroll
    for (int o = 16; o; o >>= 1) ss += __shfl_xor_sync(0xffffffffu, ss, o);
    __shared__ float sred[4];
    if ((tid & 31) == 0) sred[tid >> 5] = ss;
    __syncthreads();
    float tot = sred[0] + sred[1] + sred[2] + sred[3];
    float scale = rsqrtf(tot * (1.f/(float)DM) + 1e-5f);
    float4 wv = reinterpret_cast<const float4*>(w)[tid];
    float o0 = v.x*scale*wv.x, o1 = v.y*scale*wv.y, o2 = v.z*scale*wv.z, o3 = v.w*scale*wv.w;
    size_t off = (size_t)row*DM + tid*4;
    __half2* oa2 = reinterpret_cast<__half2*>(oa + off);
    oa2[0] = __floats2half2_rn(o0, o1);
    oa2[1] = __floats2half2_rn(o2, o3);
}

// ---------------- depthwise causal conv(4) + bias + silu (float4 over channels) ----------------
__global__ void conv_silu_kernel(const float* __restrict__ xz, const float* __restrict__ cw,
                                 const float* __restrict__ cb, float* __restrict__ out) {
    size_t idx = (size_t)blockIdx.x * 256 + threadIdx.x;   // over B*L*ED/4
    int e4 = (idx & (ED/4 - 1)) * 4;         // channel group
    size_t row = idx >> 8;                    // b*L + l
    int l = (int)(row & (L_-1));
    const float* xr = xz + row * (size_t)(2*ED) + e4;
    float4 b4 = *reinterpret_cast<const float4*>(&cb[e4]);
    float4 w0 = *reinterpret_cast<const float4*>(&cw[(size_t)(e4+0)*4]);
    float4 w1 = *reinterpret_cast<const float4*>(&cw[(size_t)(e4+1)*4]);
    float4 w2 = *reinterpret_cast<const float4*>(&cw[(size_t)(e4+2)*4]);
    float4 w3 = *reinterpret_cast<const float4*>(&cw[(size_t)(e4+3)*4]);
    float4 acc = b4;
    float4 t0 = *reinterpret_cast<const float4*>(xr);
    acc.x = fmaf(w0.w, t0.x, acc.x); acc.y = fmaf(w1.w, t0.y, acc.y);
    acc.z = fmaf(w2.w, t0.z, acc.z); acc.w = fmaf(w3.w, t0.w, acc.w);
    if (l >= 1) {
        float4 t = *reinterpret_cast<const float4*>(xr - 2*ED);
        acc.x = fmaf(w0.z, t.x, acc.x); acc.y = fmaf(w1.z, t.y, acc.y);
        acc.z = fmaf(w2.z, t.z, acc.z); acc.w = fmaf(w3.z, t.w, acc.w);
    }
    if (l >= 2) {
        float4 t = *reinterpret_cast<const float4*>(xr - 4*ED);
        acc.x = fmaf(w0.y, t.x, acc.x); acc.y = fmaf(w1.y, t.y, acc.y);
        acc.z = fmaf(w2.y, t.z, acc.z); acc.w = fmaf(w3.y, t.w, acc.w);
    }
    if (l >= 3) {
        float4 t = *reinterpret_cast<const float4*>(xr - 6*ED);
        acc.x = fmaf(w0.x, t.x, acc.x); acc.y = fmaf(w1.x, t.y, acc.y);
        acc.z = fmaf(w2.x, t.z, acc.z); acc.w = fmaf(w3.x, t.w, acc.w);
    }
    float4 o;
    o.x = acc.x * sigmoidf_(acc.x); o.y = acc.y * sigmoidf_(acc.y);
    o.z = acc.z * sigmoidf_(acc.z); o.w = acc.w * sigmoidf_(acc.w);
    *reinterpret_cast<float4*>(&out[row * (size_t)ED + e4]) = o;
}

// ---------------- scan pass A: per-chunk local scan (h0=0) + decay product ----------------
__global__ void scan_passA(const float* __restrict__ delta, const float* __restrict__ u,
                           const float* __restrict__ dbc, const float* __restrict__ A_log,
                           float* __restrict__ hloc, float* __restrict__ Pout) {
    __shared__ float sB[LC][NST];
    int e = blockIdx.x * 128 + threadIdx.x;
    int c = blockIdx.y, b = blockIdx.z;
    for (int i = threadIdx.x; i < LC*NST; i += 128) {
        int row = i >> 4, col = i & 15;
        sB[row][col] = dbc[(size_t)(b*L_ + c*LC + row)*64 + 32 + col];
    }
    __syncthreads();

    float A[NST];
    bool fast = true;
#pragma unroll
    for (int n = 0; n < NST; n++) {
        float a = -__expf(A_log[(size_t)e*NST + n]);
        A[n] = a;
        fast = fast && (fabsf(a + (float)(n+1)) < 1e-4f * (float)(n+1));
    }

    float h[NST];
#pragma unroll
    for (int n = 0; n < NST; n++) h[n] = 0.f;
    float sd = 0.f;
    const float* dp = delta + (size_t)(b*L_ + c*LC)*ED + e;
    const float* up = u     + (size_t)(b*L_ + c*LC)*ED + e;

    if (fast) {
        for (int l = 0; l < LC; l++) {
            float dl = dp[(size_t)l*ED];
            float ul = up[(size_t)l*ED];
            float r  = __expf(-dl);
            float du = dl * ul;
            float p  = r;
            sd += dl;
#pragma unroll
            for (int n = 0; n < NST; n++) {
                h[n] = fmaf(p, h[n], du * sB[l][n]);
                p *= r;
            }
        }
    } else {
        for (int l = 0; l < LC; l++) {
            float dl = dp[(size_t)l*ED];
            float ul = up[(size_t)l*ED];
            float du = dl * ul;
            sd += dl;
#pragma unroll
            for (int n = 0; n < NST; n++) {
                float dA = __expf(dl * A[n]);
                h[n] = fmaf(dA, h[n], du * sB[l][n]);
            }
        }
    }
    size_t o = ((size_t)(b*CH + c)*ED + e)*NST;
#pragma unroll
    for (int n = 0; n < NST; n++) {
        hloc[o+n] = h[n];
        Pout[o+n] = __expf(A[n] * sd);
    }
}

// ---------------- scan combine: sequential over CH chunks ----------------
__global__ void scan_combine(const float* __restrict__ hloc, const float* __restrict__ P,
                             float* __restrict__ Hin) {
    int idx = blockIdx.x * 256 + threadIdx.x;   // over B*ED*NST = 262144
    int n = idx & 15;
    int e = (idx >> 4) & (ED-1);
    int b = idx >> 14;
    float H = 0.f;
#pragma unroll
    for (int c = 0; c < CH; c++) {
        size_t o = ((size_t)(b*CH + c)*ED + e)*NST + n;
        Hin[o] = H;
        H = fmaf(P[o], H, hloc[o]);
    }
}

// ---------------- scan pass B: re-scan with true init; fused y, D-skip, silu(z) gate, fp16 out ----------------
__global__ void scan_passB(const float* __restrict__ delta, const float* __restrict__ u,
                           const float* __restrict__ dbc, const float* __restrict__ xz,
                           const float* __restrict__ A_log, const float* __restrict__ Dv,
                           const float* __restrict__ Hin, __half* __restrict__ ya) {
    __shared__ float sB[LC][NST];
    __shared__ float sC[LC][NST];
    int e = blockIdx.x * 128 + threadIdx.x;
    int c = blockIdx.y, b = blockIdx.z;
    for (int i = threadIdx.x; i < LC*32; i += 128) {
        int row = i >> 5, col = i & 31;
        float v = dbc[(size_t)(b*L_ + c*LC + row)*64 + 32 + col];
        if (col < 16) sB[row][col] = v; else sC[row][col-16] = v;
    }
    __syncthreads();

    float A[NST];
    bool fast = true;
#pragma unroll
    for (int n = 0; n < NST; n++) {
        float a = -__expf(A_log[(size_t)e*NST + n]);
        A[n] = a;
        fast = fast && (fabsf(a + (float)(n+1)) < 1e-4f * (float)(n+1));
    }

    float h[NST];
    size_t oH = ((size_t)(b*CH + c)*ED + e)*NST;
#pragma unroll
    for (int n4 = 0; n4 < NST; n4 += 4) {
        float4 v = *reinterpret_cast<const float4*>(&Hin[oH + n4]);
        h[n4+0] = v.x; h[n4+1] = v.y; h[n4+2] = v.z; h[n4+3] = v.w;
    }
    float Dp = Dv[e];

    const float* dp = delta + (size_t)(b*L_ + c*LC)*ED + e;
    const float* up = u     + (size_t)(b*L_ + c*LC)*ED + e;
    const float* zp = xz    + (size_t)(b*L_ + c*LC)*(2*ED) + ED + e;
    size_t yo = (size_t)(b*L_ + c*LC)*ED + e;

    if (fast) {
        for (int l = 0; l < LC; l++) {
            float dl = dp[(size_t)l*ED];
            float ul = up[(size_t)l*ED];
            float r  = __expf(-dl);
            float du = dl * ul;
            float p  = r;
            float y  = 0.f;
#pragma unroll
            for (int n = 0; n < NST; n++) {
                h[n] = fmaf(p, h[n], du * sB[l][n]);
                y = fmaf(h[n], sC[l][n], y);
                p *= r;
            }
            float zl = zp[(size_t)l*(2*ED)];
            float yt = fmaf(Dp, ul, y) * zl * sigmoidf_(zl);
            ya[yo + (size_t)l*ED] = __float2half_rn(yt);
        }
    } else {
        for (int l = 0; l < LC; l++) {
            float dl = dp[(size_t)l*ED];
            float ul = up[(size_t)l*ED];
            float du = dl * ul;
            float y  = 0.f;
#pragma unroll
            for (int n = 0; n < NST; n++) {
                float dA = __expf(dl * A[n]);
                h[n] = fmaf(dA, h[n], du * sB[l][n]);
                y = fmaf(h[n], sC[l][n], y);
            }
            float zl = zp[(size_t)l*(2*ED)];
            float yt = fmaf(Dp, ul, y) * zl * sigmoidf_(zl);
            ya[yo + (size_t)l*ED] = __float2half_rn(yt);
        }
    }
}

// ---------------- head: y = h[:, -1, :] @ head_w^T + head_b, transposed write ----------------
__global__ void head_kernel(const float* __restrict__ h, const float* __restrict__ hw,
                            const float* __restrict__ hb, float* __restrict__ out) {
    int w    = blockIdx.x * 8 + (threadIdx.x >> 5);
    int lane = threadIdx.x & 31;
    int n = w % 3072;
    int b = w / 3072;
    const float4* hr4 = reinterpret_cast<const float4*>(h + ((size_t)b*L_ + (L_-1))*DM);
    const float4* wr4 = reinterpret_cast<const float4*>(hw + (size_t)n*DM);
    float s = 0.f;
#pragma unroll
    for (int i = 0; i < 4; i++) {
        int k4 = lane + i*32;
        float4 a = hr4[k4];
        float4 ww = wr4[k4];
        s += a.x*ww.x + a.y*ww.y + a.z*ww.z + a.w*ww.w;
    }
#pragma unroll
    for (int o = 16; o; o >>= 1) s += __shfl_xor_sync(0xffffffffu, s, o);
    if (lane == 0) {
        int c = n & 31, t = n >> 5;
        out[(size_t)b*3072 + (size_t)c*96 + t] = s + hb[n];
    }
}

// ---------------- launch ----------------
extern "C" void kernel_launch(void* const* d_in, const int* in_sizes, int n_in,
                              void* d_out, int out_size) {
    const float* x        = (const float*)d_in[0];
    const float* embed_w  = (const float*)d_in[1];
    const float* embed_b  = (const float*)d_in[2];
    const float* norm_w   = (const float*)d_in[3];
    const float* in_w     = (const float*)d_in[4];
    const float* conv_w   = (const float*)d_in[5];
    const float* conv_b   = (const float*)d_in[6];
    const float* xp_w     = (const float*)d_in[7];
    const float* dt_w     = (const float*)d_in[8];
    const float* dt_b     = (const float*)d_in[9];
    const float* A_log    = (const float*)d_in[10];
    const float* Dv       = (const float*)d_in[11];
    const float* out_w    = (const float*)d_in[12];
    const float* head_w   = (const float*)d_in[13];
    const float* head_b   = (const float*)d_in[14];
    float* out = (float*)d_out;

    float *h, *xz, *xc, *dbc, *delta, *hloc, *P, *Hin, *xT;
    __half *a, *wih, *wil, *woh, *wol;
    cudaGetSymbolAddress((void**)&h,     g_h);
    cudaGetSymbolAddress((void**)&xz,    g_xz);
    cudaGetSymbolAddress((void**)&xc,    g_xc);
    cudaGetSymbolAddress((void**)&dbc,   g_dbc);
    cudaGetSymbolAddress((void**)&delta, g_delta);
    cudaGetSymbolAddress((void**)&hloc,  g_hloc);
    cudaGetSymbolAddress((void**)&P,     g_P);
    cudaGetSymbolAddress((void**)&Hin,   g_Hin);
    cudaGetSymbolAddress((void**)&xT,    g_xT);
    cudaGetSymbolAddress((void**)&a,     g_a);
    cudaGetSymbolAddress((void**)&wih,   g_wih);
    cudaGetSymbolAddress((void**)&wil,   g_wil);
    cudaGetSymbolAddress((void**)&woh,   g_woh);
    cudaGetSymbolAddress((void**)&wol,   g_wol);

    cudaFuncSetAttribute(mma_gemm<0>, cudaFuncAttributeMaxDynamicSharedMemorySize, MMA_SMEM);
    cudaFuncSetAttribute(mma_gemm<1>, cudaFuncAttributeMaxDynamicSharedMemorySize, MMA_SMEM);

    // weight splits (all layers, once per launch)
    cvt_split_kernel<<<(NL*2*ED*DM + 255)/256, 256>>>(in_w,  wih, wil, NL*2*ED*DM);
    cvt_split_kernel<<<(NL*DM*ED   + 255)/256, 256>>>(out_w, woh, wol, NL*DM*ED);

    // embed: h = x^T @ embed_w^T + embed_b
    transpose_x_kernel<<<dim3(L_/32, B_), dim3(32, 32)>>>(x, xT);
    sgemm_kernel<128,128,16,8,8,1><<<dim3(DM/128, MROWS/128), 256>>>(
        xT, embed_w, h, embed_b, MROWS, DM, 32, 32, 32, DM);

    for (int i = 0; i < NL; i++) {
        // rmsnorm -> fp16 (A operand for in_proj, lda=512)
        rmsnorm_kernel<<<MROWS, 128>>>(h, norm_w + (size_t)i*DM, a);

        // xz = rms @ in_proj^T  (split-fp16 tensor-core: M=16384, N=2048, K=512)
        mma_gemm<0><<<dim3(2*ED/256, MROWS/128), 512, MMA_SMEM>>>(
            a, wih + (size_t)i*2*ED*DM, wil + (size_t)i*2*ED*DM,
            xz, DM, DM, DM, 2*ED);

        // depthwise causal conv + silu
        conv_silu_kernel<<<(MROWS*ED/4)/256, 256>>>(
            xz, conv_w + (size_t)i*ED*4, conv_b + (size_t)i*ED, xc);

        // dbc = xc @ x_proj^T   (N=64, K=1024)
        sgemm_kernel<64,64,16,4,4,0><<<dim3(1, MROWS/64), 256>>>(
            xc, xp_w + (size_t)i*64*ED, dbc, nullptr, MROWS, 64, ED, ED, ED, 64);

        // delta = softplus(dbc[:, :32] @ dt_w^T + dt_b)
        sgemm_kernel<128,128,16,8,8,2><<<dim3(ED/128, MROWS/128), 256>>>(
            dbc, dt_w + (size_t)i*ED*DR, delta, dt_b + (size_t)i*ED,
            MROWS, ED, DR, 64, DR, ED);

        // chunked selective scan (pass B emits y as fp16, lda=1024)
        scan_passA<<<dim3(ED/128, CH, B_), 128>>>(
            delta, xc, dbc, A_log + (size_t)i*ED*NST, hloc, P);
        scan_combine<<<(B_*ED*NST)/256, 256>>>(hloc, P, Hin);
        scan_passB<<<dim3(ED/128, CH, B_), 128>>>(
            delta, xc, dbc, xz, A_log + (size_t)i*ED*NST, Dv + (size_t)i*ED, Hin, a);

        // h += y @ out_proj^T  (split-fp16 tensor-core: M=16384, N=512, K=1024, residual)
        mma_gemm<1><<<dim3(DM/256, MROWS/128), 512, MMA_SMEM>>>(
            a, woh + (size_t)i*DM*ED, wol + (size_t)i*DM*ED,
            h, ED, ED, ED, DM);
    }

    head_kernel<<<(B_*3072)/8, 256>>>(h, head_w, head_b, out);
}

// round 9
// speedup vs baseline: 2.6484x; 1.1854x over previous
#include <cuda_runtime.h>
#include <cuda_fp16.h>
#include <math.h>
#include <stdint.h>

// ---------------- problem constants ----------------
#define B_   16
#define L_   1024
#define DM   512      // d_model
#define ED   1024     // d_inner
#define NST  16       // d_state
#define NL   4
#define DR   32       // dt_rank
#define CH   8        // scan chunks
#define LC   128      // chunk length  (CH*LC == L_)
#define MROWS (B_*L_) // 16384

// ---------------- scratch (device globals; no allocation allowed) ----------------
__device__ __align__(16) float g_h    [(size_t)MROWS*DM];
__device__ __align__(16) float g_xz   [(size_t)MROWS*2*ED];
__device__ __align__(16) float g_xc   [(size_t)MROWS*ED];
__device__ __align__(16) float g_dbc  [(size_t)MROWS*64];
__device__ __align__(16) float g_delta[(size_t)MROWS*ED];
__device__ __align__(16) float g_hloc [(size_t)B_*CH*ED*NST];
__device__ __align__(16) float g_P    [(size_t)B_*CH*ED*NST];
__device__ __align__(16) float g_Hin  [(size_t)B_*CH*ED*NST];
__device__ __align__(16) float g_xT   [(size_t)MROWS*32];
// fp16 activations (A operand). lda=512 (rmsnorm out) then lda=1024 (y).
__device__ __align__(16) __half g_a  [(size_t)MROWS*ED];
// fp16 weights
__device__ __align__(16) __half g_wi [(size_t)NL*2*ED*DM];
__device__ __align__(16) __half g_wo [(size_t)NL*DM*ED];

__device__ __forceinline__ float sigmoidf_(float x) { return 1.f / (1.f + __expf(-x)); }

// ================= mma.sync fp16 helpers (non-arch-gated PTX) =================
__device__ __forceinline__ void ldm_x4(uint32_t (&r)[4], uint32_t a) {
    asm volatile("ldmatrix.sync.aligned.m8n8.x4.shared.b16 {%0,%1,%2,%3}, [%4];"
                 : "=r"(r[0]), "=r"(r[1]), "=r"(r[2]), "=r"(r[3]) : "r"(a));
}
__device__ __forceinline__ void mma_fp16(float (&d)[4], const uint32_t (&a)[4],
                                         uint32_t b0, uint32_t b1) {
    asm volatile(
        "mma.sync.aligned.m16n8k16.row.col.f32.f16.f16.f32 "
        "{%0,%1,%2,%3}, {%4,%5,%6,%7}, {%8,%9}, {%0,%1,%2,%3};"
        : "+f"(d[0]), "+f"(d[1]), "+f"(d[2]), "+f"(d[3])
        : "r"(a[0]), "r"(a[1]), "r"(a[2]), "r"(a[3]), "r"(b0), "r"(b1));
}
__device__ __forceinline__ void cp_async16(uint32_t sdst, const void* gsrc) {
    asm volatile("cp.async.cg.shared.global [%0], [%1], 16;" :: "r"(sdst), "l"(gsrc));
}
__device__ __forceinline__ void cp_commit() { asm volatile("cp.async.commit_group;"); }
__device__ __forceinline__ void cp_wait1()  { asm volatile("cp.async.wait_group 1;"); }
__device__ __forceinline__ void cp_wait0()  { asm volatile("cp.async.wait_group 0;"); }

// ================= fp16 tensor-core GEMM =================
// C(MxN) = A(MxK)*B(NxK)^T  (fp16 mma, fp32 accum)
// CTA tile 128(M)x256(N), 512 threads = 16 warps (4x4), warp tile 32x64.
// BK=32, 3-stage cp.async pipeline (R7-proven scheme), one __syncthreads/chunk.
// SMEM row pitch 80B (32 fp16 + 16B pad).
#define ROWB    80
#define A_TEN   (128*ROWB)               // 10240
#define B_TEN   (256*ROWB)               // 20480
#define STG_SZ  (A_TEN + B_TEN)          // 30720
#define MMA_SMEM (3*STG_SZ)              // 92160

template<int MODE>  // 0: store, 1: C += result
__global__ __launch_bounds__(512, 1)
void mma_gemm(const __half* __restrict__ A, const __half* __restrict__ B,
              float* __restrict__ C, int K, int lda, int ldb, int ldc) {
    extern __shared__ char smem[];
    const uint32_t sbase = (uint32_t)__cvta_generic_to_shared(smem);
    const int tid  = threadIdx.x;
    const int wid  = tid >> 5, lane = tid & 31;
    const int wm   = wid & 3;           // 0..3 : 32 rows each
    const int wn   = wid >> 2;          // 0..3 : 64 cols each
    const int bm   = blockIdx.y * 128;
    const int bn   = blockIdx.x * 256;
    const int NC   = K >> 5;

    float acc[2][8][4];
#pragma unroll
    for (int i = 0; i < 2; i++)
#pragma unroll
        for (int j = 0; j < 8; j++)
#pragma unroll
            for (int q = 0; q < 4; q++) acc[i][j][q] = 0.f;

    const int arow  = tid >> 2,          akc = tid & 3;
    const int brow0 = tid >> 2,          bkc0 = tid & 3;
    const int brow1 = (tid + 512) >> 2,  bkc1 = tid & 3;

    const __half* gA  = A + (size_t)(bm + arow)  * lda + akc  * 8;
    const __half* gB0 = B + (size_t)(bn + brow0) * ldb + bkc0 * 8;
    const __half* gB1 = B + (size_t)(bn + brow1) * ldb + bkc1 * 8;
    const uint32_t sA  = sbase + arow  * ROWB + akc  * 16;
    const uint32_t sB0 = sbase + brow0 * ROWB + bkc0 * 16;
    const uint32_t sB1 = sbase + brow1 * ROWB + bkc1 * 16;

#define LOAD_STAGE(c, s) do {                                          \
        int koff = (c) << 5;                                           \
        uint32_t st = (uint32_t)(s) * STG_SZ;                          \
        cp_async16(sA  + st,         gA  + koff);                      \
        cp_async16(sB0 + st + A_TEN, gB0 + koff);                      \
        cp_async16(sB1 + st + A_TEN, gB1 + koff);                      \
        cp_commit();                                                   \
    } while (0)

    LOAD_STAGE(0, 0);
    LOAD_STAGE(1, 1);

    const int aRow = (lane & 15);
    const int aKby = ((lane >> 4) << 4);
    const int bRow = (lane & 7) | ((lane >> 4) << 3);
    const int bKby = (((lane >> 3) & 1) << 4);

    int stg = 0;  // stage holding chunk c
    for (int c = 0; c < NC; c++) {
        if (c + 1 < NC) cp_wait1(); else cp_wait0();
        __syncthreads();   // all warps finished reading stage (c+2)%3 (chunk c-1's stage)
        int nstg = stg + 2; if (nstg >= 3) nstg -= 3;
        if (c + 2 < NC) LOAD_STAGE(c + 2, nstg);

        const uint32_t st  = sbase + (uint32_t)stg * STG_SZ;
        const uint32_t sA_ = st;
        const uint32_t sB_ = st + A_TEN;

        // A-fragment double buffer across the two k16 halves
        uint32_t af[2][2][4];
#pragma unroll
        for (int mf = 0; mf < 2; mf++) {
            uint32_t off = (uint32_t)(wm*32 + mf*16 + aRow) * ROWB + aKby;
            ldm_x4(af[0][mf], sA_ + off);
        }
#pragma unroll
        for (int k16 = 0; k16 < 2; k16++) {
            const int kb = k16 * 32;
            if (k16 == 0) {
#pragma unroll
                for (int mf = 0; mf < 2; mf++) {
                    uint32_t off = (uint32_t)(wm*32 + mf*16 + aRow) * ROWB + 32 + aKby;
                    ldm_x4(af[1][mf], sA_ + off);
                }
            }
#pragma unroll
            for (int nf2 = 0; nf2 < 4; nf2++) {
                uint32_t bf[4];
                uint32_t off = (uint32_t)(wn*64 + nf2*16 + bRow) * ROWB + kb + bKby;
                ldm_x4(bf, sB_ + off);
#pragma unroll
                for (int half = 0; half < 2; half++) {
#pragma unroll
                    for (int mf = 0; mf < 2; mf++) {
                        int nf = nf2*2 + half;
                        mma_fp16(acc[mf][nf], af[k16][mf], bf[half*2], bf[half*2+1]);
                    }
                }
            }
        }
        stg++; if (stg >= 3) stg = 0;
    }

    // epilogue: direct register -> gmem (float2 stores)
    const int erow = lane >> 2;
    const int ecol = (lane & 3) * 2;
#pragma unroll
    for (int mf = 0; mf < 2; mf++) {
#pragma unroll
        for (int nf = 0; nf < 8; nf++) {
            int row0 = bm + wm*32 + mf*16 + erow;
            int col  = bn + wn*64 + nf*8 + ecol;
            float* p0 = C + (size_t)row0 * ldc + col;
            float* p1 = C + (size_t)(row0 + 8) * ldc + col;
            float2 v0 = make_float2(acc[mf][nf][0], acc[mf][nf][1]);
            float2 v1 = make_float2(acc[mf][nf][2], acc[mf][nf][3]);
            if (MODE == 1) {
                float2 o0 = *reinterpret_cast<float2*>(p0);
                float2 o1 = *reinterpret_cast<float2*>(p1);
                v0.x += o0.x; v0.y += o0.y; v1.x += o1.x; v1.y += o1.y;
            }
            *reinterpret_cast<float2*>(p0) = v0;
            *reinterpret_cast<float2*>(p1) = v1;
        }
    }
#undef LOAD_STAGE
}

// ---------------- fp32 -> fp16 ----------------
__global__ void cvt_fp16_kernel(const float* __restrict__ x, __half* __restrict__ h, int n) {
    int i = blockIdx.x * 256 + threadIdx.x;
    if (i < n) h[i] = __float2half_rn(x[i]);
}

// ---------------- transpose x: (B,32,L) -> (B*L, 32) ----------------
__global__ void transpose_x_kernel(const float* __restrict__ x, float* __restrict__ xT) {
    __shared__ float t[32][33];
    int b  = blockIdx.y;
    int l0 = blockIdx.x * 32;
    int tx = threadIdx.x, ty = threadIdx.y;
    t[ty][tx] = x[((size_t)b*32 + ty)*L_ + l0 + tx];
    __syncthreads();
    xT[((size_t)b*L_ + l0 + ty)*32 + tx] = t[tx][ty];
}

// ---------------- generic SGEMM (small GEMMs): C = A * B^T (+epilogue) ----------------
// MODE: 0=store, 1=+bias, 2=softplus(+bias)
template<int BM, int BN, int BK, int TM, int TN, int MODE>
__global__ __launch_bounds__((BM/TM)*(BN/TN))
void sgemm_kernel(const float* __restrict__ A, const float* __restrict__ Bw,
                  float* __restrict__ C, const float* __restrict__ bias,
                  int M, int N, int K, int lda, int ldb, int ldc) {
    constexpr int THREADS = (BM/TM)*(BN/TN);
    __shared__ float As[BK][BM];
    __shared__ float Bs[BK][BN];
    const int tid = threadIdx.x;
    const int bm  = blockIdx.y * BM;
    const int bn  = blockIdx.x * BN;
    const int tx  = tid % (BN/TN);
    const int ty  = tid / (BN/TN);

    float acc[TM][TN];
#pragma unroll
    for (int i = 0; i < TM; i++)
#pragma unroll
        for (int j = 0; j < TN; j++) acc[i][j] = 0.f;

    constexpr int AVEC = BM*BK/4/THREADS;
    constexpr int BVEC = BN*BK/4/THREADS;

    for (int k0 = 0; k0 < K; k0 += BK) {
#pragma unroll
        for (int i = 0; i < AVEC; i++) {
            int idx = tid + i*THREADS;
            int row = idx / (BK/4);
            int kc  = (idx % (BK/4)) * 4;
            float4 v = *reinterpret_cast<const float4*>(&A[(size_t)(bm+row)*lda + k0 + kc]);
            As[kc+0][row] = v.x; As[kc+1][row] = v.y; As[kc+2][row] = v.z; As[kc+3][row] = v.w;
        }
#pragma unroll
        for (int i = 0; i < BVEC; i++) {
            int idx = tid + i*THREADS;
            int row = idx / (BK/4);
            int kc  = (idx % (BK/4)) * 4;
            float4 v = *reinterpret_cast<const float4*>(&Bw[(size_t)(bn+row)*ldb + k0 + kc]);
            Bs[kc+0][row] = v.x; Bs[kc+1][row] = v.y; Bs[kc+2][row] = v.z; Bs[kc+3][row] = v.w;
        }
        __syncthreads();
#pragma unroll
        for (int kk = 0; kk < BK; kk++) {
            float a[TM], b[TN];
#pragma unroll
            for (int i = 0; i < TM; i++) a[i] = As[kk][ty*TM + i];
#pragma unroll
            for (int j = 0; j < TN; j++) b[j] = Bs[kk][tx*TN + j];
#pragma unroll
            for (int i = 0; i < TM; i++)
#pragma unroll
                for (int j = 0; j < TN; j++)
                    acc[i][j] = fmaf(a[i], b[j], acc[i][j]);
        }
        __syncthreads();
    }

#pragma unroll
    for (int i = 0; i < TM; i++) {
        int row = bm + ty*TM + i;
#pragma unroll
        for (int j = 0; j < TN; j++) {
            int col = bn + tx*TN + j;
            float v = acc[i][j];
            if (MODE == 1) v += bias[col];
            if (MODE == 2) {
                v += bias[col];
                v = (v > 20.f) ? v : log1pf(__expf(v));
            }
            C[(size_t)row*ldc + col] = v;
        }
    }
}

// ---------------- RMSNorm over d_model=512, fp16 output ----------------
__global__ void rmsnorm_kernel(const float* __restrict__ x, const float* __restrict__ w,
                               __half* __restrict__ oa) {
    int row = blockIdx.x;
    int tid = threadIdx.x;                       // 128 threads, 4 elems each
    const float4* xr = reinterpret_cast<const float4*>(x + (size_t)row*DM);
    float4 v = xr[tid];
    float ss = v.x*v.x + v.y*v.y + v.z*v.z + v.w*v.w;
#pragma unroll
    for (int o = 16; o; o >>= 1) ss += __shfl_xor_sync(0xffffffffu, ss, o);
    __shared__ float sred[4];
    if ((tid & 31) == 0) sred[tid >> 5] = ss;
    __syncthreads();
    float tot = sred[0] + sred[1] + sred[2] + sred[3];
    float scale = rsqrtf(tot * (1.f/(float)DM) + 1e-5f);
    float4 wv = reinterpret_cast<const float4*>(w)[tid];
    float o0 = v.x*scale*wv.x, o1 = v.y*scale*wv.y, o2 = v.z*scale*wv.z, o3 = v.w*scale*wv.w;
    size_t off = (size_t)row*DM + tid*4;
    __half2* oa2 = reinterpret_cast<__half2*>(oa + off);
    oa2[0] = __floats2half2_rn(o0, o1);
    oa2[1] = __floats2half2_rn(o2, o3);
}

// ---------------- depthwise causal conv(4) + bias + silu (float4 over channels) ----------------
__global__ void conv_silu_kernel(const float* __restrict__ xz, const float* __restrict__ cw,
                                 const float* __restrict__ cb, float* __restrict__ out) {
    size_t idx = (size_t)blockIdx.x * 256 + threadIdx.x;   // over B*L*ED/4
    int e4 = (idx & (ED/4 - 1)) * 4;         // channel group
    size_t row = idx >> 8;                    // b*L + l
    int l = (int)(row & (L_-1));
    const float* xr = xz + row * (size_t)(2*ED) + e4;
    float4 b4 = *reinterpret_cast<const float4*>(&cb[e4]);
    float4 w0 = *reinterpret_cast<const float4*>(&cw[(size_t)(e4+0)*4]);
    float4 w1 = *reinterpret_cast<const float4*>(&cw[(size_t)(e4+1)*4]);
    float4 w2 = *reinterpret_cast<const float4*>(&cw[(size_t)(e4+2)*4]);
    float4 w3 = *reinterpret_cast<const float4*>(&cw[(size_t)(e4+3)*4]);
    float4 acc = b4;
    float4 t0 = *reinterpret_cast<const float4*>(xr);
    acc.x = fmaf(w0.w, t0.x, acc.x); acc.y = fmaf(w1.w, t0.y, acc.y);
    acc.z = fmaf(w2.w, t0.z, acc.z); acc.w = fmaf(w3.w, t0.w, acc.w);
    if (l >= 1) {
        float4 t = *reinterpret_cast<const float4*>(xr - 2*ED);
        acc.x = fmaf(w0.z, t.x, acc.x); acc.y = fmaf(w1.z, t.y, acc.y);
        acc.z = fmaf(w2.z, t.z, acc.z); acc.w = fmaf(w3.z, t.w, acc.w);
    }
    if (l >= 2) {
        float4 t = *reinterpret_cast<const float4*>(xr - 4*ED);
        acc.x = fmaf(w0.y, t.x, acc.x); acc.y = fmaf(w1.y, t.y, acc.y);
        acc.z = fmaf(w2.y, t.z, acc.z); acc.w = fmaf(w3.y, t.w, acc.w);
    }
    if (l >= 3) {
        float4 t = *reinterpret_cast<const float4*>(xr - 6*ED);
        acc.x = fmaf(w0.x, t.x, acc.x); acc.y = fmaf(w1.x, t.y, acc.y);
        acc.z = fmaf(w2.x, t.z, acc.z); acc.w = fmaf(w3.x, t.w, acc.w);
    }
    float4 o;
    o.x = acc.x * sigmoidf_(acc.x); o.y = acc.y * sigmoidf_(acc.y);
    o.z = acc.z * sigmoidf_(acc.z); o.w = acc.w * sigmoidf_(acc.w);
    *reinterpret_cast<float4*>(&out[row * (size_t)ED + e4]) = o;
}

// ---------------- scan pass A: per-chunk local scan (h0=0) + decay product ----------------
__global__ void scan_passA(const float* __restrict__ delta, const float* __restrict__ u,
                           const float* __restrict__ dbc, const float* __restrict__ A_log,
                           float* __restrict__ hloc, float* __restrict__ Pout) {
    __shared__ float sB[LC][NST];
    int e = blockIdx.x * 128 + threadIdx.x;
    int c = blockIdx.y, b = blockIdx.z;
    for (int i = threadIdx.x; i < LC*NST; i += 128) {
        int row = i >> 4, col = i & 15;
        sB[row][col] = dbc[(size_t)(b*L_ + c*LC + row)*64 + 32 + col];
    }
    __syncthreads();

    float A[NST];
    bool fast = true;
#pragma unroll
    for (int n = 0; n < NST; n++) {
        float a = -__expf(A_log[(size_t)e*NST + n]);
        A[n] = a;
        fast = fast && (fabsf(a + (float)(n+1)) < 1e-4f * (float)(n+1));
    }

    float h[NST];
#pragma unroll
    for (int n = 0; n < NST; n++) h[n] = 0.f;
    float sd = 0.f;
    const float* dp = delta + (size_t)(b*L_ + c*LC)*ED + e;
    const float* up = u     + (size_t)(b*L_ + c*LC)*ED + e;

    if (fast) {
        for (int l = 0; l < LC; l++) {
            float dl = dp[(size_t)l*ED];
            float ul = up[(size_t)l*ED];
            float r  = __expf(-dl);
            float du = dl * ul;
            float p  = r;
            sd += dl;
#pragma unroll
            for (int n = 0; n < NST; n++) {
                h[n] = fmaf(p, h[n], du * sB[l][n]);
                p *= r;
            }
        }
    } else {
        for (int l = 0; l < LC; l++) {
            float dl = dp[(size_t)l*ED];
            float ul = up[(size_t)l*ED];
            float du = dl * ul;
            sd += dl;
#pragma unroll
            for (int n = 0; n < NST; n++) {
                float dA = __expf(dl * A[n]);
                h[n] = fmaf(dA, h[n], du * sB[l][n]);
            }
        }
    }
    size_t o = ((size_t)(b*CH + c)*ED + e)*NST;
#pragma unroll
    for (int n = 0; n < NST; n++) {
        hloc[o+n] = h[n];
        Pout[o+n] = __expf(A[n] * sd);
    }
}

// ---------------- scan combine: sequential over CH chunks ----------------
__global__ void scan_combine(const float* __restrict__ hloc, const float* __restrict__ P,
                             float* __restrict__ Hin) {
    int idx = blockIdx.x * 256 + threadIdx.x;   // over B*ED*NST = 262144
    int n = idx & 15;
    int e = (idx >> 4) & (ED-1);
    int b = idx >> 14;
    float H = 0.f;
#pragma unroll
    for (int c = 0; c < CH; c++) {
        size_t o = ((size_t)(b*CH + c)*ED + e)*NST + n;
        Hin[o] = H;
        H = fmaf(P[o], H, hloc[o]);
    }
}

// ---------------- scan pass B: re-scan with true init; fused y, D-skip, silu(z) gate, fp16 out ----------------
__global__ void scan_passB(const float* __restrict__ delta, const float* __restrict__ u,
                           const float* __restrict__ dbc, const float* __restrict__ xz,
                           const float* __restrict__ A_log, const float* __restrict__ Dv,
                           const float* __restrict__ Hin, __half* __restrict__ ya) {
    __shared__ float sB[LC][NST];
    __shared__ float sC[LC][NST];
    int e = blockIdx.x * 128 + threadIdx.x;
    int c = blockIdx.y, b = blockIdx.z;
    for (int i = threadIdx.x; i < LC*32; i += 128) {
        int row = i >> 5, col = i & 31;
        float v = dbc[(size_t)(b*L_ + c*LC + row)*64 + 32 + col];
        if (col < 16) sB[row][col] = v; else sC[row][col-16] = v;
    }
    __syncthreads();

    float A[NST];
    bool fast = true;
#pragma unroll
    for (int n = 0; n < NST; n++) {
        float a = -__expf(A_log[(size_t)e*NST + n]);
        A[n] = a;
        fast = fast && (fabsf(a + (float)(n+1)) < 1e-4f * (float)(n+1));
    }

    float h[NST];
    size_t oH = ((size_t)(b*CH + c)*ED + e)*NST;
#pragma unroll
    for (int n4 = 0; n4 < NST; n4 += 4) {
        float4 v = *reinterpret_cast<const float4*>(&Hin[oH + n4]);
        h[n4+0] = v.x; h[n4+1] = v.y; h[n4+2] = v.z; h[n4+3] = v.w;
    }
    float Dp = Dv[e];

    const float* dp = delta + (size_t)(b*L_ + c*LC)*ED + e;
    const float* up = u     + (size_t)(b*L_ + c*LC)*ED + e;
    const float* zp = xz    + (size_t)(b*L_ + c*LC)*(2*ED) + ED + e;
    size_t yo = (size_t)(b*L_ + c*LC)*ED + e;

    if (fast) {
        for (int l = 0; l < LC; l++) {
            float dl = dp[(size_t)l*ED];
            float ul = up[(size_t)l*ED];
            float r  = __expf(-dl);
            float du = dl * ul;
            float p  = r;
            float y  = 0.f;
#pragma unroll
            for (int n = 0; n < NST; n++) {
                h[n] = fmaf(p, h[n], du * sB[l][n]);
                y = fmaf(h[n], sC[l][n], y);
                p *= r;
            }
            float zl = zp[(size_t)l*(2*ED)];
            float yt = fmaf(Dp, ul, y) * zl * sigmoidf_(zl);
            ya[yo + (size_t)l*ED] = __float2half_rn(yt);
        }
    } else {
        for (int l = 0; l < LC; l++) {
            float dl = dp[(size_t)l*ED];
            float ul = up[(size_t)l*ED];
            float du = dl * ul;
            float y  = 0.f;
#pragma unroll
            for (int n = 0; n < NST; n++) {
                float dA = __expf(dl * A[n]);
                h[n] = fmaf(dA, h[n], du * sB[l][n]);
                y = fmaf(h[n], sC[l][n], y);
            }
            float zl = zp[(size_t)l*(2*ED)];
            float yt = fmaf(Dp, ul, y) * zl * sigmoidf_(zl);
            ya[yo + (size_t)l*ED] = __float2half_rn(yt);
        }
    }
}

// ---------------- head: y = h[:, -1, :] @ head_w^T + head_b, transposed write ----------------
__global__ void head_kernel(const float* __restrict__ h, const float* __restrict__ hw,
                            const float* __restrict__ hb, float* __restrict__ out) {
    int w    = blockIdx.x * 8 + (threadIdx.x >> 5);
    int lane = threadIdx.x & 31;
    int n = w % 3072;
    int b = w / 3072;
    const float4* hr4 = reinterpret_cast<const float4*>(h + ((size_t)b*L_ + (L_-1))*DM);
    const float4* wr4 = reinterpret_cast<const float4*>(hw + (size_t)n*DM);
    float s = 0.f;
#pragma unroll
    for (int i = 0; i < 4; i++) {
        int k4 = lane + i*32;
        float4 a = hr4[k4];
        float4 ww = wr4[k4];
        s += a.x*ww.x + a.y*ww.y + a.z*ww.z + a.w*ww.w;
    }
#pragma unroll
    for (int o = 16; o; o >>= 1) s += __shfl_xor_sync(0xffffffffu, s, o);
    if (lane == 0) {
        int c = n & 31, t = n >> 5;
        out[(size_t)b*3072 + (size_t)c*96 + t] = s + hb[n];
    }
}

// ---------------- launch ----------------
extern "C" void kernel_launch(void* const* d_in, const int* in_sizes, int n_in,
                              void* d_out, int out_size) {
    const float* x        = (const float*)d_in[0];
    const float* embed_w  = (const float*)d_in[1];
    const float* embed_b  = (const float*)d_in[2];
    const float* norm_w   = (const float*)d_in[3];
    const float* in_w     = (const float*)d_in[4];
    const float* conv_w   = (const float*)d_in[5];
    const float* conv_b   = (const float*)d_in[6];
    const float* xp_w     = (const float*)d_in[7];
    const float* dt_w     = (const float*)d_in[8];
    const float* dt_b     = (const float*)d_in[9];
    const float* A_log    = (const float*)d_in[10];
    const float* Dv       = (const float*)d_in[11];
    const float* out_w    = (const float*)d_in[12];
    const float* head_w   = (const float*)d_in[13];
    const float* head_b   = (const float*)d_in[14];
    float* out = (float*)d_out;

    float *h, *xz, *xc, *dbc, *delta, *hloc, *P, *Hin, *xT;
    __half *a, *wi, *wo;
    cudaGetSymbolAddress((void**)&h,     g_h);
    cudaGetSymbolAddress((void**)&xz,    g_xz);
    cudaGetSymbolAddress((void**)&xc,    g_xc);
    cudaGetSymbolAddress((void**)&dbc,   g_dbc);
    cudaGetSymbolAddress((void**)&delta, g_delta);
    cudaGetSymbolAddress((void**)&hloc,  g_hloc);
    cudaGetSymbolAddress((void**)&P,     g_P);
    cudaGetSymbolAddress((void**)&Hin,   g_Hin);
    cudaGetSymbolAddress((void**)&xT,    g_xT);
    cudaGetSymbolAddress((void**)&a,     g_a);
    cudaGetSymbolAddress((void**)&wi,    g_wi);
    cudaGetSymbolAddress((void**)&wo,    g_wo);

    cudaFuncSetAttribute(mma_gemm<0>, cudaFuncAttributeMaxDynamicSharedMemorySize, MMA_SMEM);
    cudaFuncSetAttribute(mma_gemm<1>, cudaFuncAttributeMaxDynamicSharedMemorySize, MMA_SMEM);

    // weight conversion (all layers, once per launch)
    cvt_fp16_kernel<<<(NL*2*ED*DM + 255)/256, 256>>>(in_w,  wi, NL*2*ED*DM);
    cvt_fp16_kernel<<<(NL*DM*ED   + 255)/256, 256>>>(out_w, wo, NL*DM*ED);

    // embed: h = x^T @ embed_w^T + embed_b
    transpose_x_kernel<<<dim3(L_/32, B_), dim3(32, 32)>>>(x, xT);
    sgemm_kernel<128,128,16,8,8,1><<<dim3(DM/128, MROWS/128), 256>>>(
        xT, embed_w, h, embed_b, MROWS, DM, 32, 32, 32, DM);

    for (int i = 0; i < NL; i++) {
        // rmsnorm -> fp16 (A operand for in_proj, lda=512)
        rmsnorm_kernel<<<MROWS, 128>>>(h, norm_w + (size_t)i*DM, a);

        // xz = rms @ in_proj^T  (fp16 tensor-core: M=16384, N=2048, K=512)
        mma_gemm<0><<<dim3(2*ED/256, MROWS/128), 512, MMA_SMEM>>>(
            a, wi + (size_t)i*2*ED*DM, xz, DM, DM, DM, 2*ED);

        // depthwise causal conv + silu
        conv_silu_kernel<<<(MROWS*ED/4)/256, 256>>>(
            xz, conv_w + (size_t)i*ED*4, conv_b + (size_t)i*ED, xc);

        // dbc = xc @ x_proj^T   (N=64, K=1024)
        sgemm_kernel<64,64,16,4,4,0><<<dim3(1, MROWS/64), 256>>>(
            xc, xp_w + (size_t)i*64*ED, dbc, nullptr, MROWS, 64, ED, ED, ED, 64);

        // delta = softplus(dbc[:, :32] @ dt_w^T + dt_b)
        sgemm_kernel<128,128,16,8,8,2><<<dim3(ED/128, MROWS/128), 256>>>(
            dbc, dt_w + (size_t)i*ED*DR, delta, dt_b + (size_t)i*ED,
            MROWS, ED, DR, 64, DR, ED);

        // chunked selective scan (pass B emits y as fp16, lda=1024)
        scan_passA<<<dim3(ED/128, CH, B_), 128>>>(
            delta, xc, dbc, A_log + (size_t)i*ED*NST, hloc, P);
        scan_combine<<<(B_*ED*NST)/256, 256>>>(hloc, P, Hin);
        scan_passB<<<dim3(ED/128, CH, B_), 128>>>(
            delta, xc, dbc, xz, A_log + (size_t)i*ED*NST, Dv + (size_t)i*ED, Hin, a);

        // h += y @ out_proj^T  (fp16 tensor-core: M=16384, N=512, K=1024, residual)
        mma_gemm<1><<<dim3(DM/256, MROWS/128), 512, MMA_SMEM>>>(
            a, wo + (size_t)i*DM*ED, h, ED, ED, ED, DM);
    }

    head_kernel<<<(B_*3072)/8, 256>>>(h, head_w, head_b, out);
}

// round 10
// speedup vs baseline: 3.0121x; 1.1373x over previous
#include <cuda_runtime.h>
#include <cuda_fp16.h>
#include <math.h>
#include <stdint.h>

// ---------------- problem constants ----------------
#define B_   16
#define L_   1024
#define DM   512      // d_model
#define ED   1024     // d_inner
#define NST  16       // d_state
#define NL   4
#define DR   32       // dt_rank
#define CH   8        // scan chunks
#define LC   128      // chunk length  (CH*LC == L_)
#define MROWS (B_*L_) // 16384

// ---------------- scratch (device globals; no allocation allowed) ----------------
__device__ __align__(16) float  g_h    [(size_t)MROWS*DM];
__device__ __align__(16) __half g_xz   [(size_t)MROWS*2*ED];   // fp16 now
__device__ __align__(16) __half g_xc   [(size_t)MROWS*ED];     // fp16 now
__device__ __align__(16) float  g_dbc  [(size_t)MROWS*64];
__device__ __align__(16) __half g_delta[(size_t)MROWS*ED];     // fp16 now
__device__ __align__(16) float  g_hloc [(size_t)B_*CH*ED*NST];
__device__ __align__(16) float  g_P    [(size_t)B_*CH*ED*NST];
__device__ __align__(16) float  g_Hin  [(size_t)B_*CH*ED*NST];
__device__ __align__(16) float  g_xT   [(size_t)MROWS*32];
// fp16 activations (A operand). lda=512 (rmsnorm out) then lda=1024 (y).
__device__ __align__(16) __half g_a  [(size_t)MROWS*ED];
// fp16 weights
__device__ __align__(16) __half g_wi [(size_t)NL*2*ED*DM];
__device__ __align__(16) __half g_wo [(size_t)NL*DM*ED];

__device__ __forceinline__ float sigmoidf_(float x) { return 1.f / (1.f + __expf(-x)); }

// ================= mma.sync fp16 helpers (non-arch-gated PTX) =================
__device__ __forceinline__ void ldm_x4(uint32_t (&r)[4], uint32_t a) {
    asm volatile("ldmatrix.sync.aligned.m8n8.x4.shared.b16 {%0,%1,%2,%3}, [%4];"
                 : "=r"(r[0]), "=r"(r[1]), "=r"(r[2]), "=r"(r[3]) : "r"(a));
}
__device__ __forceinline__ void mma_fp16(float (&d)[4], const uint32_t (&a)[4],
                                         uint32_t b0, uint32_t b1) {
    asm volatile(
        "mma.sync.aligned.m16n8k16.row.col.f32.f16.f16.f32 "
        "{%0,%1,%2,%3}, {%4,%5,%6,%7}, {%8,%9}, {%0,%1,%2,%3};"
        : "+f"(d[0]), "+f"(d[1]), "+f"(d[2]), "+f"(d[3])
        : "r"(a[0]), "r"(a[1]), "r"(a[2]), "r"(a[3]), "r"(b0), "r"(b1));
}
__device__ __forceinline__ void cp_async16(uint32_t sdst, const void* gsrc) {
    asm volatile("cp.async.cg.shared.global [%0], [%1], 16;" :: "r"(sdst), "l"(gsrc));
}
__device__ __forceinline__ void cp_commit() { asm volatile("cp.async.commit_group;"); }
__device__ __forceinline__ void cp_wait1()  { asm volatile("cp.async.wait_group 1;"); }
__device__ __forceinline__ void cp_wait0()  { asm volatile("cp.async.wait_group 0;"); }

// ================= fp16 tensor-core GEMM =================
// C(MxN) = A(MxK)*B(NxK)^T  (fp16 mma, fp32 accum)
// CTA tile 128(M)x256(N), 512 threads = 16 warps (4x4), warp tile 32x64.
// BK=32, 3-stage cp.async pipeline (proven scheme), one __syncthreads/chunk.
// MODE 0: store as fp16. MODE 1: fp32 C += result (residual).
#define ROWB    80
#define A_TEN   (128*ROWB)               // 10240
#define B_TEN   (256*ROWB)               // 20480
#define STG_SZ  (A_TEN + B_TEN)          // 30720
#define MMA_SMEM (3*STG_SZ)              // 92160

template<int MODE>
__global__ __launch_bounds__(512, 1)
void mma_gemm(const __half* __restrict__ A, const __half* __restrict__ B,
              void* __restrict__ C, int K, int lda, int ldb, int ldc) {
    extern __shared__ char smem[];
    const uint32_t sbase = (uint32_t)__cvta_generic_to_shared(smem);
    const int tid  = threadIdx.x;
    const int wid  = tid >> 5, lane = tid & 31;
    const int wm   = wid & 3;           // 0..3 : 32 rows each
    const int wn   = wid >> 2;          // 0..3 : 64 cols each
    const int bm   = blockIdx.y * 128;
    const int bn   = blockIdx.x * 256;
    const int NC   = K >> 5;

    float acc[2][8][4];
#pragma unroll
    for (int i = 0; i < 2; i++)
#pragma unroll
        for (int j = 0; j < 8; j++)
#pragma unroll
            for (int q = 0; q < 4; q++) acc[i][j][q] = 0.f;

    const int arow  = tid >> 2,          akc = tid & 3;
    const int brow0 = tid >> 2,          bkc0 = tid & 3;
    const int brow1 = (tid + 512) >> 2,  bkc1 = tid & 3;

    const __half* gA  = A + (size_t)(bm + arow)  * lda + akc  * 8;
    const __half* gB0 = B + (size_t)(bn + brow0) * ldb + bkc0 * 8;
    const __half* gB1 = B + (size_t)(bn + brow1) * ldb + bkc1 * 8;
    const uint32_t sA  = sbase + arow  * ROWB + akc  * 16;
    const uint32_t sB0 = sbase + brow0 * ROWB + bkc0 * 16;
    const uint32_t sB1 = sbase + brow1 * ROWB + bkc1 * 16;

#define LOAD_STAGE(c, s) do {                                          \
        int koff = (c) << 5;                                           \
        uint32_t st = (uint32_t)(s) * STG_SZ;                          \
        cp_async16(sA  + st,         gA  + koff);                      \
        cp_async16(sB0 + st + A_TEN, gB0 + koff);                      \
        cp_async16(sB1 + st + A_TEN, gB1 + koff);                      \
        cp_commit();                                                   \
    } while (0)

    LOAD_STAGE(0, 0);
    LOAD_STAGE(1, 1);

    const int aRow = (lane & 15);
    const int aKby = ((lane >> 4) << 4);
    const int bRow = (lane & 7) | ((lane >> 4) << 3);
    const int bKby = (((lane >> 3) & 1) << 4);

    int stg = 0;  // stage holding chunk c
    for (int c = 0; c < NC; c++) {
        if (c + 1 < NC) cp_wait1(); else cp_wait0();
        __syncthreads();
        int nstg = stg + 2; if (nstg >= 3) nstg -= 3;
        if (c + 2 < NC) LOAD_STAGE(c + 2, nstg);

        const uint32_t st  = sbase + (uint32_t)stg * STG_SZ;
        const uint32_t sA_ = st;
        const uint32_t sB_ = st + A_TEN;

        uint32_t af[2][2][4];
#pragma unroll
        for (int mf = 0; mf < 2; mf++) {
            uint32_t off = (uint32_t)(wm*32 + mf*16 + aRow) * ROWB + aKby;
            ldm_x4(af[0][mf], sA_ + off);
        }
#pragma unroll
        for (int k16 = 0; k16 < 2; k16++) {
            const int kb = k16 * 32;
            if (k16 == 0) {
#pragma unroll
                for (int mf = 0; mf < 2; mf++) {
                    uint32_t off = (uint32_t)(wm*32 + mf*16 + aRow) * ROWB + 32 + aKby;
                    ldm_x4(af[1][mf], sA_ + off);
                }
            }
#pragma unroll
            for (int nf2 = 0; nf2 < 4; nf2++) {
                uint32_t bf[4];
                uint32_t off = (uint32_t)(wn*64 + nf2*16 + bRow) * ROWB + kb + bKby;
                ldm_x4(bf, sB_ + off);
#pragma unroll
                for (int half = 0; half < 2; half++) {
#pragma unroll
                    for (int mf = 0; mf < 2; mf++) {
                        int nf = nf2*2 + half;
                        mma_fp16(acc[mf][nf], af[k16][mf], bf[half*2], bf[half*2+1]);
                    }
                }
            }
        }
        stg++; if (stg >= 3) stg = 0;
    }

    // epilogue
    const int erow = lane >> 2;
    const int ecol = (lane & 3) * 2;
#pragma unroll
    for (int mf = 0; mf < 2; mf++) {
#pragma unroll
        for (int nf = 0; nf < 8; nf++) {
            int row0 = bm + wm*32 + mf*16 + erow;
            int col  = bn + wn*64 + nf*8 + ecol;
            if (MODE == 0) {
                __half* Ch = (__half*)C;
                *reinterpret_cast<__half2*>(Ch + (size_t)row0 * ldc + col) =
                    __floats2half2_rn(acc[mf][nf][0], acc[mf][nf][1]);
                *reinterpret_cast<__half2*>(Ch + (size_t)(row0 + 8) * ldc + col) =
                    __floats2half2_rn(acc[mf][nf][2], acc[mf][nf][3]);
            } else {
                float* Cf = (float*)C;
                float* p0 = Cf + (size_t)row0 * ldc + col;
                float* p1 = Cf + (size_t)(row0 + 8) * ldc + col;
                float2 o0 = *reinterpret_cast<float2*>(p0);
                float2 o1 = *reinterpret_cast<float2*>(p1);
                o0.x += acc[mf][nf][0]; o0.y += acc[mf][nf][1];
                o1.x += acc[mf][nf][2]; o1.y += acc[mf][nf][3];
                *reinterpret_cast<float2*>(p0) = o0;
                *reinterpret_cast<float2*>(p1) = o1;
            }
        }
    }
#undef LOAD_STAGE
}

// ---------------- fp32 -> fp16 ----------------
__global__ void cvt_fp16_kernel(const float* __restrict__ x, __half* __restrict__ h, int n) {
    int i = blockIdx.x * 256 + threadIdx.x;
    if (i < n) h[i] = __float2half_rn(x[i]);
}

// ---------------- transpose x: (B,32,L) -> (B*L, 32) ----------------
__global__ void transpose_x_kernel(const float* __restrict__ x, float* __restrict__ xT) {
    __shared__ float t[32][33];
    int b  = blockIdx.y;
    int l0 = blockIdx.x * 32;
    int tx = threadIdx.x, ty = threadIdx.y;
    t[ty][tx] = x[((size_t)b*32 + ty)*L_ + l0 + tx];
    __syncthreads();
    xT[((size_t)b*L_ + l0 + ty)*32 + tx] = t[tx][ty];
}

// ---------------- generic fp32 SGEMM (embed): C = A*B^T + bias ----------------
template<int BM, int BN, int BK, int TM, int TN>
__global__ __launch_bounds__((BM/TM)*(BN/TN))
void sgemm_kernel(const float* __restrict__ A, const float* __restrict__ Bw,
                  float* __restrict__ C, const float* __restrict__ bias,
                  int M, int N, int K, int lda, int ldb, int ldc) {
    constexpr int THREADS = (BM/TM)*(BN/TN);
    __shared__ float As[BK][BM];
    __shared__ float Bs[BK][BN];
    const int tid = threadIdx.x;
    const int bm  = blockIdx.y * BM;
    const int bn  = blockIdx.x * BN;
    const int tx  = tid % (BN/TN);
    const int ty  = tid / (BN/TN);

    float acc[TM][TN];
#pragma unroll
    for (int i = 0; i < TM; i++)
#pragma unroll
        for (int j = 0; j < TN; j++) acc[i][j] = 0.f;

    constexpr int AVEC = BM*BK/4/THREADS;
    constexpr int BVEC = BN*BK/4/THREADS;

    for (int k0 = 0; k0 < K; k0 += BK) {
#pragma unroll
        for (int i = 0; i < AVEC; i++) {
            int idx = tid + i*THREADS;
            int row = idx / (BK/4);
            int kc  = (idx % (BK/4)) * 4;
            float4 v = *reinterpret_cast<const float4*>(&A[(size_t)(bm+row)*lda + k0 + kc]);
            As[kc+0][row] = v.x; As[kc+1][row] = v.y; As[kc+2][row] = v.z; As[kc+3][row] = v.w;
        }
#pragma unroll
        for (int i = 0; i < BVEC; i++) {
            int idx = tid + i*THREADS;
            int row = idx / (BK/4);
            int kc  = (idx % (BK/4)) * 4;
            float4 v = *reinterpret_cast<const float4*>(&Bw[(size_t)(bn+row)*ldb + k0 + kc]);
            Bs[kc+0][row] = v.x; Bs[kc+1][row] = v.y; Bs[kc+2][row] = v.z; Bs[kc+3][row] = v.w;
        }
        __syncthreads();
#pragma unroll
        for (int kk = 0; kk < BK; kk++) {
            float a[TM], b[TN];
#pragma unroll
            for (int i = 0; i < TM; i++) a[i] = As[kk][ty*TM + i];
#pragma unroll
            for (int j = 0; j < TN; j++) b[j] = Bs[kk][tx*TN + j];
#pragma unroll
            for (int i = 0; i < TM; i++)
#pragma unroll
                for (int j = 0; j < TN; j++)
                    acc[i][j] = fmaf(a[i], b[j], acc[i][j]);
        }
        __syncthreads();
    }

#pragma unroll
    for (int i = 0; i < TM; i++) {
        int row = bm + ty*TM + i;
#pragma unroll
        for (int j = 0; j < TN; j++) {
            int col = bn + tx*TN + j;
            C[(size_t)row*ldc + col] = acc[i][j] + bias[col];
        }
    }
}

// ---------------- dbc GEMM: A fp16, B fp32, C fp32.  64x64 tiles, BK=16 ----------------
__global__ __launch_bounds__(256)
void sgemm_hin_kernel(const __half* __restrict__ A, const float* __restrict__ Bw,
                      float* __restrict__ C, int K, int lda, int ldb, int ldc) {
    constexpr int BM = 64, BN = 64, BK = 16, TM = 4, TN = 4;
    __shared__ float As[BK][BM];
    __shared__ float Bs[BK][BN];
    const int tid = threadIdx.x;
    const int bm  = blockIdx.y * BM;
    const int bn  = blockIdx.x * BN;
    const int tx  = tid % (BN/TN);
    const int ty  = tid / (BN/TN);

    float acc[TM][TN];
#pragma unroll
    for (int i = 0; i < TM; i++)
#pragma unroll
        for (int j = 0; j < TN; j++) acc[i][j] = 0.f;

    for (int k0 = 0; k0 < K; k0 += BK) {
        {   // A fp16 loader: 64*16 = 1024 halves; 256 threads x 4 halves
            int row = tid / 4;
            int kc  = (tid % 4) * 4;
            uint2 u = *reinterpret_cast<const uint2*>(&A[(size_t)(bm+row)*lda + k0 + kc]);
            __half2 h01 = *reinterpret_cast<__half2*>(&u.x);
            __half2 h23 = *reinterpret_cast<__half2*>(&u.y);
            float2 f01 = __half22float2(h01);
            float2 f23 = __half22float2(h23);
            As[kc+0][row] = f01.x; As[kc+1][row] = f01.y;
            As[kc+2][row] = f23.x; As[kc+3][row] = f23.y;
        }
        {   // B fp32 loader
            int row = tid / 4;
            int kc  = (tid % 4) * 4;
            float4 v = *reinterpret_cast<const float4*>(&Bw[(size_t)(bn+row)*ldb + k0 + kc]);
            Bs[kc+0][row] = v.x; Bs[kc+1][row] = v.y; Bs[kc+2][row] = v.z; Bs[kc+3][row] = v.w;
        }
        __syncthreads();
#pragma unroll
        for (int kk = 0; kk < BK; kk++) {
            float a[TM], b[TN];
#pragma unroll
            for (int i = 0; i < TM; i++) a[i] = As[kk][ty*TM + i];
#pragma unroll
            for (int j = 0; j < TN; j++) b[j] = Bs[kk][tx*TN + j];
#pragma unroll
            for (int i = 0; i < TM; i++)
#pragma unroll
                for (int j = 0; j < TN; j++)
                    acc[i][j] = fmaf(a[i], b[j], acc[i][j]);
        }
        __syncthreads();
    }

#pragma unroll
    for (int i = 0; i < TM; i++) {
        int row = bm + ty*TM + i;
#pragma unroll
        for (int j = 0; j < TN; j++)
            C[(size_t)row*ldc + bn + tx*TN + j] = acc[i][j];
    }
}

// ---------------- delta GEMM: A fp32 (dbc, lda=64), softplus(+bias), fp16 out ----------------
__global__ __launch_bounds__(256)
void sgemm_dt_kernel(const float* __restrict__ A, const float* __restrict__ Bw,
                     __half* __restrict__ C, const float* __restrict__ bias,
                     int K, int lda, int ldb, int ldc) {
    constexpr int BM = 128, BN = 128, BK = 16, TM = 8, TN = 8;
    __shared__ float As[BK][BM];
    __shared__ float Bs[BK][BN];
    const int tid = threadIdx.x;
    const int bm  = blockIdx.y * BM;
    const int bn  = blockIdx.x * BN;
    const int tx  = tid % (BN/TN);
    const int ty  = tid / (BN/TN);

    float acc[TM][TN];
#pragma unroll
    for (int i = 0; i < TM; i++)
#pragma unroll
        for (int j = 0; j < TN; j++) acc[i][j] = 0.f;

    for (int k0 = 0; k0 < K; k0 += BK) {
#pragma unroll
        for (int i = 0; i < 2; i++) {
            int idx = tid + i*256;
            int row = idx / 4;
            int kc  = (idx % 4) * 4;
            float4 v = *reinterpret_cast<const float4*>(&A[(size_t)(bm+row)*lda + k0 + kc]);
            As[kc+0][row] = v.x; As[kc+1][row] = v.y; As[kc+2][row] = v.z; As[kc+3][row] = v.w;
        }
#pragma unroll
        for (int i = 0; i < 2; i++) {
            int idx = tid + i*256;
            int row = idx / 4;
            int kc  = (idx % 4) * 4;
            float4 v = *reinterpret_cast<const float4*>(&Bw[(size_t)(bn+row)*ldb + k0 + kc]);
            Bs[kc+0][row] = v.x; Bs[kc+1][row] = v.y; Bs[kc+2][row] = v.z; Bs[kc+3][row] = v.w;
        }
        __syncthreads();
#pragma unroll
        for (int kk = 0; kk < BK; kk++) {
            float a[TM], b[TN];
#pragma unroll
            for (int i = 0; i < TM; i++) a[i] = As[kk][ty*TM + i];
#pragma unroll
            for (int j = 0; j < TN; j++) b[j] = Bs[kk][tx*TN + j];
#pragma unroll
            for (int i = 0; i < TM; i++)
#pragma unroll
                for (int j = 0; j < TN; j++)
                    acc[i][j] = fmaf(a[i], b[j], acc[i][j]);
        }
        __syncthreads();
    }

#pragma unroll
    for (int i = 0; i < TM; i++) {
        int row = bm + ty*TM + i;
#pragma unroll
        for (int j = 0; j < TN; j += 2) {
            int col = bn + tx*TN + j;
            float v0 = acc[i][j]   + bias[col];
            float v1 = acc[i][j+1] + bias[col+1];
            v0 = (v0 > 20.f) ? v0 : log1pf(__expf(v0));
            v1 = (v1 > 20.f) ? v1 : log1pf(__expf(v1));
            *reinterpret_cast<__half2*>(C + (size_t)row*ldc + col) = __floats2half2_rn(v0, v1);
        }
    }
}

// ---------------- RMSNorm over d_model=512, fp16 output ----------------
__global__ void rmsnorm_kernel(const float* __restrict__ x, const float* __restrict__ w,
                               __half* __restrict__ oa) {
    int row = blockIdx.x;
    int tid = threadIdx.x;
    const float4* xr = reinterpret_cast<const float4*>(x + (size_t)row*DM);
    float4 v = xr[tid];
    float ss = v.x*v.x + v.y*v.y + v.z*v.z + v.w*v.w;
#pragma unroll
    for (int o = 16; o; o >>= 1) ss += __shfl_xor_sync(0xffffffffu, ss, o);
    __shared__ float sred[4];
    if ((tid & 31) == 0) sred[tid >> 5] = ss;
    __syncthreads();
    float tot = sred[0] + sred[1] + sred[2] + sred[3];
    float scale = rsqrtf(tot * (1.f/(float)DM) + 1e-5f);
    float4 wv = reinterpret_cast<const float4*>(w)[tid];
    float o0 = v.x*scale*wv.x, o1 = v.y*scale*wv.y, o2 = v.z*scale*wv.z, o3 = v.w*scale*wv.w;
    size_t off = (size_t)row*DM + tid*4;
    __half2* oa2 = reinterpret_cast<__half2*>(oa + off);
    oa2[0] = __floats2half2_rn(o0, o1);
    oa2[1] = __floats2half2_rn(o2, o3);
}

// ---------------- depthwise causal conv(4) + bias + silu (fp16 in/out, 4 ch/thread) ----------------
__device__ __forceinline__ float4 ld_half4(const __half* p) {
    uint2 u = *reinterpret_cast<const uint2*>(p);
    float2 f01 = __half22float2(*reinterpret_cast<__half2*>(&u.x));
    float2 f23 = __half22float2(*reinterpret_cast<__half2*>(&u.y));
    return make_float4(f01.x, f01.y, f23.x, f23.y);
}
__global__ void conv_silu_kernel(const __half* __restrict__ xz, const float* __restrict__ cw,
                                 const float* __restrict__ cb, __half* __restrict__ out) {
    size_t idx = (size_t)blockIdx.x * 256 + threadIdx.x;   // over B*L*ED/4
    int e4 = (idx & (ED/4 - 1)) * 4;
    size_t row = idx >> 8;
    int l = (int)(row & (L_-1));
    const __half* xr = xz + row * (size_t)(2*ED) + e4;
    float4 b4 = *reinterpret_cast<const float4*>(&cb[e4]);
    float4 w0 = *reinterpret_cast<const float4*>(&cw[(size_t)(e4+0)*4]);
    float4 w1 = *reinterpret_cast<const float4*>(&cw[(size_t)(e4+1)*4]);
    float4 w2 = *reinterpret_cast<const float4*>(&cw[(size_t)(e4+2)*4]);
    float4 w3 = *reinterpret_cast<const float4*>(&cw[(size_t)(e4+3)*4]);
    float4 acc = b4;
    float4 t0 = ld_half4(xr);
    acc.x = fmaf(w0.w, t0.x, acc.x); acc.y = fmaf(w1.w, t0.y, acc.y);
    acc.z = fmaf(w2.w, t0.z, acc.z); acc.w = fmaf(w3.w, t0.w, acc.w);
    if (l >= 1) {
        float4 t = ld_half4(xr - 2*ED);
        acc.x = fmaf(w0.z, t.x, acc.x); acc.y = fmaf(w1.z, t.y, acc.y);
        acc.z = fmaf(w2.z, t.z, acc.z); acc.w = fmaf(w3.z, t.w, acc.w);
    }
    if (l >= 2) {
        float4 t = ld_half4(xr - 4*ED);
        acc.x = fmaf(w0.y, t.x, acc.x); acc.y = fmaf(w1.y, t.y, acc.y);
        acc.z = fmaf(w2.y, t.z, acc.z); acc.w = fmaf(w3.y, t.w, acc.w);
    }
    if (l >= 3) {
        float4 t = ld_half4(xr - 6*ED);
        acc.x = fmaf(w0.x, t.x, acc.x); acc.y = fmaf(w1.x, t.y, acc.y);
        acc.z = fmaf(w2.x, t.z, acc.z); acc.w = fmaf(w3.x, t.w, acc.w);
    }
    float4 o;
    o.x = acc.x * sigmoidf_(acc.x); o.y = acc.y * sigmoidf_(acc.y);
    o.z = acc.z * sigmoidf_(acc.z); o.w = acc.w * sigmoidf_(acc.w);
    uint2 st;
    *reinterpret_cast<__half2*>(&st.x) = __floats2half2_rn(o.x, o.y);
    *reinterpret_cast<__half2*>(&st.y) = __floats2half2_rn(o.z, o.w);
    *reinterpret_cast<uint2*>(&out[row * (size_t)ED + e4]) = st;
}

// ---------------- scan pass A ----------------
__global__ void scan_passA(const __half* __restrict__ delta, const __half* __restrict__ u,
                           const float* __restrict__ dbc, const float* __restrict__ A_log,
                           float* __restrict__ hloc, float* __restrict__ Pout) {
    __shared__ float sB[LC][NST];
    int e = blockIdx.x * 128 + threadIdx.x;
    int c = blockIdx.y, b = blockIdx.z;
    for (int i = threadIdx.x; i < LC*NST; i += 128) {
        int row = i >> 4, col = i & 15;
        sB[row][col] = dbc[(size_t)(b*L_ + c*LC + row)*64 + 32 + col];
    }
    __syncthreads();

    float A[NST];
    bool fast = true;
#pragma unroll
    for (int n = 0; n < NST; n++) {
        float a = -__expf(A_log[(size_t)e*NST + n]);
        A[n] = a;
        fast = fast && (fabsf(a + (float)(n+1)) < 1e-4f * (float)(n+1));
    }

    float h[NST];
#pragma unroll
    for (int n = 0; n < NST; n++) h[n] = 0.f;
    float sd = 0.f;
    const __half* dp = delta + (size_t)(b*L_ + c*LC)*ED + e;
    const __half* up = u     + (size_t)(b*L_ + c*LC)*ED + e;

    if (fast) {
        for (int l = 0; l < LC; l++) {
            float dl = __half2float(dp[(size_t)l*ED]);
            float ul = __half2float(up[(size_t)l*ED]);
            float r  = __expf(-dl);
            float du = dl * ul;
            float p  = r;
            sd += dl;
#pragma unroll
            for (int n = 0; n < NST; n++) {
                h[n] = fmaf(p, h[n], du * sB[l][n]);
                p *= r;
            }
        }
    } else {
        for (int l = 0; l < LC; l++) {
            float dl = __half2float(dp[(size_t)l*ED]);
            float ul = __half2float(up[(size_t)l*ED]);
            float du = dl * ul;
            sd += dl;
#pragma unroll
            for (int n = 0; n < NST; n++) {
                float dA = __expf(dl * A[n]);
                h[n] = fmaf(dA, h[n], du * sB[l][n]);
            }
        }
    }
    size_t o = ((size_t)(b*CH + c)*ED + e)*NST;
#pragma unroll
    for (int n = 0; n < NST; n++) {
        hloc[o+n] = h[n];
        Pout[o+n] = __expf(A[n] * sd);
    }
}

// ---------------- scan combine ----------------
__global__ void scan_combine(const float* __restrict__ hloc, const float* __restrict__ P,
                             float* __restrict__ Hin) {
    int idx = blockIdx.x * 256 + threadIdx.x;
    int n = idx & 15;
    int e = (idx >> 4) & (ED-1);
    int b = idx >> 14;
    float H = 0.f;
#pragma unroll
    for (int c = 0; c < CH; c++) {
        size_t o = ((size_t)(b*CH + c)*ED + e)*NST + n;
        Hin[o] = H;
        H = fmaf(P[o], H, hloc[o]);
    }
}

// ---------------- scan pass B ----------------
__global__ void scan_passB(const __half* __restrict__ delta, const __half* __restrict__ u,
                           const float* __restrict__ dbc, const __half* __restrict__ xz,
                           const float* __restrict__ A_log, const float* __restrict__ Dv,
                           const float* __restrict__ Hin, __half* __restrict__ ya) {
    __shared__ float sB[LC][NST];
    __shared__ float sC[LC][NST];
    int e = blockIdx.x * 128 + threadIdx.x;
    int c = blockIdx.y, b = blockIdx.z;
    for (int i = threadIdx.x; i < LC*32; i += 128) {
        int row = i >> 5, col = i & 31;
        float v = dbc[(size_t)(b*L_ + c*LC + row)*64 + 32 + col];
        if (col < 16) sB[row][col] = v; else sC[row][col-16] = v;
    }
    __syncthreads();

    float A[NST];
    bool fast = true;
#pragma unroll
    for (int n = 0; n < NST; n++) {
        float a = -__expf(A_log[(size_t)e*NST + n]);
        A[n] = a;
        fast = fast && (fabsf(a + (float)(n+1)) < 1e-4f * (float)(n+1));
    }

    float h[NST];
    size_t oH = ((size_t)(b*CH + c)*ED + e)*NST;
#pragma unroll
    for (int n4 = 0; n4 < NST; n4 += 4) {
        float4 v = *reinterpret_cast<const float4*>(&Hin[oH + n4]);
        h[n4+0] = v.x; h[n4+1] = v.y; h[n4+2] = v.z; h[n4+3] = v.w;
    }
    float Dp = Dv[e];

    const __half* dp = delta + (size_t)(b*L_ + c*LC)*ED + e;
    const __half* up = u     + (size_t)(b*L_ + c*LC)*ED + e;
    const __half* zp = xz    + (size_t)(b*L_ + c*LC)*(2*ED) + ED + e;
    size_t yo = (size_t)(b*L_ + c*LC)*ED + e;

    if (fast) {
        for (int l = 0; l < LC; l++) {
            float dl = __half2float(dp[(size_t)l*ED]);
            float ul = __half2float(up[(size_t)l*ED]);
            float r  = __expf(-dl);
            float du = dl * ul;
            float p  = r;
            float y  = 0.f;
#pragma unroll
            for (int n = 0; n < NST; n++) {
                h[n] = fmaf(p, h[n], du * sB[l][n]);
                y = fmaf(h[n], sC[l][n], y);
                p *= r;
            }
            float zl = __half2float(zp[(size_t)l*(2*ED)]);
            float yt = fmaf(Dp, ul, y) * zl * sigmoidf_(zl);
            ya[yo + (size_t)l*ED] = __float2half_rn(yt);
        }
    } else {
        for (int l = 0; l < LC; l++) {
            float dl = __half2float(dp[(size_t)l*ED]);
            float ul = __half2float(up[(size_t)l*ED]);
            float du = dl * ul;
            float y  = 0.f;
#pragma unroll
            for (int n = 0; n < NST; n++) {
                float dA = __expf(dl * A[n]);
                h[n] = fmaf(dA, h[n], du * sB[l][n]);
                y = fmaf(h[n], sC[l][n], y);
            }
            float zl = __half2float(zp[(size_t)l*(2*ED)]);
            float yt = fmaf(Dp, ul, y) * zl * sigmoidf_(zl);
            ya[yo + (size_t)l*ED] = __float2half_rn(yt);
        }
    }
}

// ---------------- head ----------------
__global__ void head_kernel(const float* __restrict__ h, const float* __restrict__ hw,
                            const float* __restrict__ hb, float* __restrict__ out) {
    int w    = blockIdx.x * 8 + (threadIdx.x >> 5);
    int lane = threadIdx.x & 31;
    int n = w % 3072;
    int b = w / 3072;
    const float4* hr4 = reinterpret_cast<const float4*>(h + ((size_t)b*L_ + (L_-1))*DM);
    const float4* wr4 = reinterpret_cast<const float4*>(hw + (size_t)n*DM);
    float s = 0.f;
#pragma unroll
    for (int i = 0; i < 4; i++) {
        int k4 = lane + i*32;
        float4 a = hr4[k4];
        float4 ww = wr4[k4];
        s += a.x*ww.x + a.y*ww.y + a.z*ww.z + a.w*ww.w;
    }
#pragma unroll
    for (int o = 16; o; o >>= 1) s += __shfl_xor_sync(0xffffffffu, s, o);
    if (lane == 0) {
        int c = n & 31, t = n >> 5;
        out[(size_t)b*3072 + (size_t)c*96 + t] = s + hb[n];
    }
}

// ---------------- launch ----------------
extern "C" void kernel_launch(void* const* d_in, const int* in_sizes, int n_in,
                              void* d_out, int out_size) {
    const float* x        = (const float*)d_in[0];
    const float* embed_w  = (const float*)d_in[1];
    const float* embed_b  = (const float*)d_in[2];
    const float* norm_w   = (const float*)d_in[3];
    const float* in_w     = (const float*)d_in[4];
    const float* conv_w   = (const float*)d_in[5];
    const float* conv_b   = (const float*)d_in[6];
    const float* xp_w     = (const float*)d_in[7];
    const float* dt_w     = (const float*)d_in[8];
    const float* dt_b     = (const float*)d_in[9];
    const float* A_log    = (const float*)d_in[10];
    const float* Dv       = (const float*)d_in[11];
    const float* out_w    = (const float*)d_in[12];
    const float* head_w   = (const float*)d_in[13];
    const float* head_b   = (const float*)d_in[14];
    float* out = (float*)d_out;

    float *h, *dbc, *hloc, *P, *Hin, *xT;
    __half *xz, *xc, *delta, *a, *wi, *wo;
    cudaGetSymbolAddress((void**)&h,     g_h);
    cudaGetSymbolAddress((void**)&xz,    g_xz);
    cudaGetSymbolAddress((void**)&xc,    g_xc);
    cudaGetSymbolAddress((void**)&dbc,   g_dbc);
    cudaGetSymbolAddress((void**)&delta, g_delta);
    cudaGetSymbolAddress((void**)&hloc,  g_hloc);
    cudaGetSymbolAddress((void**)&P,     g_P);
    cudaGetSymbolAddress((void**)&Hin,   g_Hin);
    cudaGetSymbolAddress((void**)&xT,    g_xT);
    cudaGetSymbolAddress((void**)&a,     g_a);
    cudaGetSymbolAddress((void**)&wi,    g_wi);
    cudaGetSymbolAddress((void**)&wo,    g_wo);

    cudaFuncSetAttribute(mma_gemm<0>, cudaFuncAttributeMaxDynamicSharedMemorySize, MMA_SMEM);
    cudaFuncSetAttribute(mma_gemm<1>, cudaFuncAttributeMaxDynamicSharedMemorySize, MMA_SMEM);

    // weight conversion (all layers, once per launch)
    cvt_fp16_kernel<<<(NL*2*ED*DM + 255)/256, 256>>>(in_w,  wi, NL*2*ED*DM);
    cvt_fp16_kernel<<<(NL*DM*ED   + 255)/256, 256>>>(out_w, wo, NL*DM*ED);

    // embed: h = x^T @ embed_w^T + embed_b
    transpose_x_kernel<<<dim3(L_/32, B_), dim3(32, 32)>>>(x, xT);
    sgemm_kernel<128,128,16,8,8><<<dim3(DM/128, MROWS/128), 256>>>(
        xT, embed_w, h, embed_b, MROWS, DM, 32, 32, 32, DM);

    for (int i = 0; i < NL; i++) {
        // rmsnorm -> fp16 (A operand for in_proj, lda=512)
        rmsnorm_kernel<<<MROWS, 128>>>(h, norm_w + (size_t)i*DM, a);

        // xz = rms @ in_proj^T  (fp16 tensor-core; fp16 out)
        mma_gemm<0><<<dim3(2*ED/256, MROWS/128), 512, MMA_SMEM>>>(
            a, wi + (size_t)i*2*ED*DM, xz, DM, DM, DM, 2*ED);

        // depthwise causal conv + silu (fp16 in/out)
        conv_silu_kernel<<<(MROWS*ED/4)/256, 256>>>(
            xz, conv_w + (size_t)i*ED*4, conv_b + (size_t)i*ED, xc);

        // dbc = xc @ x_proj^T  (fp16 A, fp32 B/C; N=64, K=1024)
        sgemm_hin_kernel<<<dim3(1, MROWS/64), 256>>>(
            xc, xp_w + (size_t)i*64*ED, dbc, ED, ED, ED, 64);

        // delta = softplus(dbc[:, :32] @ dt_w^T + dt_b)  -> fp16
        sgemm_dt_kernel<<<dim3(ED/128, MROWS/128), 256>>>(
            dbc, dt_w + (size_t)i*ED*DR, delta, dt_b + (size_t)i*ED, DR, 64, DR, ED);

        // chunked selective scan (fp16 delta/u/z; pass B emits y fp16, lda=1024)
        scan_passA<<<dim3(ED/128, CH, B_), 128>>>(
            delta, xc, dbc, A_log + (size_t)i*ED*NST, hloc, P);
        scan_combine<<<(B_*ED*NST)/256, 256>>>(hloc, P, Hin);
        scan_passB<<<dim3(ED/128, CH, B_), 128>>>(
            delta, xc, dbc, xz, A_log + (size_t)i*ED*NST, Dv + (size_t)i*ED, Hin, a);

        // h += y @ out_proj^T  (fp16 tensor-core, fp32 residual out)
        mma_gemm<1><<<dim3(DM/256, MROWS/128), 512, MMA_SMEM>>>(
            a, wo + (size_t)i*DM*ED, h, ED, ED, ED, DM);
    }

    head_kernel<<<(B_*3072)/8, 256>>>(h, head_w, head_b, out);
}

// round 11
// speedup vs baseline: 3.5518x; 1.1792x over previous
#include <cuda_runtime.h>
#include <cuda_fp16.h>
#include <math.h>
#include <stdint.h>

// ---------------- problem constants ----------------
#define B_   16
#define L_   1024
#define DM   512      // d_model
#define ED   1024     // d_inner
#define NST  16       // d_state
#define NL   4
#define DR   32       // dt_rank
#define CH   8        // scan chunks
#define LC   128      // chunk length  (CH*LC == L_)
#define MROWS (B_*L_) // 16384

// ---------------- scratch (device globals; no allocation allowed) ----------------
__device__ __align__(16) float  g_h    [(size_t)MROWS*DM];
__device__ __align__(16) __half g_xz   [(size_t)MROWS*2*ED];
__device__ __align__(16) __half g_xc   [(size_t)MROWS*ED];
__device__ __align__(16) __half g_dbc  [(size_t)MROWS*64];     // fp16 now
__device__ __align__(16) __half g_delta[(size_t)MROWS*ED];
__device__ __align__(16) float  g_hloc [(size_t)B_*CH*ED*NST];
__device__ __align__(16) float  g_P    [(size_t)B_*CH*ED*NST];
__device__ __align__(16) float  g_Hin  [(size_t)B_*CH*ED*NST];
__device__ __align__(16) float  g_xT   [(size_t)MROWS*32];
// fp16 activations (A operand). lda=512 (rmsnorm out) then lda=1024 (y).
__device__ __align__(16) __half g_a  [(size_t)MROWS*ED];
// fp16 weights
__device__ __align__(16) __half g_wi [(size_t)NL*2*ED*DM];
__device__ __align__(16) __half g_wo [(size_t)NL*DM*ED];
__device__ __align__(16) __half g_wx [(size_t)NL*64*ED];
__device__ __align__(16) __half g_wd [(size_t)NL*ED*DR];

__device__ __forceinline__ float sigmoidf_(float x) { return 1.f / (1.f + __expf(-x)); }

// ================= mma.sync fp16 helpers (non-arch-gated PTX) =================
__device__ __forceinline__ void ldm_x4(uint32_t (&r)[4], uint32_t a) {
    asm volatile("ldmatrix.sync.aligned.m8n8.x4.shared.b16 {%0,%1,%2,%3}, [%4];"
                 : "=r"(r[0]), "=r"(r[1]), "=r"(r[2]), "=r"(r[3]) : "r"(a));
}
__device__ __forceinline__ void mma_fp16(float (&d)[4], const uint32_t (&a)[4],
                                         uint32_t b0, uint32_t b1) {
    asm volatile(
        "mma.sync.aligned.m16n8k16.row.col.f32.f16.f16.f32 "
        "{%0,%1,%2,%3}, {%4,%5,%6,%7}, {%8,%9}, {%0,%1,%2,%3};"
        : "+f"(d[0]), "+f"(d[1]), "+f"(d[2]), "+f"(d[3])
        : "r"(a[0]), "r"(a[1]), "r"(a[2]), "r"(a[3]), "r"(b0), "r"(b1));
}
__device__ __forceinline__ void cp_async16(uint32_t sdst, const void* gsrc) {
    asm volatile("cp.async.cg.shared.global [%0], [%1], 16;" :: "r"(sdst), "l"(gsrc));
}
__device__ __forceinline__ void cp_commit() { asm volatile("cp.async.commit_group;"); }
__device__ __forceinline__ void cp_wait1()  { asm volatile("cp.async.wait_group 1;"); }
__device__ __forceinline__ void cp_wait0()  { asm volatile("cp.async.wait_group 0;"); }

__device__ __forceinline__ float softplusf_(float v) {
    return (v > 20.f) ? v : log1pf(__expf(v));
}

// ================= fp16 tensor-core GEMM (wide tiles) =================
// C(MxN) = A(MxK)*B(NxK)^T  (fp16 mma, fp32 accum)
// CTA tile 128(M)x256(N), 512 threads = 16 warps (4x4), warp tile 32x64.
// BK=32, 3-stage cp.async pipeline, one __syncthreads/chunk.
// MODE 0: store fp16. MODE 1: fp32 C += result. MODE 2: softplus(+bias) fp16.
#define ROWB    80
#define A_TEN   (128*ROWB)               // 10240
#define B_TEN   (256*ROWB)               // 20480
#define STG_SZ  (A_TEN + B_TEN)          // 30720
#define MMA_SMEM (3*STG_SZ)              // 92160

template<int MODE>
__global__ __launch_bounds__(512, 1)
void mma_gemm(const __half* __restrict__ A, const __half* __restrict__ B,
              void* __restrict__ C, const float* __restrict__ bias,
              int K, int lda, int ldb, int ldc) {
    extern __shared__ char smem[];
    const uint32_t sbase = (uint32_t)__cvta_generic_to_shared(smem);
    const int tid  = threadIdx.x;
    const int wid  = tid >> 5, lane = tid & 31;
    const int wm   = wid & 3;
    const int wn   = wid >> 2;
    const int bm   = blockIdx.y * 128;
    const int bn   = blockIdx.x * 256;
    const int NC   = K >> 5;

    float acc[2][8][4];
#pragma unroll
    for (int i = 0; i < 2; i++)
#pragma unroll
        for (int j = 0; j < 8; j++)
#pragma unroll
            for (int q = 0; q < 4; q++) acc[i][j][q] = 0.f;

    const int arow  = tid >> 2,          akc = tid & 3;
    const int brow0 = tid >> 2,          bkc0 = tid & 3;
    const int brow1 = (tid + 512) >> 2,  bkc1 = tid & 3;

    const __half* gA  = A + (size_t)(bm + arow)  * lda + akc  * 8;
    const __half* gB0 = B + (size_t)(bn + brow0) * ldb + bkc0 * 8;
    const __half* gB1 = B + (size_t)(bn + brow1) * ldb + bkc1 * 8;
    const uint32_t sA  = sbase + arow  * ROWB + akc  * 16;
    const uint32_t sB0 = sbase + brow0 * ROWB + bkc0 * 16;
    const uint32_t sB1 = sbase + brow1 * ROWB + bkc1 * 16;

#define LOAD_STAGE(c, s) do {                                          \
        int koff = (c) << 5;                                           \
        uint32_t st = (uint32_t)(s) * STG_SZ;                          \
        cp_async16(sA  + st,         gA  + koff);                      \
        cp_async16(sB0 + st + A_TEN, gB0 + koff);                      \
        cp_async16(sB1 + st + A_TEN, gB1 + koff);                      \
        cp_commit();                                                   \
    } while (0)

    LOAD_STAGE(0, 0);
    if (NC > 1) LOAD_STAGE(1, 1);

    const int aRow = (lane & 15);
    const int aKby = ((lane >> 4) << 4);
    const int bRow = (lane & 7) | ((lane >> 4) << 3);
    const int bKby = (((lane >> 3) & 1) << 4);

    int stg = 0;
    for (int c = 0; c < NC; c++) {
        if (c + 1 < NC) cp_wait1(); else cp_wait0();
        __syncthreads();
        int nstg = stg + 2; if (nstg >= 3) nstg -= 3;
        if (c + 2 < NC) LOAD_STAGE(c + 2, nstg);

        const uint32_t st  = sbase + (uint32_t)stg * STG_SZ;
        const uint32_t sA_ = st;
        const uint32_t sB_ = st + A_TEN;

        uint32_t af[2][2][4];
#pragma unroll
        for (int mf = 0; mf < 2; mf++) {
            uint32_t off = (uint32_t)(wm*32 + mf*16 + aRow) * ROWB + aKby;
            ldm_x4(af[0][mf], sA_ + off);
        }
#pragma unroll
        for (int k16 = 0; k16 < 2; k16++) {
            const int kb = k16 * 32;
            if (k16 == 0) {
#pragma unroll
                for (int mf = 0; mf < 2; mf++) {
                    uint32_t off = (uint32_t)(wm*32 + mf*16 + aRow) * ROWB + 32 + aKby;
                    ldm_x4(af[1][mf], sA_ + off);
                }
            }
#pragma unroll
            for (int nf2 = 0; nf2 < 4; nf2++) {
                uint32_t bf[4];
                uint32_t off = (uint32_t)(wn*64 + nf2*16 + bRow) * ROWB + kb + bKby;
                ldm_x4(bf, sB_ + off);
#pragma unroll
                for (int half = 0; half < 2; half++) {
#pragma unroll
                    for (int mf = 0; mf < 2; mf++) {
                        int nf = nf2*2 + half;
                        mma_fp16(acc[mf][nf], af[k16][mf], bf[half*2], bf[half*2+1]);
                    }
                }
            }
        }
        stg++; if (stg >= 3) stg = 0;
    }

    // epilogue
    const int erow = lane >> 2;
    const int ecol = (lane & 3) * 2;
#pragma unroll
    for (int mf = 0; mf < 2; mf++) {
#pragma unroll
        for (int nf = 0; nf < 8; nf++) {
            int row0 = bm + wm*32 + mf*16 + erow;
            int col  = bn + wn*64 + nf*8 + ecol;
            if (MODE == 0) {
                __half* Ch = (__half*)C;
                *reinterpret_cast<__half2*>(Ch + (size_t)row0 * ldc + col) =
                    __floats2half2_rn(acc[mf][nf][0], acc[mf][nf][1]);
                *reinterpret_cast<__half2*>(Ch + (size_t)(row0 + 8) * ldc + col) =
                    __floats2half2_rn(acc[mf][nf][2], acc[mf][nf][3]);
            } else if (MODE == 1) {
                float* Cf = (float*)C;
                float* p0 = Cf + (size_t)row0 * ldc + col;
                float* p1 = Cf + (size_t)(row0 + 8) * ldc + col;
                float2 o0 = *reinterpret_cast<float2*>(p0);
                float2 o1 = *reinterpret_cast<float2*>(p1);
                o0.x += acc[mf][nf][0]; o0.y += acc[mf][nf][1];
                o1.x += acc[mf][nf][2]; o1.y += acc[mf][nf][3];
                *reinterpret_cast<float2*>(p0) = o0;
                *reinterpret_cast<float2*>(p1) = o1;
            } else {
                __half* Ch = (__half*)C;
                float b0 = bias[col], b1 = bias[col+1];
                *reinterpret_cast<__half2*>(Ch + (size_t)row0 * ldc + col) =
                    __floats2half2_rn(softplusf_(acc[mf][nf][0] + b0),
                                      softplusf_(acc[mf][nf][1] + b1));
                *reinterpret_cast<__half2*>(Ch + (size_t)(row0 + 8) * ldc + col) =
                    __floats2half2_rn(softplusf_(acc[mf][nf][2] + b0),
                                      softplusf_(acc[mf][nf][3] + b1));
            }
        }
    }
#undef LOAD_STAGE
}

// ================= fp16 tensor-core GEMM, narrow N=64 (dbc) =================
// CTA tile 128(M)x64(N), 256 threads = 8 warps (4m x 2n), warp tile 32x32.
// BK=32, 3-stage pipeline. C stored fp16 (ldc=64).
#define B64_TEN (64*ROWB)                 // 5120
#define STG64   (A_TEN + B64_TEN)         // 15360
#define N64_SMEM (3*STG64)                // 46080

__global__ __launch_bounds__(256, 1)
void tc_gemm_n64(const __half* __restrict__ A, const __half* __restrict__ B,
                 __half* __restrict__ C, int K, int lda, int ldb, int ldc) {
    extern __shared__ char smem[];
    const uint32_t sbase = (uint32_t)__cvta_generic_to_shared(smem);
    const int tid  = threadIdx.x;
    const int wid  = tid >> 5, lane = tid & 31;
    const int wm   = wid & 3;           // 4 x 32 rows
    const int wn   = wid >> 2;          // 2 x 32 cols
    const int bm   = blockIdx.y * 128;
    const int NC   = K >> 5;

    float acc[2][4][4];
#pragma unroll
    for (int i = 0; i < 2; i++)
#pragma unroll
        for (int j = 0; j < 4; j++)
#pragma unroll
            for (int q = 0; q < 4; q++) acc[i][j][q] = 0.f;

    const int arow0 = tid >> 2,        akc = tid & 3;
    const int arow1 = (tid + 256) >> 2;
    const int brow  = tid >> 2,        bkc = tid & 3;   // 0..63

    const __half* gA0 = A + (size_t)(bm + arow0) * lda + akc * 8;
    const __half* gA1 = A + (size_t)(bm + arow1) * lda + akc * 8;
    const __half* gB  = B + (size_t)brow * ldb + bkc * 8;
    const uint32_t sA0 = sbase + arow0 * ROWB + akc * 16;
    const uint32_t sA1 = sbase + arow1 * ROWB + akc * 16;
    const uint32_t sBr = sbase + brow  * ROWB + bkc * 16;

#define LOAD_STG64(c, s) do {                                          \
        int koff = (c) << 5;                                           \
        uint32_t st = (uint32_t)(s) * STG64;                           \
        cp_async16(sA0 + st,         gA0 + koff);                      \
        cp_async16(sA1 + st,         gA1 + koff);                      \
        cp_async16(sBr + st + A_TEN, gB  + koff);                      \
        cp_commit();                                                   \
    } while (0)

    LOAD_STG64(0, 0);
    if (NC > 1) LOAD_STG64(1, 1);

    const int aRow = (lane & 15);
    const int aKby = ((lane >> 4) << 4);
    const int bRow = (lane & 7) | ((lane >> 4) << 3);
    const int bKby = (((lane >> 3) & 1) << 4);

    int stg = 0;
    for (int c = 0; c < NC; c++) {
        if (c + 1 < NC) cp_wait1(); else cp_wait0();
        __syncthreads();
        int nstg = stg + 2; if (nstg >= 3) nstg -= 3;
        if (c + 2 < NC) LOAD_STG64(c + 2, nstg);

        const uint32_t st  = sbase + (uint32_t)stg * STG64;
        const uint32_t sA_ = st;
        const uint32_t sB_ = st + A_TEN;

#pragma unroll
        for (int k16 = 0; k16 < 2; k16++) {
            const int kb = k16 * 32;
            uint32_t af[2][4];
#pragma unroll
            for (int mf = 0; mf < 2; mf++) {
                uint32_t off = (uint32_t)(wm*32 + mf*16 + aRow) * ROWB + kb + aKby;
                ldm_x4(af[mf], sA_ + off);
            }
#pragma unroll
            for (int nf2 = 0; nf2 < 2; nf2++) {
                uint32_t bf[4];
                uint32_t off = (uint32_t)(wn*32 + nf2*16 + bRow) * ROWB + kb + bKby;
                ldm_x4(bf, sB_ + off);
#pragma unroll
                for (int half = 0; half < 2; half++) {
#pragma unroll
                    for (int mf = 0; mf < 2; mf++) {
                        int nf = nf2*2 + half;
                        mma_fp16(acc[mf][nf], af[mf], bf[half*2], bf[half*2+1]);
                    }
                }
            }
        }
        stg++; if (stg >= 3) stg = 0;
    }

    const int erow = lane >> 2;
    const int ecol = (lane & 3) * 2;
#pragma unroll
    for (int mf = 0; mf < 2; mf++) {
#pragma unroll
        for (int nf = 0; nf < 4; nf++) {
            int row0 = bm + wm*32 + mf*16 + erow;
            int col  = wn*32 + nf*8 + ecol;
            *reinterpret_cast<__half2*>(C + (size_t)row0 * ldc + col) =
                __floats2half2_rn(acc[mf][nf][0], acc[mf][nf][1]);
            *reinterpret_cast<__half2*>(C + (size_t)(row0 + 8) * ldc + col) =
                __floats2half2_rn(acc[mf][nf][2], acc[mf][nf][3]);
        }
    }
#undef LOAD_STG64
}

// ---------------- fp32 -> fp16 ----------------
__global__ void cvt_fp16_kernel(const float* __restrict__ x, __half* __restrict__ h, int n) {
    int i = blockIdx.x * 256 + threadIdx.x;
    if (i < n) h[i] = __float2half_rn(x[i]);
}

// ---------------- transpose x: (B,32,L) -> (B*L, 32) ----------------
__global__ void transpose_x_kernel(const float* __restrict__ x, float* __restrict__ xT) {
    __shared__ float t[32][33];
    int b  = blockIdx.y;
    int l0 = blockIdx.x * 32;
    int tx = threadIdx.x, ty = threadIdx.y;
    t[ty][tx] = x[((size_t)b*32 + ty)*L_ + l0 + tx];
    __syncthreads();
    xT[((size_t)b*L_ + l0 + ty)*32 + tx] = t[tx][ty];
}

// ---------------- fp32 SGEMM (embed only): C = A*B^T + bias ----------------
template<int BM, int BN, int BK, int TM, int TN>
__global__ __launch_bounds__((BM/TM)*(BN/TN))
void sgemm_kernel(const float* __restrict__ A, const float* __restrict__ Bw,
                  float* __restrict__ C, const float* __restrict__ bias,
                  int M, int N, int K, int lda, int ldb, int ldc) {
    constexpr int THREADS = (BM/TM)*(BN/TN);
    __shared__ float As[BK][BM];
    __shared__ float Bs[BK][BN];
    const int tid = threadIdx.x;
    const int bm  = blockIdx.y * BM;
    const int bn  = blockIdx.x * BN;
    const int tx  = tid % (BN/TN);
    const int ty  = tid / (BN/TN);

    float acc[TM][TN];
#pragma unroll
    for (int i = 0; i < TM; i++)
#pragma unroll
        for (int j = 0; j < TN; j++) acc[i][j] = 0.f;

    constexpr int AVEC = BM*BK/4/THREADS;
    constexpr int BVEC = BN*BK/4/THREADS;

    for (int k0 = 0; k0 < K; k0 += BK) {
#pragma unroll
        for (int i = 0; i < AVEC; i++) {
            int idx = tid + i*THREADS;
            int row = idx / (BK/4);
            int kc  = (idx % (BK/4)) * 4;
            float4 v = *reinterpret_cast<const float4*>(&A[(size_t)(bm+row)*lda + k0 + kc]);
            As[kc+0][row] = v.x; As[kc+1][row] = v.y; As[kc+2][row] = v.z; As[kc+3][row] = v.w;
        }
#pragma unroll
        for (int i = 0; i < BVEC; i++) {
            int idx = tid + i*THREADS;
            int row = idx / (BK/4);
            int kc  = (idx % (BK/4)) * 4;
            float4 v = *reinterpret_cast<const float4*>(&Bw[(size_t)(bn+row)*ldb + k0 + kc]);
            Bs[kc+0][row] = v.x; Bs[kc+1][row] = v.y; Bs[kc+2][row] = v.z; Bs[kc+3][row] = v.w;
        }
        __syncthreads();
#pragma unroll
        for (int kk = 0; kk < BK; kk++) {
            float a[TM], b[TN];
#pragma unroll
            for (int i = 0; i < TM; i++) a[i] = As[kk][ty*TM + i];
#pragma unroll
            for (int j = 0; j < TN; j++) b[j] = Bs[kk][tx*TN + j];
#pragma unroll
            for (int i = 0; i < TM; i++)
#pragma unroll
                for (int j = 0; j < TN; j++)
                    acc[i][j] = fmaf(a[i], b[j], acc[i][j]);
        }
        __syncthreads();
    }

#pragma unroll
    for (int i = 0; i < TM; i++) {
        int row = bm + ty*TM + i;
#pragma unroll
        for (int j = 0; j < TN; j++) {
            int col = bn + tx*TN + j;
            C[(size_t)row*ldc + col] = acc[i][j] + bias[col];
        }
    }
}

// ---------------- RMSNorm over d_model=512, fp16 output ----------------
__global__ void rmsnorm_kernel(const float* __restrict__ x, const float* __restrict__ w,
                               __half* __restrict__ oa) {
    int row = blockIdx.x;
    int tid = threadIdx.x;
    const float4* xr = reinterpret_cast<const float4*>(x + (size_t)row*DM);
    float4 v = xr[tid];
    float ss = v.x*v.x + v.y*v.y + v.z*v.z + v.w*v.w;
#pragma unroll
    for (int o = 16; o; o >>= 1) ss += __shfl_xor_sync(0xffffffffu, ss, o);
    __shared__ float sred[4];
    if ((tid & 31) == 0) sred[tid >> 5] = ss;
    __syncthreads();
    float tot = sred[0] + sred[1] + sred[2] + sred[3];
    float scale = rsqrtf(tot * (1.f/(float)DM) + 1e-5f);
    float4 wv = reinterpret_cast<const float4*>(w)[tid];
    float o0 = v.x*scale*wv.x, o1 = v.y*scale*wv.y, o2 = v.z*scale*wv.z, o3 = v.w*scale*wv.w;
    size_t off = (size_t)row*DM + tid*4;
    __half2* oa2 = reinterpret_cast<__half2*>(oa + off);
    oa2[0] = __floats2half2_rn(o0, o1);
    oa2[1] = __floats2half2_rn(o2, o3);
}

// ---------------- depthwise causal conv(4) + bias + silu (fp16 in/out) ----------------
__device__ __forceinline__ float4 ld_half4(const __half* p) {
    uint2 u = *reinterpret_cast<const uint2*>(p);
    float2 f01 = __half22float2(*reinterpret_cast<__half2*>(&u.x));
    float2 f23 = __half22float2(*reinterpret_cast<__half2*>(&u.y));
    return make_float4(f01.x, f01.y, f23.x, f23.y);
}
__global__ void conv_silu_kernel(const __half* __restrict__ xz, const float* __restrict__ cw,
                                 const float* __restrict__ cb, __half* __restrict__ out) {
    size_t idx = (size_t)blockIdx.x * 256 + threadIdx.x;   // over B*L*ED/4
    int e4 = (idx & (ED/4 - 1)) * 4;
    size_t row = idx >> 8;
    int l = (int)(row & (L_-1));
    const __half* xr = xz + row * (size_t)(2*ED) + e4;
    float4 b4 = *reinterpret_cast<const float4*>(&cb[e4]);
    float4 w0 = *reinterpret_cast<const float4*>(&cw[(size_t)(e4+0)*4]);
    float4 w1 = *reinterpret_cast<const float4*>(&cw[(size_t)(e4+1)*4]);
    float4 w2 = *reinterpret_cast<const float4*>(&cw[(size_t)(e4+2)*4]);
    float4 w3 = *reinterpret_cast<const float4*>(&cw[(size_t)(e4+3)*4]);
    float4 acc = b4;
    float4 t0 = ld_half4(xr);
    acc.x = fmaf(w0.w, t0.x, acc.x); acc.y = fmaf(w1.w, t0.y, acc.y);
    acc.z = fmaf(w2.w, t0.z, acc.z); acc.w = fmaf(w3.w, t0.w, acc.w);
    if (l >= 1) {
        float4 t = ld_half4(xr - 2*ED);
        acc.x = fmaf(w0.z, t.x, acc.x); acc.y = fmaf(w1.z, t.y, acc.y);
        acc.z = fmaf(w2.z, t.z, acc.z); acc.w = fmaf(w3.z, t.w, acc.w);
    }
    if (l >= 2) {
        float4 t = ld_half4(xr - 4*ED);
        acc.x = fmaf(w0.y, t.x, acc.x); acc.y = fmaf(w1.y, t.y, acc.y);
        acc.z = fmaf(w2.y, t.z, acc.z); acc.w = fmaf(w3.y, t.w, acc.w);
    }
    if (l >= 3) {
        float4 t = ld_half4(xr - 6*ED);
        acc.x = fmaf(w0.x, t.x, acc.x); acc.y = fmaf(w1.x, t.y, acc.y);
        acc.z = fmaf(w2.x, t.z, acc.z); acc.w = fmaf(w3.x, t.w, acc.w);
    }
    float4 o;
    o.x = acc.x * sigmoidf_(acc.x); o.y = acc.y * sigmoidf_(acc.y);
    o.z = acc.z * sigmoidf_(acc.z); o.w = acc.w * sigmoidf_(acc.w);
    uint2 st;
    *reinterpret_cast<__half2*>(&st.x) = __floats2half2_rn(o.x, o.y);
    *reinterpret_cast<__half2*>(&st.y) = __floats2half2_rn(o.z, o.w);
    *reinterpret_cast<uint2*>(&out[row * (size_t)ED + e4]) = st;
}

// ---------------- scan pass A ----------------
__global__ void scan_passA(const __half* __restrict__ delta, const __half* __restrict__ u,
                           const __half* __restrict__ dbc, const float* __restrict__ A_log,
                           float* __restrict__ hloc, float* __restrict__ Pout) {
    __shared__ float sB[LC][NST];
    int e = blockIdx.x * 128 + threadIdx.x;
    int c = blockIdx.y, b = blockIdx.z;
    for (int i = threadIdx.x; i < LC*NST; i += 128) {
        int row = i >> 4, col = i & 15;
        sB[row][col] = __half2float(dbc[(size_t)(b*L_ + c*LC + row)*64 + 32 + col]);
    }
    __syncthreads();

    float A[NST];
    bool fast = true;
#pragma unroll
    for (int n = 0; n < NST; n++) {
        float a = -__expf(A_log[(size_t)e*NST + n]);
        A[n] = a;
        fast = fast && (fabsf(a + (float)(n+1)) < 1e-4f * (float)(n+1));
    }

    float h[NST];
#pragma unroll
    for (int n = 0; n < NST; n++) h[n] = 0.f;
    float sd = 0.f;
    const __half* dp = delta + (size_t)(b*L_ + c*LC)*ED + e;
    const __half* up = u     + (size_t)(b*L_ + c*LC)*ED + e;

    if (fast) {
        for (int l = 0; l < LC; l++) {
            float dl = __half2float(dp[(size_t)l*ED]);
            float ul = __half2float(up[(size_t)l*ED]);
            float r  = __expf(-dl);
            float du = dl * ul;
            float p  = r;
            sd += dl;
#pragma unroll
            for (int n = 0; n < NST; n++) {
                h[n] = fmaf(p, h[n], du * sB[l][n]);
                p *= r;
            }
        }
    } else {
        for (int l = 0; l < LC; l++) {
            float dl = __half2float(dp[(size_t)l*ED]);
            float ul = __half2float(up[(size_t)l*ED]);
            float du = dl * ul;
            sd += dl;
#pragma unroll
            for (int n = 0; n < NST; n++) {
                float dA = __expf(dl * A[n]);
                h[n] = fmaf(dA, h[n], du * sB[l][n]);
            }
        }
    }
    size_t o = ((size_t)(b*CH + c)*ED + e)*NST;
#pragma unroll
    for (int n = 0; n < NST; n++) {
        hloc[o+n] = h[n];
        Pout[o+n] = __expf(A[n] * sd);
    }
}

// ---------------- scan combine ----------------
__global__ void scan_combine(const float* __restrict__ hloc, const float* __restrict__ P,
                             float* __restrict__ Hin) {
    int idx = blockIdx.x * 256 + threadIdx.x;
    int n = idx & 15;
    int e = (idx >> 4) & (ED-1);
    int b = idx >> 14;
    float H = 0.f;
#pragma unroll
    for (int c = 0; c < CH; c++) {
        size_t o = ((size_t)(b*CH + c)*ED + e)*NST + n;
        Hin[o] = H;
        H = fmaf(P[o], H, hloc[o]);
    }
}

// ---------------- scan pass B ----------------
__global__ void scan_passB(const __half* __restrict__ delta, const __half* __restrict__ u,
                           const __half* __restrict__ dbc, const __half* __restrict__ xz,
                           const float* __restrict__ A_log, const float* __restrict__ Dv,
                           const float* __restrict__ Hin, __half* __restrict__ ya) {
    __shared__ float sB[LC][NST];
    __shared__ float sC[LC][NST];
    int e = blockIdx.x * 128 + threadIdx.x;
    int c = blockIdx.y, b = blockIdx.z;
    for (int i = threadIdx.x; i < LC*32; i += 128) {
        int row = i >> 5, col = i & 31;
        float v = __half2float(dbc[(size_t)(b*L_ + c*LC + row)*64 + 32 + col]);
        if (col < 16) sB[row][col] = v; else sC[row][col-16] = v;
    }
    __syncthreads();

    float A[NST];
    bool fast = true;
#pragma unroll
    for (int n = 0; n < NST; n++) {
        float a = -__expf(A_log[(size_t)e*NST + n]);
        A[n] = a;
        fast = fast && (fabsf(a + (float)(n+1)) < 1e-4f * (float)(n+1));
    }

    float h[NST];
    size_t oH = ((size_t)(b*CH + c)*ED + e)*NST;
#pragma unroll
    for (int n4 = 0; n4 < NST; n4 += 4) {
        float4 v = *reinterpret_cast<const float4*>(&Hin[oH + n4]);
        h[n4+0] = v.x; h[n4+1] = v.y; h[n4+2] = v.z; h[n4+3] = v.w;
    }
    float Dp = Dv[e];

    const __half* dp = delta + (size_t)(b*L_ + c*LC)*ED + e;
    const __half* up = u     + (size_t)(b*L_ + c*LC)*ED + e;
    const __half* zp = xz    + (size_t)(b*L_ + c*LC)*(2*ED) + ED + e;
    size_t yo = (size_t)(b*L_ + c*LC)*ED + e;

    if (fast) {
        for (int l = 0; l < LC; l++) {
            float dl = __half2float(dp[(size_t)l*ED]);
            float ul = __half2float(up[(size_t)l*ED]);
            float r  = __expf(-dl);
            float du = dl * ul;
            float p  = r;
            float y  = 0.f;
#pragma unroll
            for (int n = 0; n < NST; n++) {
                h[n] = fmaf(p, h[n], du * sB[l][n]);
                y = fmaf(h[n], sC[l][n], y);
                p *= r;
            }
            float zl = __half2float(zp[(size_t)l*(2*ED)]);
            float yt = fmaf(Dp, ul, y) * zl * sigmoidf_(zl);
            ya[yo + (size_t)l*ED] = __float2half_rn(yt);
        }
    } else {
        for (int l = 0; l < LC; l++) {
            float dl = __half2float(dp[(size_t)l*ED]);
            float ul = __half2float(up[(size_t)l*ED]);
            float du = dl * ul;
            float y  = 0.f;
#pragma unroll
            for (int n = 0; n < NST; n++) {
                float dA = __expf(dl * A[n]);
                h[n] = fmaf(dA, h[n], du * sB[l][n]);
                y = fmaf(h[n], sC[l][n], y);
            }
            float zl = __half2float(zp[(size_t)l*(2*ED)]);
            float yt = fmaf(Dp, ul, y) * zl * sigmoidf_(zl);
            ya[yo + (size_t)l*ED] = __float2half_rn(yt);
        }
    }
}

// ---------------- head ----------------
__global__ void head_kernel(const float* __restrict__ h, const float* __restrict__ hw,
                            const float* __restrict__ hb, float* __restrict__ out) {
    int w    = blockIdx.x * 8 + (threadIdx.x >> 5);
    int lane = threadIdx.x & 31;
    int n = w % 3072;
    int b = w / 3072;
    const float4* hr4 = reinterpret_cast<const float4*>(h + ((size_t)b*L_ + (L_-1))*DM);
    const float4* wr4 = reinterpret_cast<const float4*>(hw + (size_t)n*DM);
    float s = 0.f;
#pragma unroll
    for (int i = 0; i < 4; i++) {
        int k4 = lane + i*32;
        float4 a = hr4[k4];
        float4 ww = wr4[k4];
        s += a.x*ww.x + a.y*ww.y + a.z*ww.z + a.w*ww.w;
    }
#pragma unroll
    for (int o = 16; o; o >>= 1) s += __shfl_xor_sync(0xffffffffu, s, o);
    if (lane == 0) {
        int c = n & 31, t = n >> 5;
        out[(size_t)b*3072 + (size_t)c*96 + t] = s + hb[n];
    }
}

// ---------------- launch ----------------
extern "C" void kernel_launch(void* const* d_in, const int* in_sizes, int n_in,
                              void* d_out, int out_size) {
    const float* x        = (const float*)d_in[0];
    const float* embed_w  = (const float*)d_in[1];
    const float* embed_b  = (const float*)d_in[2];
    const float* norm_w   = (const float*)d_in[3];
    const float* in_w     = (const float*)d_in[4];
    const float* conv_w   = (const float*)d_in[5];
    const float* conv_b   = (const float*)d_in[6];
    const float* xp_w     = (const float*)d_in[7];
    const float* dt_w     = (const float*)d_in[8];
    const float* dt_b     = (const float*)d_in[9];
    const float* A_log    = (const float*)d_in[10];
    const float* Dv       = (const float*)d_in[11];
    const float* out_w    = (const float*)d_in[12];
    const float* head_w   = (const float*)d_in[13];
    const float* head_b   = (const float*)d_in[14];
    float* out = (float*)d_out;

    float *h, *hloc, *P, *Hin, *xT;
    __half *xz, *xc, *dbc, *delta, *a, *wi, *wo, *wx, *wd;
    cudaGetSymbolAddress((void**)&h,     g_h);
    cudaGetSymbolAddress((void**)&xz,    g_xz);
    cudaGetSymbolAddress((void**)&xc,    g_xc);
    cudaGetSymbolAddress((void**)&dbc,   g_dbc);
    cudaGetSymbolAddress((void**)&delta, g_delta);
    cudaGetSymbolAddress((void**)&hloc,  g_hloc);
    cudaGetSymbolAddress((void**)&P,     g_P);
    cudaGetSymbolAddress((void**)&Hin,   g_Hin);
    cudaGetSymbolAddress((void**)&xT,    g_xT);
    cudaGetSymbolAddress((void**)&a,     g_a);
    cudaGetSymbolAddress((void**)&wi,    g_wi);
    cudaGetSymbolAddress((void**)&wo,    g_wo);
    cudaGetSymbolAddress((void**)&wx,    g_wx);
    cudaGetSymbolAddress((void**)&wd,    g_wd);

    cudaFuncSetAttribute(mma_gemm<0>, cudaFuncAttributeMaxDynamicSharedMemorySize, MMA_SMEM);
    cudaFuncSetAttribute(mma_gemm<1>, cudaFuncAttributeMaxDynamicSharedMemorySize, MMA_SMEM);
    cudaFuncSetAttribute(mma_gemm<2>, cudaFuncAttributeMaxDynamicSharedMemorySize, MMA_SMEM);
    cudaFuncSetAttribute(tc_gemm_n64, cudaFuncAttributeMaxDynamicSharedMemorySize, N64_SMEM);

    // weight conversion (all layers, once per launch)
    cvt_fp16_kernel<<<(NL*2*ED*DM + 255)/256, 256>>>(in_w,  wi, NL*2*ED*DM);
    cvt_fp16_kernel<<<(NL*DM*ED   + 255)/256, 256>>>(out_w, wo, NL*DM*ED);
    cvt_fp16_kernel<<<(NL*64*ED   + 255)/256, 256>>>(xp_w,  wx, NL*64*ED);
    cvt_fp16_kernel<<<(NL*ED*DR   + 255)/256, 256>>>(dt_w,  wd, NL*ED*DR);

    // embed: h = x^T @ embed_w^T + embed_b
    transpose_x_kernel<<<dim3(L_/32, B_), dim3(32, 32)>>>(x, xT);
    sgemm_kernel<128,128,16,8,8><<<dim3(DM/128, MROWS/128), 256>>>(
        xT, embed_w, h, embed_b, MROWS, DM, 32, 32, 32, DM);

    for (int i = 0; i < NL; i++) {
        // rmsnorm -> fp16 (A operand for in_proj, lda=512)
        rmsnorm_kernel<<<MROWS, 128>>>(h, norm_w + (size_t)i*DM, a);

        // xz = rms @ in_proj^T  (fp16 out)
        mma_gemm<0><<<dim3(2*ED/256, MROWS/128), 512, MMA_SMEM>>>(
            a, wi + (size_t)i*2*ED*DM, xz, nullptr, DM, DM, DM, 2*ED);

        // depthwise causal conv + silu (fp16)
        conv_silu_kernel<<<(MROWS*ED/4)/256, 256>>>(
            xz, conv_w + (size_t)i*ED*4, conv_b + (size_t)i*ED, xc);

        // dbc = xc @ x_proj^T  (tensor-core, fp16 out, ldc=64)
        tc_gemm_n64<<<dim3(1, MROWS/128), 256, N64_SMEM>>>(
            xc, wx + (size_t)i*64*ED, dbc, ED, ED, ED, 64);

        // delta = softplus(dbc[:, :32] @ dt_w^T + dt_b)  (tensor-core, fp16 out)
        mma_gemm<2><<<dim3(ED/256, MROWS/128), 512, MMA_SMEM>>>(
            dbc, wd + (size_t)i*ED*DR, delta, dt_b + (size_t)i*ED, DR, 64, DR, ED);

        // chunked selective scan
        scan_passA<<<dim3(ED/128, CH, B_), 128>>>(
            delta, xc, dbc, A_log + (size_t)i*ED*NST, hloc, P);
        scan_combine<<<(B_*ED*NST)/256, 256>>>(hloc, P, Hin);
        scan_passB<<<dim3(ED/128, CH, B_), 128>>>(
            delta, xc, dbc, xz, A_log + (size_t)i*ED*NST, Dv + (size_t)i*ED, Hin, a);

        // h += y @ out_proj^T
        mma_gemm<1><<<dim3(DM/256, MROWS/128), 512, MMA_SMEM>>>(
            a, wo + (size_t)i*DM*ED, h, nullptr, ED, ED, ED, DM);
    }

    head_kernel<<<(B_*3072)/8, 256>>>(h, head_w, head_b, out);
}

// round 12
// speedup vs baseline: 3.6447x; 1.0262x over previous
#include <cuda_runtime.h>
#include <cuda_fp16.h>
#include <math.h>
#include <stdint.h>

// ---------------- problem constants ----------------
#define B_   16
#define L_   1024
#define DM   512      // d_model
#define ED   1024     // d_inner
#define NST  16       // d_state
#define NL   4
#define DR   32       // dt_rank
#define CH   8        // scan chunks
#define LC   128      // chunk length  (CH*LC == L_)
#define MROWS (B_*L_) // 16384

// ---------------- scratch (device globals; no allocation allowed) ----------------
__device__ __align__(16) float  g_h    [(size_t)MROWS*DM];
__device__ __align__(16) __half g_xz   [(size_t)MROWS*2*ED];
__device__ __align__(16) __half g_xc   [(size_t)MROWS*ED];
__device__ __align__(16) __half g_dbc  [(size_t)MROWS*64];
__device__ __align__(16) __half g_delta[(size_t)MROWS*ED];
__device__ __align__(16) float  g_hloc [(size_t)B_*CH*ED*NST];
__device__ __align__(16) float  g_P    [(size_t)B_*CH*ED*NST];
__device__ __align__(16) float  g_Hin  [(size_t)B_*CH*ED*NST];
__device__ __align__(16) float  g_xT   [(size_t)MROWS*32];
__device__ __align__(16) __half g_a  [(size_t)MROWS*ED];
__device__ __align__(16) __half g_wi [(size_t)NL*2*ED*DM];
__device__ __align__(16) __half g_wo [(size_t)NL*DM*ED];
__device__ __align__(16) __half g_wx [(size_t)NL*64*ED];
__device__ __align__(16) __half g_wd [(size_t)NL*ED*DR];

__device__ __forceinline__ float sigmoidf_(float x) { return 1.f / (1.f + __expf(-x)); }

// ================= mma.sync fp16 helpers (non-arch-gated PTX) =================
__device__ __forceinline__ void ldm_x4(uint32_t (&r)[4], uint32_t a) {
    asm volatile("ldmatrix.sync.aligned.m8n8.x4.shared.b16 {%0,%1,%2,%3}, [%4];"
                 : "=r"(r[0]), "=r"(r[1]), "=r"(r[2]), "=r"(r[3]) : "r"(a));
}
__device__ __forceinline__ void mma_fp16(float (&d)[4], const uint32_t (&a)[4],
                                         uint32_t b0, uint32_t b1) {
    asm volatile(
        "mma.sync.aligned.m16n8k16.row.col.f32.f16.f16.f32 "
        "{%0,%1,%2,%3}, {%4,%5,%6,%7}, {%8,%9}, {%0,%1,%2,%3};"
        : "+f"(d[0]), "+f"(d[1]), "+f"(d[2]), "+f"(d[3])
        : "r"(a[0]), "r"(a[1]), "r"(a[2]), "r"(a[3]), "r"(b0), "r"(b1));
}
__device__ __forceinline__ void cp_async16(uint32_t sdst, const void* gsrc) {
    asm volatile("cp.async.cg.shared.global [%0], [%1], 16;" :: "r"(sdst), "l"(gsrc));
}
__device__ __forceinline__ void cp_commit() { asm volatile("cp.async.commit_group;"); }
__device__ __forceinline__ void cp_wait1()  { asm volatile("cp.async.wait_group 1;"); }
__device__ __forceinline__ void cp_wait0()  { asm volatile("cp.async.wait_group 0;"); }

__device__ __forceinline__ float softplusf_(float v) {
    return (v > 20.f) ? v : log1pf(__expf(v));
}

// log-depth powers: pw[n] = r^(n+1), n=0..15
__device__ __forceinline__ void powers16(float r, float (&pw)[16]) {
    float r2 = r*r, r3 = r2*r, r4 = r2*r2;
    float r5 = r4*r, r6 = r4*r2, r7 = r4*r3, r8 = r4*r4;
    pw[0]=r;  pw[1]=r2; pw[2]=r3; pw[3]=r4;
    pw[4]=r5; pw[5]=r6; pw[6]=r7; pw[7]=r8;
    pw[8]=r8*r;  pw[9]=r8*r2;  pw[10]=r8*r3;  pw[11]=r8*r4;
    pw[12]=r8*r5; pw[13]=r8*r6; pw[14]=r8*r7; pw[15]=r8*r8;
}

// ================= fp16 tensor-core GEMM (wide tiles) =================
// MODE 0: store fp16. MODE 1: fp32 C += result. MODE 2: softplus(+bias) fp16.
#define ROWB    80
#define A_TEN   (128*ROWB)
#define B_TEN   (256*ROWB)
#define STG_SZ  (A_TEN + B_TEN)
#define MMA_SMEM (3*STG_SZ)

template<int MODE>
__global__ __launch_bounds__(512, 1)
void mma_gemm(const __half* __restrict__ A, const __half* __restrict__ B,
              void* __restrict__ C, const float* __restrict__ bias,
              int K, int lda, int ldb, int ldc) {
    extern __shared__ char smem[];
    const uint32_t sbase = (uint32_t)__cvta_generic_to_shared(smem);
    const int tid  = threadIdx.x;
    const int wid  = tid >> 5, lane = tid & 31;
    const int wm   = wid & 3;
    const int wn   = wid >> 2;
    const int bm   = blockIdx.y * 128;
    const int bn   = blockIdx.x * 256;
    const int NC   = K >> 5;

    float acc[2][8][4];
#pragma unroll
    for (int i = 0; i < 2; i++)
#pragma unroll
        for (int j = 0; j < 8; j++)
#pragma unroll
            for (int q = 0; q < 4; q++) acc[i][j][q] = 0.f;

    const int arow  = tid >> 2,          akc = tid & 3;
    const int brow0 = tid >> 2,          bkc0 = tid & 3;
    const int brow1 = (tid + 512) >> 2,  bkc1 = tid & 3;

    const __half* gA  = A + (size_t)(bm + arow)  * lda + akc  * 8;
    const __half* gB0 = B + (size_t)(bn + brow0) * ldb + bkc0 * 8;
    const __half* gB1 = B + (size_t)(bn + brow1) * ldb + bkc1 * 8;
    const uint32_t sA  = sbase + arow  * ROWB + akc  * 16;
    const uint32_t sB0 = sbase + brow0 * ROWB + bkc0 * 16;
    const uint32_t sB1 = sbase + brow1 * ROWB + bkc1 * 16;

#define LOAD_STAGE(c, s) do {                                          \
        int koff = (c) << 5;                                           \
        uint32_t st = (uint32_t)(s) * STG_SZ;                          \
        cp_async16(sA  + st,         gA  + koff);                      \
        cp_async16(sB0 + st + A_TEN, gB0 + koff);                      \
        cp_async16(sB1 + st + A_TEN, gB1 + koff);                      \
        cp_commit();                                                   \
    } while (0)

    LOAD_STAGE(0, 0);
    if (NC > 1) LOAD_STAGE(1, 1);

    const int aRow = (lane & 15);
    const int aKby = ((lane >> 4) << 4);
    const int bRow = (lane & 7) | ((lane >> 4) << 3);
    const int bKby = (((lane >> 3) & 1) << 4);

    int stg = 0;
    for (int c = 0; c < NC; c++) {
        if (c + 1 < NC) cp_wait1(); else cp_wait0();
        __syncthreads();
        int nstg = stg + 2; if (nstg >= 3) nstg -= 3;
        if (c + 2 < NC) LOAD_STAGE(c + 2, nstg);

        const uint32_t st  = sbase + (uint32_t)stg * STG_SZ;
        const uint32_t sA_ = st;
        const uint32_t sB_ = st + A_TEN;

        uint32_t af[2][2][4];
#pragma unroll
        for (int mf = 0; mf < 2; mf++) {
            uint32_t off = (uint32_t)(wm*32 + mf*16 + aRow) * ROWB + aKby;
            ldm_x4(af[0][mf], sA_ + off);
        }
#pragma unroll
        for (int k16 = 0; k16 < 2; k16++) {
            const int kb = k16 * 32;
            if (k16 == 0) {
#pragma unroll
                for (int mf = 0; mf < 2; mf++) {
                    uint32_t off = (uint32_t)(wm*32 + mf*16 + aRow) * ROWB + 32 + aKby;
                    ldm_x4(af[1][mf], sA_ + off);
                }
            }
#pragma unroll
            for (int nf2 = 0; nf2 < 4; nf2++) {
                uint32_t bf[4];
                uint32_t off = (uint32_t)(wn*64 + nf2*16 + bRow) * ROWB + kb + bKby;
                ldm_x4(bf, sB_ + off);
#pragma unroll
                for (int half = 0; half < 2; half++) {
#pragma unroll
                    for (int mf = 0; mf < 2; mf++) {
                        int nf = nf2*2 + half;
                        mma_fp16(acc[mf][nf], af[k16][mf], bf[half*2], bf[half*2+1]);
                    }
                }
            }
        }
        stg++; if (stg >= 3) stg = 0;
    }

    const int erow = lane >> 2;
    const int ecol = (lane & 3) * 2;
#pragma unroll
    for (int mf = 0; mf < 2; mf++) {
#pragma unroll
        for (int nf = 0; nf < 8; nf++) {
            int row0 = bm + wm*32 + mf*16 + erow;
            int col  = bn + wn*64 + nf*8 + ecol;
            if (MODE == 0) {
                __half* Ch = (__half*)C;
                *reinterpret_cast<__half2*>(Ch + (size_t)row0 * ldc + col) =
                    __floats2half2_rn(acc[mf][nf][0], acc[mf][nf][1]);
                *reinterpret_cast<__half2*>(Ch + (size_t)(row0 + 8) * ldc + col) =
                    __floats2half2_rn(acc[mf][nf][2], acc[mf][nf][3]);
            } else if (MODE == 1) {
                float* Cf = (float*)C;
                float* p0 = Cf + (size_t)row0 * ldc + col;
                float* p1 = Cf + (size_t)(row0 + 8) * ldc + col;
                float2 o0 = *reinterpret_cast<float2*>(p0);
                float2 o1 = *reinterpret_cast<float2*>(p1);
                o0.x += acc[mf][nf][0]; o0.y += acc[mf][nf][1];
                o1.x += acc[mf][nf][2]; o1.y += acc[mf][nf][3];
                *reinterpret_cast<float2*>(p0) = o0;
                *reinterpret_cast<float2*>(p1) = o1;
            } else {
                __half* Ch = (__half*)C;
                float b0 = bias[col], b1 = bias[col+1];
                *reinterpret_cast<__half2*>(Ch + (size_t)row0 * ldc + col) =
                    __floats2half2_rn(softplusf_(acc[mf][nf][0] + b0),
                                      softplusf_(acc[mf][nf][1] + b1));
                *reinterpret_cast<__half2*>(Ch + (size_t)(row0 + 8) * ldc + col) =
                    __floats2half2_rn(softplusf_(acc[mf][nf][2] + b0),
                                      softplusf_(acc[mf][nf][3] + b1));
            }
        }
    }
#undef LOAD_STAGE
}

// ================= fp16 tensor-core GEMM, narrow N=64 (dbc) =================
#define B64_TEN (64*ROWB)
#define STG64   (A_TEN + B64_TEN)
#define N64_SMEM (3*STG64)

__global__ __launch_bounds__(256, 1)
void tc_gemm_n64(const __half* __restrict__ A, const __half* __restrict__ B,
                 __half* __restrict__ C, int K, int lda, int ldb, int ldc) {
    extern __shared__ char smem[];
    const uint32_t sbase = (uint32_t)__cvta_generic_to_shared(smem);
    const int tid  = threadIdx.x;
    const int wid  = tid >> 5, lane = tid & 31;
    const int wm   = wid & 3;
    const int wn   = wid >> 2;
    const int bm   = blockIdx.y * 128;
    const int NC   = K >> 5;

    float acc[2][4][4];
#pragma unroll
    for (int i = 0; i < 2; i++)
#pragma unroll
        for (int j = 0; j < 4; j++)
#pragma unroll
            for (int q = 0; q < 4; q++) acc[i][j][q] = 0.f;

    const int arow0 = tid >> 2,        akc = tid & 3;
    const int arow1 = (tid + 256) >> 2;
    const int brow  = tid >> 2,        bkc = tid & 3;

    const __half* gA0 = A + (size_t)(bm + arow0) * lda + akc * 8;
    const __half* gA1 = A + (size_t)(bm + arow1) * lda + akc * 8;
    const __half* gB  = B + (size_t)brow * ldb + bkc * 8;
    const uint32_t sA0 = sbase + arow0 * ROWB + akc * 16;
    const uint32_t sA1 = sbase + arow1 * ROWB + akc * 16;
    const uint32_t sBr = sbase + brow  * ROWB + bkc * 16;

#define LOAD_STG64(c, s) do {                                          \
        int koff = (c) << 5;                                           \
        uint32_t st = (uint32_t)(s) * STG64;                           \
        cp_async16(sA0 + st,         gA0 + koff);                      \
        cp_async16(sA1 + st,         gA1 + koff);                      \
        cp_async16(sBr + st + A_TEN, gB  + koff);                      \
        cp_commit();                                                   \
    } while (0)

    LOAD_STG64(0, 0);
    if (NC > 1) LOAD_STG64(1, 1);

    const int aRow = (lane & 15);
    const int aKby = ((lane >> 4) << 4);
    const int bRow = (lane & 7) | ((lane >> 4) << 3);
    const int bKby = (((lane >> 3) & 1) << 4);

    int stg = 0;
    for (int c = 0; c < NC; c++) {
        if (c + 1 < NC) cp_wait1(); else cp_wait0();
        __syncthreads();
        int nstg = stg + 2; if (nstg >= 3) nstg -= 3;
        if (c + 2 < NC) LOAD_STG64(c + 2, nstg);

        const uint32_t st  = sbase + (uint32_t)stg * STG64;
        const uint32_t sA_ = st;
        const uint32_t sB_ = st + A_TEN;

#pragma unroll
        for (int k16 = 0; k16 < 2; k16++) {
            const int kb = k16 * 32;
            uint32_t af[2][4];
#pragma unroll
            for (int mf = 0; mf < 2; mf++) {
                uint32_t off = (uint32_t)(wm*32 + mf*16 + aRow) * ROWB + kb + aKby;
                ldm_x4(af[mf], sA_ + off);
            }
#pragma unroll
            for (int nf2 = 0; nf2 < 2; nf2++) {
                uint32_t bf[4];
                uint32_t off = (uint32_t)(wn*32 + nf2*16 + bRow) * ROWB + kb + bKby;
                ldm_x4(bf, sB_ + off);
#pragma unroll
                for (int half = 0; half < 2; half++) {
#pragma unroll
                    for (int mf = 0; mf < 2; mf++) {
                        int nf = nf2*2 + half;
                        mma_fp16(acc[mf][nf], af[mf], bf[half*2], bf[half*2+1]);
                    }
                }
            }
        }
        stg++; if (stg >= 3) stg = 0;
    }

    const int erow = lane >> 2;
    const int ecol = (lane & 3) * 2;
#pragma unroll
    for (int mf = 0; mf < 2; mf++) {
#pragma unroll
        for (int nf = 0; nf < 4; nf++) {
            int row0 = bm + wm*32 + mf*16 + erow;
            int col  = wn*32 + nf*8 + ecol;
            *reinterpret_cast<__half2*>(C + (size_t)row0 * ldc + col) =
                __floats2half2_rn(acc[mf][nf][0], acc[mf][nf][1]);
            *reinterpret_cast<__half2*>(C + (size_t)(row0 + 8) * ldc + col) =
                __floats2half2_rn(acc[mf][nf][2], acc[mf][nf][3]);
        }
    }
#undef LOAD_STG64
}

// ---------------- fp32 -> fp16 ----------------
__global__ void cvt_fp16_kernel(const float* __restrict__ x, __half* __restrict__ h, int n) {
    int i = blockIdx.x * 256 + threadIdx.x;
    if (i < n) h[i] = __float2half_rn(x[i]);
}

// ---------------- transpose x ----------------
__global__ void transpose_x_kernel(const float* __restrict__ x, float* __restrict__ xT) {
    __shared__ float t[32][33];
    int b  = blockIdx.y;
    int l0 = blockIdx.x * 32;
    int tx = threadIdx.x, ty = threadIdx.y;
    t[ty][tx] = x[((size_t)b*32 + ty)*L_ + l0 + tx];
    __syncthreads();
    xT[((size_t)b*L_ + l0 + ty)*32 + tx] = t[tx][ty];
}

// ---------------- fp32 SGEMM (embed only) ----------------
template<int BM, int BN, int BK, int TM, int TN>
__global__ __launch_bounds__((BM/TM)*(BN/TN))
void sgemm_kernel(const float* __restrict__ A, const float* __restrict__ Bw,
                  float* __restrict__ C, const float* __restrict__ bias,
                  int M, int N, int K, int lda, int ldb, int ldc) {
    constexpr int THREADS = (BM/TM)*(BN/TN);
    __shared__ float As[BK][BM];
    __shared__ float Bs[BK][BN];
    const int tid = threadIdx.x;
    const int bm  = blockIdx.y * BM;
    const int bn  = blockIdx.x * BN;
    const int tx  = tid % (BN/TN);
    const int ty  = tid / (BN/TN);

    float acc[TM][TN];
#pragma unroll
    for (int i = 0; i < TM; i++)
#pragma unroll
        for (int j = 0; j < TN; j++) acc[i][j] = 0.f;

    constexpr int AVEC = BM*BK/4/THREADS;
    constexpr int BVEC = BN*BK/4/THREADS;

    for (int k0 = 0; k0 < K; k0 += BK) {
#pragma unroll
        for (int i = 0; i < AVEC; i++) {
            int idx = tid + i*THREADS;
            int row = idx / (BK/4);
            int kc  = (idx % (BK/4)) * 4;
            float4 v = *reinterpret_cast<const float4*>(&A[(size_t)(bm+row)*lda + k0 + kc]);
            As[kc+0][row] = v.x; As[kc+1][row] = v.y; As[kc+2][row] = v.z; As[kc+3][row] = v.w;
        }
#pragma unroll
        for (int i = 0; i < BVEC; i++) {
            int idx = tid + i*THREADS;
            int row = idx / (BK/4);
            int kc  = (idx % (BK/4)) * 4;
            float4 v = *reinterpret_cast<const float4*>(&Bw[(size_t)(bn+row)*ldb + k0 + kc]);
            Bs[kc+0][row] = v.x; Bs[kc+1][row] = v.y; Bs[kc+2][row] = v.z; Bs[kc+3][row] = v.w;
        }
        __syncthreads();
#pragma unroll
        for (int kk = 0; kk < BK; kk++) {
            float a[TM], b[TN];
#pragma unroll
            for (int i = 0; i < TM; i++) a[i] = As[kk][ty*TM + i];
#pragma unroll
            for (int j = 0; j < TN; j++) b[j] = Bs[kk][tx*TN + j];
#pragma unroll
            for (int i = 0; i < TM; i++)
#pragma unroll
                for (int j = 0; j < TN; j++)
                    acc[i][j] = fmaf(a[i], b[j], acc[i][j]);
        }
        __syncthreads();
    }

#pragma unroll
    for (int i = 0; i < TM; i++) {
        int row = bm + ty*TM + i;
#pragma unroll
        for (int j = 0; j < TN; j++) {
            int col = bn + tx*TN + j;
            C[(size_t)row*ldc + col] = acc[i][j] + bias[col];
        }
    }
}

// ---------------- RMSNorm, fp16 output ----------------
__global__ void rmsnorm_kernel(const float* __restrict__ x, const float* __restrict__ w,
                               __half* __restrict__ oa) {
    int row = blockIdx.x;
    int tid = threadIdx.x;
    const float4* xr = reinterpret_cast<const float4*>(x + (size_t)row*DM);
    float4 v = xr[tid];
    float ss = v.x*v.x + v.y*v.y + v.z*v.z + v.w*v.w;
#pragma unroll
    for (int o = 16; o; o >>= 1) ss += __shfl_xor_sync(0xffffffffu, ss, o);
    __shared__ float sred[4];
    if ((tid & 31) == 0) sred[tid >> 5] = ss;
    __syncthreads();
    float tot = sred[0] + sred[1] + sred[2] + sred[3];
    float scale = rsqrtf(tot * (1.f/(float)DM) + 1e-5f);
    float4 wv = reinterpret_cast<const float4*>(w)[tid];
    float o0 = v.x*scale*wv.x, o1 = v.y*scale*wv.y, o2 = v.z*scale*wv.z, o3 = v.w*scale*wv.w;
    size_t off = (size_t)row*DM + tid*4;
    __half2* oa2 = reinterpret_cast<__half2*>(oa + off);
    oa2[0] = __floats2half2_rn(o0, o1);
    oa2[1] = __floats2half2_rn(o2, o3);
}

// ---------------- depthwise causal conv(4) + bias + silu ----------------
// fp16 in/out; each thread: 4 channels x 4 consecutive timesteps (7-load sliding window)
__device__ __forceinline__ float4 ld_half4(const __half* p) {
    uint2 u = *reinterpret_cast<const uint2*>(p);
    float2 f01 = __half22float2(*reinterpret_cast<__half2*>(&u.x));
    float2 f23 = __half22float2(*reinterpret_cast<__half2*>(&u.y));
    return make_float4(f01.x, f01.y, f23.x, f23.y);
}
__global__ void conv_silu_kernel(const __half* __restrict__ xz, const float* __restrict__ cw,
                                 const float* __restrict__ cb, __half* __restrict__ out) {
    size_t idx = (size_t)blockIdx.x * 256 + threadIdx.x;   // over (MROWS/4)*(ED/4)
    int e4 = (idx & (ED/4 - 1)) * 4;
    size_t rg = idx >> 8;                 // row group: b*(L/4) + l0/4
    int l0 = (int)(rg & (L_/4 - 1)) * 4;
    size_t row0 = (rg >> 8) * (size_t)L_ + l0;   // b*L + l0

    float4 b4 = *reinterpret_cast<const float4*>(&cb[e4]);
    float4 w0 = *reinterpret_cast<const float4*>(&cw[(size_t)(e4+0)*4]);
    float4 w1 = *reinterpret_cast<const float4*>(&cw[(size_t)(e4+1)*4]);
    float4 w2 = *reinterpret_cast<const float4*>(&cw[(size_t)(e4+2)*4]);
    float4 w3 = *reinterpret_cast<const float4*>(&cw[(size_t)(e4+3)*4]);

    // window v[i] = x(l0-3+i), i=0..6
    float4 v[7];
#pragma unroll
    for (int i = 0; i < 7; i++) {
        int l = l0 - 3 + i;
        if (l >= 0) v[i] = ld_half4(xz + (row0 + (i - 3)) * (size_t)(2*ED) + e4);
        else        v[i] = make_float4(0.f, 0.f, 0.f, 0.f);
    }

#pragma unroll
    for (int j = 0; j < 4; j++) {       // output timestep l0+j uses v[j..j+3]
        float4 acc = b4;
        acc.x = fmaf(w0.x, v[j].x,   acc.x); acc.y = fmaf(w1.x, v[j].y,   acc.y);
        acc.z = fmaf(w2.x, v[j].z,   acc.z); acc.w = fmaf(w3.x, v[j].w,   acc.w);
        acc.x = fmaf(w0.y, v[j+1].x, acc.x); acc.y = fmaf(w1.y, v[j+1].y, acc.y);
        acc.z = fmaf(w2.y, v[j+1].z, acc.z); acc.w = fmaf(w3.y, v[j+1].w, acc.w);
        acc.x = fmaf(w0.z, v[j+2].x, acc.x); acc.y = fmaf(w1.z, v[j+2].y, acc.y);
        acc.z = fmaf(w2.z, v[j+2].z, acc.z); acc.w = fmaf(w3.z, v[j+2].w, acc.w);
        acc.x = fmaf(w0.w, v[j+3].x, acc.x); acc.y = fmaf(w1.w, v[j+3].y, acc.y);
        acc.z = fmaf(w2.w, v[j+3].z, acc.z); acc.w = fmaf(w3.w, v[j+3].w, acc.w);
        float4 o;
        o.x = acc.x * sigmoidf_(acc.x); o.y = acc.y * sigmoidf_(acc.y);
        o.z = acc.z * sigmoidf_(acc.z); o.w = acc.w * sigmoidf_(acc.w);
        uint2 st;
        *reinterpret_cast<__half2*>(&st.x) = __floats2half2_rn(o.x, o.y);
        *reinterpret_cast<__half2*>(&st.y) = __floats2half2_rn(o.z, o.w);
        *reinterpret_cast<uint2*>(&out[(row0 + j) * (size_t)ED + e4]) = st;
    }
}

// ---------------- scan pass A ----------------
__global__ void scan_passA(const __half* __restrict__ delta, const __half* __restrict__ u,
                           const __half* __restrict__ dbc, const float* __restrict__ A_log,
                           float* __restrict__ hloc, float* __restrict__ Pout) {
    __shared__ float sB[LC][NST];
    int e = blockIdx.x * 128 + threadIdx.x;
    int c = blockIdx.y, b = blockIdx.z;
    for (int i = threadIdx.x; i < LC*NST; i += 128) {
        int row = i >> 4, col = i & 15;
        sB[row][col] = __half2float(dbc[(size_t)(b*L_ + c*LC + row)*64 + 32 + col]);
    }
    __syncthreads();

    float A[NST];
    bool fast = true;
#pragma unroll
    for (int n = 0; n < NST; n++) {
        float a = -__expf(A_log[(size_t)e*NST + n]);
        A[n] = a;
        fast = fast && (fabsf(a + (float)(n+1)) < 1e-4f * (float)(n+1));
    }

    float h[NST];
#pragma unroll
    for (int n = 0; n < NST; n++) h[n] = 0.f;
    float sd = 0.f;
    const __half* dp = delta + (size_t)(b*L_ + c*LC)*ED + e;
    const __half* up = u     + (size_t)(b*L_ + c*LC)*ED + e;

    if (fast) {
        for (int l = 0; l < LC; l++) {
            float dl = __half2float(dp[(size_t)l*ED]);
            float ul = __half2float(up[(size_t)l*ED]);
            float r  = __expf(-dl);
            float du = dl * ul;
            sd += dl;
            float pw[16];
            powers16(r, pw);
#pragma unroll
            for (int n = 0; n < NST; n++)
                h[n] = fmaf(pw[n], h[n], du * sB[l][n]);
        }
    } else {
        for (int l = 0; l < LC; l++) {
            float dl = __half2float(dp[(size_t)l*ED]);
            float ul = __half2float(up[(size_t)l*ED]);
            float du = dl * ul;
            sd += dl;
#pragma unroll
            for (int n = 0; n < NST; n++) {
                float dA = __expf(dl * A[n]);
                h[n] = fmaf(dA, h[n], du * sB[l][n]);
            }
        }
    }
    size_t o = ((size_t)(b*CH + c)*ED + e)*NST;
#pragma unroll
    for (int n4 = 0; n4 < NST; n4 += 4)
        *reinterpret_cast<float4*>(&hloc[o + n4]) =
            make_float4(h[n4], h[n4+1], h[n4+2], h[n4+3]);
#pragma unroll
    for (int n4 = 0; n4 < NST; n4 += 4)
        *reinterpret_cast<float4*>(&Pout[o + n4]) =
            make_float4(__expf(A[n4]*sd), __expf(A[n4+1]*sd),
                        __expf(A[n4+2]*sd), __expf(A[n4+3]*sd));
}

// ---------------- scan combine ----------------
__global__ void scan_combine(const float* __restrict__ hloc, const float* __restrict__ P,
                             float* __restrict__ Hin) {
    int idx = blockIdx.x * 256 + threadIdx.x;
    int n = idx & 15;
    int e = (idx >> 4) & (ED-1);
    int b = idx >> 14;
    float H = 0.f;
#pragma unroll
    for (int c = 0; c < CH; c++) {
        size_t o = ((size_t)(b*CH + c)*ED + e)*NST + n;
        Hin[o] = H;
        H = fmaf(P[o], H, hloc[o]);
    }
}

// ---------------- scan pass B ----------------
__global__ void scan_passB(const __half* __restrict__ delta, const __half* __restrict__ u,
                           const __half* __restrict__ dbc, const __half* __restrict__ xz,
                           const float* __restrict__ A_log, const float* __restrict__ Dv,
                           const float* __restrict__ Hin, __half* __restrict__ ya) {
    __shared__ float sB[LC][NST];
    __shared__ float sC[LC][NST];
    int e = blockIdx.x * 128 + threadIdx.x;
    int c = blockIdx.y, b = blockIdx.z;
    for (int i = threadIdx.x; i < LC*32; i += 128) {
        int row = i >> 5, col = i & 31;
        float v = __half2float(dbc[(size_t)(b*L_ + c*LC + row)*64 + 32 + col]);
        if (col < 16) sB[row][col] = v; else sC[row][col-16] = v;
    }
    __syncthreads();

    float A[NST];
    bool fast = true;
#pragma unroll
    for (int n = 0; n < NST; n++) {
        float a = -__expf(A_log[(size_t)e*NST + n]);
        A[n] = a;
        fast = fast && (fabsf(a + (float)(n+1)) < 1e-4f * (float)(n+1));
    }

    float h[NST];
    size_t oH = ((size_t)(b*CH + c)*ED + e)*NST;
#pragma unroll
    for (int n4 = 0; n4 < NST; n4 += 4) {
        float4 v = *reinterpret_cast<const float4*>(&Hin[oH + n4]);
        h[n4+0] = v.x; h[n4+1] = v.y; h[n4+2] = v.z; h[n4+3] = v.w;
    }
    float Dp = Dv[e];

    const __half* dp = delta + (size_t)(b*L_ + c*LC)*ED + e;
    const __half* up = u     + (size_t)(b*L_ + c*LC)*ED + e;
    const __half* zp = xz    + (size_t)(b*L_ + c*LC)*(2*ED) + ED + e;
    size_t yo = (size_t)(b*L_ + c*LC)*ED + e;

    if (fast) {
        for (int l = 0; l < LC; l++) {
            float dl = __half2float(dp[(size_t)l*ED]);
            float ul = __half2float(up[(size_t)l*ED]);
            float r  = __expf(-dl);
            float du = dl * ul;
            float y  = 0.f;
            float pw[16];
            powers16(r, pw);
#pragma unroll
            for (int n = 0; n < NST; n++) {
                h[n] = fmaf(pw[n], h[n], du * sB[l][n]);
                y = fmaf(h[n], sC[l][n], y);
            }
            float zl = __half2float(zp[(size_t)l*(2*ED)]);
            float yt = fmaf(Dp, ul, y) * zl * sigmoidf_(zl);
            ya[yo + (size_t)l*ED] = __float2half_rn(yt);
        }
    } else {
        for (int l = 0; l < LC; l++) {
            float dl = __half2float(dp[(size_t)l*ED]);
            float ul = __half2float(up[(size_t)l*ED]);
            float du = dl * ul;
            float y  = 0.f;
#pragma unroll
            for (int n = 0; n < NST; n++) {
                float dA = __expf(dl * A[n]);
                h[n] = fmaf(dA, h[n], du * sB[l][n]);
                y = fmaf(h[n], sC[l][n], y);
            }
            float zl = __half2float(zp[(size_t)l*(2*ED)]);
            float yt = fmaf(Dp, ul, y) * zl * sigmoidf_(zl);
            ya[yo + (size_t)l*ED] = __float2half_rn(yt);
        }
    }
}

// ---------------- head ----------------
__global__ void head_kernel(const float* __restrict__ h, const float* __restrict__ hw,
                            const float* __restrict__ hb, float* __restrict__ out) {
    int w    = blockIdx.x * 8 + (threadIdx.x >> 5);
    int lane = threadIdx.x & 31;
    int n = w % 3072;
    int b = w / 3072;
    const float4* hr4 = reinterpret_cast<const float4*>(h + ((size_t)b*L_ + (L_-1))*DM);
    const float4* wr4 = reinterpret_cast<const float4*>(hw + (size_t)n*DM);
    float s = 0.f;
#pragma unroll
    for (int i = 0; i < 4; i++) {
        int k4 = lane + i*32;
        float4 a = hr4[k4];
        float4 ww = wr4[k4];
        s += a.x*ww.x + a.y*ww.y + a.z*ww.z + a.w*ww.w;
    }
#pragma unroll
    for (int o = 16; o; o >>= 1) s += __shfl_xor_sync(0xffffffffu, s, o);
    if (lane == 0) {
        int c = n & 31, t = n >> 5;
        out[(size_t)b*3072 + (size_t)c*96 + t] = s + hb[n];
    }
}

// ---------------- launch ----------------
extern "C" void kernel_launch(void* const* d_in, const int* in_sizes, int n_in,
                              void* d_out, int out_size) {
    const float* x        = (const float*)d_in[0];
    const float* embed_w  = (const float*)d_in[1];
    const float* embed_b  = (const float*)d_in[2];
    const float* norm_w   = (const float*)d_in[3];
    const float* in_w     = (const float*)d_in[4];
    const float* conv_w   = (const float*)d_in[5];
    const float* conv_b   = (const float*)d_in[6];
    const float* xp_w     = (const float*)d_in[7];
    const float* dt_w     = (const float*)d_in[8];
    const float* dt_b     = (const float*)d_in[9];
    const float* A_log    = (const float*)d_in[10];
    const float* Dv       = (const float*)d_in[11];
    const float* out_w    = (const float*)d_in[12];
    const float* head_w   = (const float*)d_in[13];
    const float* head_b   = (const float*)d_in[14];
    float* out = (float*)d_out;

    float *h, *hloc, *P, *Hin, *xT;
    __half *xz, *xc, *dbc, *delta, *a, *wi, *wo, *wx, *wd;
    cudaGetSymbolAddress((void**)&h,     g_h);
    cudaGetSymbolAddress((void**)&xz,    g_xz);
    cudaGetSymbolAddress((void**)&xc,    g_xc);
    cudaGetSymbolAddress((void**)&dbc,   g_dbc);
    cudaGetSymbolAddress((void**)&delta, g_delta);
    cudaGetSymbolAddress((void**)&hloc,  g_hloc);
    cudaGetSymbolAddress((void**)&P,     g_P);
    cudaGetSymbolAddress((void**)&Hin,   g_Hin);
    cudaGetSymbolAddress((void**)&xT,    g_xT);
    cudaGetSymbolAddress((void**)&a,     g_a);
    cudaGetSymbolAddress((void**)&wi,    g_wi);
    cudaGetSymbolAddress((void**)&wo,    g_wo);
    cudaGetSymbolAddress((void**)&wx,    g_wx);
    cudaGetSymbolAddress((void**)&wd,    g_wd);

    cudaFuncSetAttribute(mma_gemm<0>, cudaFuncAttributeMaxDynamicSharedMemorySize, MMA_SMEM);
    cudaFuncSetAttribute(mma_gemm<1>, cudaFuncAttributeMaxDynamicSharedMemorySize, MMA_SMEM);
    cudaFuncSetAttribute(mma_gemm<2>, cudaFuncAttributeMaxDynamicSharedMemorySize, MMA_SMEM);
    cudaFuncSetAttribute(tc_gemm_n64, cudaFuncAttributeMaxDynamicSharedMemorySize, N64_SMEM);

    // weight conversion (all layers, once per launch)
    cvt_fp16_kernel<<<(NL*2*ED*DM + 255)/256, 256>>>(in_w,  wi, NL*2*ED*DM);
    cvt_fp16_kernel<<<(NL*DM*ED   + 255)/256, 256>>>(out_w, wo, NL*DM*ED);
    cvt_fp16_kernel<<<(NL*64*ED   + 255)/256, 256>>>(xp_w,  wx, NL*64*ED);
    cvt_fp16_kernel<<<(NL*ED*DR   + 255)/256, 256>>>(dt_w,  wd, NL*ED*DR);

    // embed: h = x^T @ embed_w^T + embed_b
    transpose_x_kernel<<<dim3(L_/32, B_), dim3(32, 32)>>>(x, xT);
    sgemm_kernel<128,128,16,8,8><<<dim3(DM/128, MROWS/128), 256>>>(
        xT, embed_w, h, embed_b, MROWS, DM, 32, 32, 32, DM);

    for (int i = 0; i < NL; i++) {
        rmsnorm_kernel<<<MROWS, 128>>>(h, norm_w + (size_t)i*DM, a);

        // xz = rms @ in_proj^T  (fp16 out)
        mma_gemm<0><<<dim3(2*ED/256, MROWS/128), 512, MMA_SMEM>>>(
            a, wi + (size_t)i*2*ED*DM, xz, nullptr, DM, DM, DM, 2*ED);

        // depthwise causal conv + silu (fp16, 4 timesteps/thread)
        conv_silu_kernel<<<(MROWS/4)*(ED/4)/256, 256>>>(
            xz, conv_w + (size_t)i*ED*4, conv_b + (size_t)i*ED, xc);

        // dbc = xc @ x_proj^T
        tc_gemm_n64<<<dim3(1, MROWS/128), 256, N64_SMEM>>>(
            xc, wx + (size_t)i*64*ED, dbc, ED, ED, ED, 64);

        // delta = softplus(dbc[:, :32] @ dt_w^T + dt_b)
        mma_gemm<2><<<dim3(ED/256, MROWS/128), 512, MMA_SMEM>>>(
            dbc, wd + (size_t)i*ED*DR, delta, dt_b + (size_t)i*ED, DR, 64, DR, ED);

        // chunked selective scan
        scan_passA<<<dim3(ED/128, CH, B_), 128>>>(
            delta, xc, dbc, A_log + (size_t)i*ED*NST, hloc, P);
        scan_combine<<<(B_*ED*NST)/256, 256>>>(hloc, P, Hin);
        scan_passB<<<dim3(ED/128, CH, B_), 128>>>(
            delta, xc, dbc, xz, A_log + (size_t)i*ED*NST, Dv + (size_t)i*ED, Hin, a);

        // h += y @ out_proj^T
        mma_gemm<1><<<dim3(DM/256, MROWS/128), 512, MMA_SMEM>>>(
            a, wo + (size_t)i*DM*ED, h, nullptr, ED, ED, ED, DM);
    }

    head_kernel<<<(B_*3072)/8, 256>>>(h, head_w, head_b, out);
}